// round 6
// baseline (speedup 1.0000x reference)
#include <cuda_runtime.h>
#include <math.h>

// ---------------- problem constants ----------------
#define BB     8
#define NQT    350
#define NP     300
#define NT     50
#define DIM    256
#define HH     8
#define DH     32
#define NLVL   4
#define NPNT   4
#define NLAY   6
#define NH2    2
#define DH2    128
#define DFF    1024
#define STOT   20197

// output layout (tuple flattened in order)
#define OUT_PROP   0            // 8*300*256  = 614400
#define OUT_PREF   614400       // 8*300*4    = 9600
#define OUT_PTCOS  624000       // 8*2*300*50 = 240000
#define OUT_PPCOS  864000       // 8*2*300*300= 1440000
#define OUT_PTMM   2304000
#define OUT_PPMM   2544000

__device__ __constant__ int c_hl[4]    = {100, 50, 25, 13};
__device__ __constant__ int c_wl[4]    = {152, 76, 38, 19};
__device__ __constant__ int c_start[4] = {0, 15200, 19000, 19950};

// ---------------- scratch (device globals, no allocation) ----------------
__device__ float g_prop [BB * NP * DIM];
__device__ float g_ppos [BB * NP * DIM];
__device__ float g_off  [BB * NP * 256];
__device__ float g_alog [BB * NP * 128];
__device__ float g_agg  [(size_t)BB * NP * HH * DIM];   // 4.9M floats
__device__ float g_coef [BB * NP * HH];
__device__ float g_capre[BB * NP * DIM];
__device__ float g_ca   [BB * NP * DIM];
__device__ float g_ffn  [BB * NP * DFF];
__device__ float g_track[BB * NT * DIM];
__device__ float g_qh   [BB * NP * DIM];
__device__ float g_kp   [BB * NP * DIM];
__device__ float g_kt   [BB * NT * DIM];
__device__ float g_qn   [BB * NP * NH2];
__device__ float g_kpn  [BB * NP * NH2];
__device__ float g_ktn  [BB * NT * NH2];

// ---------------- packed f32x2 FMA helpers ----------------
__device__ __forceinline__ void fma2(unsigned long long& d, unsigned long long a,
                                     unsigned long long b) {
    asm("fma.rn.f32x2 %0, %1, %2, %3;" : "=l"(d) : "l"(a), "l"(b), "l"(d));
}
__device__ __forceinline__ float2 u2f(unsigned long long u) {
    float2 f;
    f.x = __uint_as_float((unsigned)u);
    f.y = __uint_as_float((unsigned)(u >> 32));
    return f;
}

// ---------------- SGEMM v2:  C = (A [+A2]) @ B + bias, opt ReLU ----------------
// Tile 64(M) x 128(N), BK=16, 256 threads, 4x8 micro-tile via fma.rn.f32x2.
// Requires N % 128 == 0, K % 16 == 0.  A rows stored DUPLICATED in smem so
// ld.shared.v4 yields replicated (a,a) 64-bit pairs directly.
template <bool RELU, bool ADD2>
__global__ void __launch_bounds__(256) sgemm2_kernel(
        const float* __restrict__ A, const float* __restrict__ A2,
        const float* __restrict__ Bm, const float* __restrict__ bias,
        float* __restrict__ C, int M, int N, int K) {
    __shared__ float As2[16][132];   // duplicated rows: [k][2*r],[2*r+1]
    __shared__ float Bs[16][132];
    const int tid = threadIdx.x;
    const int tx = tid & 15;         // 16 col-groups of 8
    const int ty = tid >> 4;         // 16 row-groups of 4
    const int bm = blockIdx.x, bn = blockIdx.y;

    unsigned long long acc[4][4];
    #pragma unroll
    for (int i = 0; i < 4; i++)
        #pragma unroll
        for (int j = 0; j < 4; j++) acc[i][j] = 0ull;

    const int ar = tid >> 2, ac = (tid & 3) * 4;     // A: 64 rows x 16 k
    const int br = tid >> 4, bc = (tid & 15) * 8;    // B: 16 k x 128 cols
    const int arow = bm * 64 + ar;
    const float* Aptr  = A  + (size_t)arow * K + ac;
    const float* A2ptr = ADD2 ? (A2 + (size_t)arow * K + ac) : nullptr;
    const float* Bptr  = Bm + (size_t)br * N + bn * 128 + bc;

    for (int kt = 0; kt < K; kt += 16) {
        float4 av = make_float4(0.f, 0.f, 0.f, 0.f);
        if (arow < M) {
            av = *(const float4*)(Aptr + kt);
            if (ADD2) {
                float4 av2 = *(const float4*)(A2ptr + kt);
                av.x += av2.x; av.y += av2.y; av.z += av2.z; av.w += av2.w;
            }
        }
        *(float2*)&As2[ac + 0][2 * ar] = make_float2(av.x, av.x);
        *(float2*)&As2[ac + 1][2 * ar] = make_float2(av.y, av.y);
        *(float2*)&As2[ac + 2][2 * ar] = make_float2(av.z, av.z);
        *(float2*)&As2[ac + 3][2 * ar] = make_float2(av.w, av.w);
        *(float4*)&Bs[br][bc]     = *(const float4*)(Bptr + (size_t)kt * N);
        *(float4*)&Bs[br][bc + 4] = *(const float4*)(Bptr + (size_t)kt * N + 4);
        __syncthreads();
        #pragma unroll
        for (int k = 0; k < 16; k++) {
            ulonglong2 aA = *(const ulonglong2*)(&As2[k][8 * ty]);      // rows 4ty,4ty+1
            ulonglong2 aB = *(const ulonglong2*)(&As2[k][8 * ty + 4]);  // rows 4ty+2,4ty+3
            ulonglong2 b0 = *(const ulonglong2*)(&Bs[k][8 * tx]);       // cols 0..3
            ulonglong2 b1 = *(const ulonglong2*)(&Bs[k][8 * tx + 4]);   // cols 4..7
            fma2(acc[0][0], aA.x, b0.x); fma2(acc[0][1], aA.x, b0.y);
            fma2(acc[0][2], aA.x, b1.x); fma2(acc[0][3], aA.x, b1.y);
            fma2(acc[1][0], aA.y, b0.x); fma2(acc[1][1], aA.y, b0.y);
            fma2(acc[1][2], aA.y, b1.x); fma2(acc[1][3], aA.y, b1.y);
            fma2(acc[2][0], aB.x, b0.x); fma2(acc[2][1], aB.x, b0.y);
            fma2(acc[2][2], aB.x, b1.x); fma2(acc[2][3], aB.x, b1.y);
            fma2(acc[3][0], aB.y, b0.x); fma2(acc[3][1], aB.y, b0.y);
            fma2(acc[3][2], aB.y, b1.x); fma2(acc[3][3], aB.y, b1.y);
        }
        __syncthreads();
    }

    const int col0 = bn * 128 + tx * 8;
    float4 bia0 = *(const float4*)(bias + col0);
    float4 bia1 = *(const float4*)(bias + col0 + 4);
    #pragma unroll
    for (int i = 0; i < 4; i++) {
        int row = bm * 64 + ty * 4 + i;
        if (row < M) {
            float2 p0 = u2f(acc[i][0]), p1 = u2f(acc[i][1]);
            float2 p2 = u2f(acc[i][2]), p3 = u2f(acc[i][3]);
            float4 o0 = make_float4(p0.x + bia0.x, p0.y + bia0.y,
                                    p1.x + bia0.z, p1.y + bia0.w);
            float4 o1 = make_float4(p2.x + bia1.x, p2.y + bia1.y,
                                    p3.x + bia1.z, p3.y + bia1.w);
            if (RELU) {
                o0.x = fmaxf(o0.x, 0.f); o0.y = fmaxf(o0.y, 0.f);
                o0.z = fmaxf(o0.z, 0.f); o0.w = fmaxf(o0.w, 0.f);
                o1.x = fmaxf(o1.x, 0.f); o1.y = fmaxf(o1.y, 0.f);
                o1.z = fmaxf(o1.z, 0.f); o1.w = fmaxf(o1.w, 0.f);
            }
            *(float4*)(C + (size_t)row * N + col0)     = o0;
            *(float4*)(C + (size_t)row * N + col0 + 4) = o1;
        }
    }
}

// ---------------- misc kernels ----------------
__global__ void posemb_kernel(const float* __restrict__ refp, float* __restrict__ out) {
    int idx = blockIdx.x * blockDim.x + threadIdx.x;
    if (idx >= BB * NP * DIM) return;
    int d = idx & 255;
    int q = (idx >> 8) % NP;
    int b = idx / (256 * NP);
    int c = d >> 6;
    int r = d & 63;
    int j = r >> 1;
    float pos = refp[(b * NQT + q) * 4 + c];
    float t = powf(10000.0f, (float)j / 32.0f);
    float arg = pos * 6.2831853071795864f / t;
    out[idx] = (r & 1) ? cosf(arg) : sinf(arg);
}

__global__ void copy_rows_kernel(const float* __restrict__ src, float* __restrict__ dst,
                                 int rowoff, int nrows) {
    int idx = blockIdx.x * blockDim.x + threadIdx.x;
    int total = BB * nrows * DIM;
    if (idx >= total) return;
    int d = idx & 255;
    int r = (idx >> 8) % nrows;
    int b = idx / (256 * nrows);
    dst[idx] = src[((size_t)(b * NQT + rowoff + r)) * DIM + d];
}

// Aggregating gather with fused softmax: for each (b,q,h) accumulate
// sum coef * src_row (256-dim) and sum coef.  block=(b,q), warp=head.
__global__ void gather2_kernel(const float* __restrict__ refp, const float* __restrict__ src) {
    int bq = blockIdx.x;
    int b = bq / NP, q = bq % NP;
    int h = threadIdx.x >> 5;
    int lane = threadIdx.x & 31;
    const float* r = refp + (size_t)(b * NQT + q) * 4;
    float rx = r[0], ry = r[1], rw = r[2], rh = r[3];
    const float* offp = g_off + (size_t)bq * 256;

    // in-register softmax over this head's 16 logits (all lanes compute; L1 broadcast)
    const float* lg = g_alog + (size_t)bq * 128 + h * 16;
    float logit[16];
    float mx = -1e30f;
    #pragma unroll
    for (int j = 0; j < 16; j++) { logit[j] = __ldg(lg + j); mx = fmaxf(mx, logit[j]); }
    float ssum = 0.f;
    #pragma unroll
    for (int j = 0; j < 16; j++) { logit[j] = expf(logit[j] - mx); ssum += logit[j]; }
    float sinv = 1.0f / ssum;

    float4 a0 = make_float4(0.f, 0.f, 0.f, 0.f);
    float4 a1 = make_float4(0.f, 0.f, 0.f, 0.f);
    float csum = 0.f;

    #pragma unroll
    for (int l = 0; l < 4; l++) {
        int wl = c_wl[l], hl = c_hl[l], st = c_start[l];
        float wlf = (float)wl, hlf = (float)hl;
        const float4* base = (const float4*)(src + ((size_t)b * STOT + st) * DIM);
        #pragma unroll
        for (int p = 0; p < 4; p++) {
            int oi = ((h * 4 + l) * 4 + p) * 2;
            float ox = offp[oi], oy = offp[oi + 1];
            float a = logit[l * 4 + p] * sinv;
            float x = (rx + ox * 0.125f * rw) * wlf - 0.5f;
            float y = (ry + oy * 0.125f * rh) * hlf - 0.5f;
            float x0 = floorf(x), y0 = floorf(y);
            float lx = x - x0, ly = y - y0;
            float wgt[4] = { (1.f - lx) * (1.f - ly), lx * (1.f - ly),
                             (1.f - lx) * ly,         lx * ly };
            float xs[4] = { x0, x0 + 1.f, x0, x0 + 1.f };
            float ys[4] = { y0, y0, y0 + 1.f, y0 + 1.f };
            #pragma unroll
            for (int c = 0; c < 4; c++) {
                float xi = xs[c], yi = ys[c];
                if (xi >= 0.f && xi <= wlf - 1.f && yi >= 0.f && yi <= hlf - 1.f) {
                    int xii = (int)xi, yii = (int)yi;
                    float coef = a * wgt[c];
                    const float4* rp = base + (size_t)(yii * wl + xii) * 64;
                    float4 v0 = rp[lane];
                    float4 v1 = rp[lane + 32];
                    a0.x += coef * v0.x; a0.y += coef * v0.y;
                    a0.z += coef * v0.z; a0.w += coef * v0.w;
                    a1.x += coef * v1.x; a1.y += coef * v1.y;
                    a1.z += coef * v1.z; a1.w += coef * v1.w;
                    csum += coef;
                }
            }
        }
    }
    float4* ag = (float4*)(g_agg + ((size_t)bq * HH + h) * DIM);
    ag[lane] = a0;
    ag[lane + 32] = a1;
    if (lane == 0) g_coef[bq * HH + h] = csum;
}

// Per-head projection: capre[bq][h*32+j] = agg[bq][h] . Wv[:, h*32+j] + coef*bv
__global__ void hproj_kernel(const float* __restrict__ Wv, const float* __restrict__ bv) {
    __shared__ float As[16][65];
    __shared__ float Bs[16][32];
    const int h = blockIdx.y;
    const int bm = blockIdx.x;
    const int tid = threadIdx.x;
    const int tx = tid & 7, ty = tid >> 3;
    float acc[2][4] = {};

    const int ar = tid >> 2, ac = (tid & 3) * 4;
    const int kr = tid >> 4, bc = (tid & 15) * 2;
    const int arow = bm * 64 + ar;

    for (int k0 = 0; k0 < DIM; k0 += 16) {
        float4 av = make_float4(0.f, 0.f, 0.f, 0.f);
        if (arow < BB * NP)
            av = *(const float4*)(g_agg + ((size_t)arow * HH + h) * DIM + k0 + ac);
        As[ac + 0][ar] = av.x; As[ac + 1][ar] = av.y;
        As[ac + 2][ar] = av.z; As[ac + 3][ar] = av.w;
        float2 bvv = *(const float2*)(Wv + (size_t)(k0 + kr) * DIM + h * 32 + bc);
        Bs[kr][bc] = bvv.x; Bs[kr][bc + 1] = bvv.y;
        __syncthreads();
        #pragma unroll
        for (int k = 0; k < 16; k++) {
            float x0 = As[k][ty * 2 + 0], x1 = As[k][ty * 2 + 1];
            float b0 = Bs[k][tx * 4 + 0], b1 = Bs[k][tx * 4 + 1];
            float b2 = Bs[k][tx * 4 + 2], b3 = Bs[k][tx * 4 + 3];
            acc[0][0] += x0 * b0; acc[0][1] += x0 * b1; acc[0][2] += x0 * b2; acc[0][3] += x0 * b3;
            acc[1][0] += x1 * b0; acc[1][1] += x1 * b1; acc[1][2] += x1 * b2; acc[1][3] += x1 * b3;
        }
        __syncthreads();
    }
    #pragma unroll
    for (int i = 0; i < 2; i++) {
        int row = bm * 64 + ty * 2 + i;
        if (row < BB * NP) {
            float cf = g_coef[row * HH + h];
            #pragma unroll
            for (int j = 0; j < 4; j++) {
                int col = h * 32 + tx * 4 + j;
                g_capre[(size_t)row * DIM + col] = acc[i][j] + cf * bv[col];
            }
        }
    }
}

// fused residual + layernorm (warp per row, in-place on g_prop)
__global__ void ln_kernel(const float* __restrict__ addv, const float* __restrict__ w,
                          const float* __restrict__ bia) {
    int row = blockIdx.x * 8 + (threadIdx.x >> 5);
    int lane = threadIdx.x & 31;
    if (row >= BB * NP) return;
    float x[8];
    float s = 0.f;
    #pragma unroll
    for (int i = 0; i < 8; i++) {
        int d = lane + 32 * i;
        x[i] = g_prop[(size_t)row * DIM + d] + addv[(size_t)row * DIM + d];
        s += x[i];
    }
    #pragma unroll
    for (int o = 16; o > 0; o >>= 1) s += __shfl_xor_sync(0xffffffff, s, o);
    float m = s / 256.0f;
    float v = 0.f;
    #pragma unroll
    for (int i = 0; i < 8; i++) { float dd = x[i] - m; v += dd * dd; }
    #pragma unroll
    for (int o = 16; o > 0; o >>= 1) v += __shfl_xor_sync(0xffffffff, v, o);
    v /= 256.0f;
    float inv = rsqrtf(v + 1e-5f);
    #pragma unroll
    for (int i = 0; i < 8; i++) {
        int d = lane + 32 * i;
        g_prop[(size_t)row * DIM + d] = (x[i] - m) * inv * w[d] + bia[d];
    }
}

// per (row, h2) L2 norm of a 128-dim half-row
__global__ void norm_kernel(const float* __restrict__ X, int rows, float* __restrict__ out) {
    int idx = blockIdx.x * blockDim.x + threadIdx.x;
    if (idx >= rows * NH2) return;
    int h = idx & 1, r = idx >> 1;
    const float* x = X + (size_t)r * DIM + h * DH2;
    float s = 0.f;
    #pragma unroll 8
    for (int d = 0; d < 128; d++) { float v = x[d]; s += v * v; }
    out[idx] = sqrtf(s);
}

// fused weight_attn: dots + softmax(mm) + cosine.  grid = (NP, 2, B), 128 threads.
__global__ void wattn_kernel(const float* __restrict__ Q, const float* __restrict__ K,
                             const float* __restrict__ qn, const float* __restrict__ kn,
                             int nk, float* __restrict__ cos_out, float* __restrict__ mm_out) {
    int qi = blockIdx.x, h = blockIdx.y, b = blockIdx.z;
    __shared__ float qv[128];
    __shared__ float sc[304];
    __shared__ float red[128];
    int t = threadIdx.x;
    int qrow = b * NP + qi;
    qv[t] = Q[(size_t)qrow * DIM + h * DH2 + t];
    __syncthreads();
    for (int k = t; k < nk; k += 128) {
        const float* kr = K + ((size_t)(b * nk + k)) * DIM + h * DH2;
        float dot = 0.f;
        #pragma unroll 8
        for (int d = 0; d < 128; d++) dot += qv[d] * kr[d];
        sc[k] = dot;
    }
    __syncthreads();
    const float scale = 0.088388347648318447f;   // 1/sqrt(128)
    float mx = -1e30f;
    for (int k = t; k < nk; k += 128) mx = fmaxf(mx, sc[k] * scale);
    red[t] = mx; __syncthreads();
    for (int s = 64; s > 0; s >>= 1) { if (t < s) red[t] = fmaxf(red[t], red[t + s]); __syncthreads(); }
    mx = red[0]; __syncthreads();
    float sum = 0.f;
    for (int k = t; k < nk; k += 128) sum += expf(sc[k] * scale - mx);
    red[t] = sum; __syncthreads();
    for (int s = 64; s > 0; s >>= 1) { if (t < s) red[t] += red[t + s]; __syncthreads(); }
    sum = red[0];
    float inv = 1.0f / sum;
    float qnv = qn[qrow * NH2 + h] + 1e-6f;
    size_t base = ((size_t)(b * NH2 + h) * NP + qi) * nk;
    for (int k = t; k < nk; k += 128) {
        mm_out[base + k] = expf(sc[k] * scale - mx) * inv;
        float knv = kn[(b * nk + k) * NH2 + h] + 1e-6f;
        cos_out[base + k] = sc[k] / (qnv * knv);
    }
}

__global__ void copy_prop_out(float* __restrict__ out) {
    int idx = blockIdx.x * blockDim.x + threadIdx.x;
    if (idx < BB * NP * DIM) out[OUT_PROP + idx] = g_prop[idx];
}
__global__ void copy_pref_out(const float* __restrict__ refp, float* __restrict__ out) {
    int idx = blockIdx.x * blockDim.x + threadIdx.x;
    if (idx >= BB * NP * 4) return;
    int c = idx & 3;
    int q = (idx >> 2) % NP;
    int b = idx / (4 * NP);
    out[OUT_PREF + idx] = refp[((size_t)(b * NQT + q)) * 4 + c];
}

// ---------------- host orchestration ----------------
static inline int cdiv(int a, int b) { return (a + b - 1) / b; }

extern "C" void kernel_launch(void* const* d_in, const int* in_sizes, int n_in,
                              void* d_out, int out_size) {
    const float* tgt   = (const float*)d_in[0];
    const float* refp  = (const float*)d_in[1];
    const float* src   = (const float*)d_in[2];
    const float* Woff  = (const float*)d_in[7];
    const float* boff  = (const float*)d_in[8];
    const float* Wa    = (const float*)d_in[9];
    const float* ba    = (const float*)d_in[10];
    const float* Wv    = (const float*)d_in[11];
    const float* bv    = (const float*)d_in[12];
    const float* Wout  = (const float*)d_in[13];
    const float* bout  = (const float*)d_in[14];
    const float* Wl1   = (const float*)d_in[15];
    const float* bl1   = (const float*)d_in[16];
    const float* Wl2   = (const float*)d_in[17];
    const float* bl2   = (const float*)d_in[18];
    const float* Wq    = (const float*)d_in[19];
    const float* bq    = (const float*)d_in[20];
    const float* Wk    = (const float*)d_in[21];
    const float* bk    = (const float*)d_in[22];
    const float* n1w   = (const float*)d_in[23];
    const float* n1b   = (const float*)d_in[24];
    const float* n3w   = (const float*)d_in[25];
    const float* n3b   = (const float*)d_in[26];
    float* out = (float*)d_out;

    float *pprop, *pppos, *poff, *palog, *pca, *pffn, *ptrack;
    float *pqh, *pkp, *pkt, *pqn, *pkpn, *pktn, *pcapre;
    cudaGetSymbolAddress((void**)&pprop,  g_prop);
    cudaGetSymbolAddress((void**)&pppos,  g_ppos);
    cudaGetSymbolAddress((void**)&poff,   g_off);
    cudaGetSymbolAddress((void**)&palog,  g_alog);
    cudaGetSymbolAddress((void**)&pcapre, g_capre);
    cudaGetSymbolAddress((void**)&pca,    g_ca);
    cudaGetSymbolAddress((void**)&pffn,   g_ffn);
    cudaGetSymbolAddress((void**)&ptrack, g_track);
    cudaGetSymbolAddress((void**)&pqh,    g_qh);
    cudaGetSymbolAddress((void**)&pkp,    g_kp);
    cudaGetSymbolAddress((void**)&pkt,    g_kt);
    cudaGetSymbolAddress((void**)&pqn,    g_qn);
    cudaGetSymbolAddress((void**)&pkpn,   g_kpn);
    cudaGetSymbolAddress((void**)&pktn,   g_ktn);

    auto gemm = [&](const float* A, const float* Bw, const float* bias, float* C,
                    int M, int N, int K, bool relu) {
        dim3 g(cdiv(M, 64), N / 128);
        if (relu) sgemm2_kernel<true, false><<<g, 256>>>(A, nullptr, Bw, bias, C, M, N, K);
        else      sgemm2_kernel<false, false><<<g, 256>>>(A, nullptr, Bw, bias, C, M, N, K);
    };
    auto gemm_add = [&](const float* A, const float* A2, const float* Bw, const float* bias,
                        float* C, int M, int N, int K) {
        dim3 g(cdiv(M, 64), N / 128);
        sgemm2_kernel<false, true><<<g, 256>>>(A, A2, Bw, bias, C, M, N, K);
    };

    const int NPROPS = BB * NP;        // 2400 proposal rows
    const int NEL = NPROPS * DIM;      // 614400

    copy_rows_kernel<<<cdiv(NEL, 256), 256>>>(tgt, pprop, 0, NP);
    copy_rows_kernel<<<cdiv(BB * NT * DIM, 256), 256>>>(tgt, ptrack, NP, NT);
    posemb_kernel<<<cdiv(NEL, 256), 256>>>(refp, pppos);

    for (int l = 0; l < NLAY; l++) {
        // offsets + attention logits from q = prop + pos (add fused into A-load)
        gemm_add(pprop, pppos, Woff + (size_t)l * DIM * 256, boff + l * 256, poff,
                 NPROPS, 256, DIM);
        gemm_add(pprop, pppos, Wa + (size_t)l * DIM * 128, ba + l * 128, palog,
                 NPROPS, 128, DIM);
        // aggregate src rows with combined softmax*bilinear coefficients
        gather2_kernel<<<BB * NP, 256>>>(refp, src);
        // per-head projection through Wv (+ coef-weighted bias)
        dim3 hg(cdiv(NPROPS, 64), HH);
        hproj_kernel<<<hg, 256>>>(Wv + (size_t)l * DIM * DIM, bv + l * DIM);
        // output projection
        gemm(pcapre, Wout + (size_t)l * DIM * DIM, bout + l * DIM, pca, NPROPS, DIM, DIM, false);
        // residual + LN1
        ln_kernel<<<cdiv(NPROPS, 8), 256>>>(pca, n1w + l * DIM, n1b + l * DIM);
        // FFN
        gemm(pprop, Wl1 + (size_t)l * DIM * DFF, bl1 + l * DFF, pffn, NPROPS, DFF, DIM, true);
        gemm(pffn, Wl2 + (size_t)l * DFF * DIM, bl2 + l * DIM, pca, NPROPS, DIM, DFF, false);
        // residual + LN3
        ln_kernel<<<cdiv(NPROPS, 8), 256>>>(pca, n3w + l * DIM, n3b + l * DIM);
    }

    // weight_attn only matters for the last layer's weights
    const int L = NLAY - 1;
    gemm(pprop,  Wq + (size_t)L * DIM * DIM, bq + L * DIM, pqh, NPROPS, DIM, DIM, false);
    gemm(pprop,  Wk + (size_t)L * DIM * DIM, bk + L * DIM, pkp, NPROPS, DIM, DIM, false);
    gemm(ptrack, Wk + (size_t)L * DIM * DIM, bk + L * DIM, pkt, BB * NT, DIM, DIM, false);
    norm_kernel<<<cdiv(NPROPS * NH2, 256), 256>>>(pqh, NPROPS, pqn);
    norm_kernel<<<cdiv(NPROPS * NH2, 256), 256>>>(pkp, NPROPS, pkpn);
    norm_kernel<<<cdiv(BB * NT * NH2, 256), 256>>>(pkt, BB * NT, pktn);

    dim3 wg(NP, NH2, BB);
    wattn_kernel<<<wg, 128>>>(pqh, pkt, pqn, pktn, NT, out + OUT_PTCOS, out + OUT_PTMM);
    wattn_kernel<<<wg, 128>>>(pqh, pkp, pqn, pkpn, NP, out + OUT_PPCOS, out + OUT_PPMM);

    copy_prop_out<<<cdiv(NEL, 256), 256>>>(out);
    copy_pref_out<<<cdiv(BB * NP * 4, 256), 256>>>(refp, out);
}

// round 7
// speedup vs baseline: 1.5147x; 1.5147x over previous
#include <cuda_runtime.h>
#include <cuda_bf16.h>
#include <math.h>

// ---------------- problem constants ----------------
#define BB     8
#define NQT    350
#define NP     300
#define NT     50
#define DIM    256
#define HH     8
#define DH     32
#define NLVL   4
#define NPNT   4
#define NLAY   6
#define NH2    2
#define DH2    128
#define DFF    1024
#define STOT   20197

// output layout (tuple flattened in order)
#define OUT_PROP   0            // 8*300*256  = 614400
#define OUT_PREF   614400       // 8*300*4    = 9600
#define OUT_PTCOS  624000       // 8*2*300*50 = 240000
#define OUT_PPCOS  864000       // 8*2*300*300= 1440000
#define OUT_PTMM   2304000
#define OUT_PPMM   2544000

__device__ __constant__ int c_hl[4]    = {100, 50, 25, 13};
__device__ __constant__ int c_wl[4]    = {152, 76, 38, 19};
__device__ __constant__ int c_start[4] = {0, 15200, 19000, 19950};

// ---------------- scratch (device globals, no allocation) ----------------
__device__ float g_prop [BB * NP * DIM];
__device__ float g_ppos [BB * NP * DIM];
__device__ float g_off  [BB * NP * 256];
__device__ float g_alog [BB * NP * 128];
__device__ float g_agg  [(size_t)BB * NP * HH * DIM];
__device__ float g_coef [BB * NP * HH];
__device__ float g_capre[BB * NP * DIM];
__device__ float g_ca   [BB * NP * DIM];
__device__ float g_ffn  [BB * NP * DFF];
__device__ float g_track[BB * NT * DIM];
__device__ float g_qh   [BB * NP * DIM];
__device__ float g_kp   [BB * NP * DIM];
__device__ float g_kt   [BB * NT * DIM];
__device__ float g_qn   [BB * NP * NH2];
__device__ float g_kpn  [BB * NP * NH2];
__device__ float g_ktn  [BB * NT * NH2];

// ---------------- bf16-split tensor-core GEMM ----------------
// C(MxN) = (A [+A2])(MxK) @ B(KxN) + bias, optional ReLU.
// fp32 emulated as bf16 hi/lo split: x*y ~= xh*yh + xh*yl + xl*yh  (rel err ~2^-17).
// Block tile 64x64, BK=32, 256 threads = 8 warps (2 M x 4 N).
// Requires N % 64 == 0, K % 32 == 0.

__device__ __forceinline__ unsigned pack_bf2(__nv_bfloat16 x, __nv_bfloat16 y) {
    __nv_bfloat162 h2; h2.x = x; h2.y = y;
    return *(unsigned*)&h2;
}

__device__ __forceinline__ void mma_bf16(float* c, const unsigned* a, const unsigned* b) {
    asm volatile(
        "mma.sync.aligned.m16n8k16.row.col.f32.bf16.bf16.f32 "
        "{%0,%1,%2,%3}, {%4,%5,%6,%7}, {%8,%9}, {%0,%1,%2,%3};"
        : "+f"(c[0]), "+f"(c[1]), "+f"(c[2]), "+f"(c[3])
        : "r"(a[0]), "r"(a[1]), "r"(a[2]), "r"(a[3]), "r"(b[0]), "r"(b[1]));
}

#define SPAD 20   // row pitch in u32; (gid*20 + tig) mod 32 covers all banks conflict-free

template <bool RELU, bool ADD2>
__global__ void __launch_bounds__(256) mma_gemm_kernel(
        const float* __restrict__ A, const float* __restrict__ A2,
        const float* __restrict__ Bm, const float* __restrict__ bias,
        float* __restrict__ C, int M, int N, int K) {
    __shared__ unsigned sAh[64][SPAD], sAl[64][SPAD];
    __shared__ unsigned sBh[64][SPAD], sBl[64][SPAD];

    const int tid = threadIdx.x;
    const int w = tid >> 5, lane = tid & 31;
    const int gid = lane >> 2, tig = lane & 3;
    const int wm = w >> 2, wn = w & 3;           // 2 x 4 warp grid
    const int bm = blockIdx.x, bn = blockIdx.y;

    float acc[2][2][4];
    #pragma unroll
    for (int i = 0; i < 2; i++)
        #pragma unroll
        for (int j = 0; j < 2; j++)
            #pragma unroll
            for (int r = 0; r < 4; r++) acc[i][j][r] = 0.f;

    for (int kb = 0; kb < K; kb += 32) {
        // --- load A tile: 64 rows x 16 kpairs ---
        #pragma unroll
        for (int i = 0; i < 4; i++) {
            int e = tid + i * 256;
            int row = e >> 4, kp = e & 15;
            int grow = bm * 64 + row;
            float2 v = make_float2(0.f, 0.f);
            if (grow < M) {
                v = *(const float2*)(A + (size_t)grow * K + kb + 2 * kp);
                if (ADD2) {
                    float2 v2 = *(const float2*)(A2 + (size_t)grow * K + kb + 2 * kp);
                    v.x += v2.x; v.y += v2.y;
                }
            }
            __nv_bfloat16 hx = __float2bfloat16_rn(v.x);
            __nv_bfloat16 hy = __float2bfloat16_rn(v.y);
            __nv_bfloat16 lx = __float2bfloat16_rn(v.x - __bfloat162float(hx));
            __nv_bfloat16 ly = __float2bfloat16_rn(v.y - __bfloat162float(hy));
            sAh[row][kp] = pack_bf2(hx, hy);
            sAl[row][kp] = pack_bf2(lx, ly);
        }
        // --- load B tile: 64 cols x 16 kpairs (k-pairs packed per column) ---
        #pragma unroll
        for (int i = 0; i < 4; i++) {
            int e = tid + i * 256;
            int n = e & 63, kp = e >> 6;          // kp = i*4 + tid/64
            int gk = kb + 2 * kp;
            float vx = Bm[(size_t)gk * N + bn * 64 + n];
            float vy = Bm[(size_t)(gk + 1) * N + bn * 64 + n];
            __nv_bfloat16 hx = __float2bfloat16_rn(vx);
            __nv_bfloat16 hy = __float2bfloat16_rn(vy);
            __nv_bfloat16 lx = __float2bfloat16_rn(vx - __bfloat162float(hx));
            __nv_bfloat16 ly = __float2bfloat16_rn(vy - __bfloat162float(hy));
            sBh[n][kp] = pack_bf2(hx, hy);
            sBl[n][kp] = pack_bf2(lx, ly);
        }
        __syncthreads();

        #pragma unroll
        for (int ks = 0; ks < 2; ks++) {
            const int kp0 = ks * 8;
            unsigned ah[2][4], al[2][4];
            #pragma unroll
            for (int mt = 0; mt < 2; mt++) {
                int r0 = wm * 32 + mt * 16;
                ah[mt][0] = sAh[r0 + gid    ][kp0 + tig];
                ah[mt][1] = sAh[r0 + gid + 8][kp0 + tig];
                ah[mt][2] = sAh[r0 + gid    ][kp0 + tig + 4];
                ah[mt][3] = sAh[r0 + gid + 8][kp0 + tig + 4];
                al[mt][0] = sAl[r0 + gid    ][kp0 + tig];
                al[mt][1] = sAl[r0 + gid + 8][kp0 + tig];
                al[mt][2] = sAl[r0 + gid    ][kp0 + tig + 4];
                al[mt][3] = sAl[r0 + gid + 8][kp0 + tig + 4];
            }
            unsigned bh[2][2], bl[2][2];
            #pragma unroll
            for (int nt = 0; nt < 2; nt++) {
                int c0 = wn * 16 + nt * 8 + gid;
                bh[nt][0] = sBh[c0][kp0 + tig];
                bh[nt][1] = sBh[c0][kp0 + tig + 4];
                bl[nt][0] = sBl[c0][kp0 + tig];
                bl[nt][1] = sBl[c0][kp0 + tig + 4];
            }
            #pragma unroll
            for (int mt = 0; mt < 2; mt++)
                #pragma unroll
                for (int nt = 0; nt < 2; nt++) {
                    mma_bf16(acc[mt][nt], ah[mt], bh[nt]);   // hi*hi
                    mma_bf16(acc[mt][nt], ah[mt], bl[nt]);   // hi*lo
                    mma_bf16(acc[mt][nt], al[mt], bh[nt]);   // lo*hi
                }
        }
        __syncthreads();
    }

    // epilogue: c0,c1 -> row gid, cols 2tig,2tig+1 ; c2,c3 -> row gid+8
    #pragma unroll
    for (int mt = 0; mt < 2; mt++) {
        #pragma unroll
        for (int nt = 0; nt < 2; nt++) {
            int col = bn * 64 + wn * 16 + nt * 8 + tig * 2;
            float b0 = bias[col], b1 = bias[col + 1];
            int row0 = bm * 64 + wm * 32 + mt * 16 + gid;
            if (row0 < M) {
                float o0 = acc[mt][nt][0] + b0, o1 = acc[mt][nt][1] + b1;
                if (RELU) { o0 = fmaxf(o0, 0.f); o1 = fmaxf(o1, 0.f); }
                *(float2*)(C + (size_t)row0 * N + col) = make_float2(o0, o1);
            }
            int row1 = row0 + 8;
            if (row1 < M) {
                float o2 = acc[mt][nt][2] + b0, o3 = acc[mt][nt][3] + b1;
                if (RELU) { o2 = fmaxf(o2, 0.f); o3 = fmaxf(o3, 0.f); }
                *(float2*)(C + (size_t)row1 * N + col) = make_float2(o2, o3);
            }
        }
    }
}

// ---------------- misc kernels ----------------
__global__ void posemb_kernel(const float* __restrict__ refp, float* __restrict__ out) {
    int idx = blockIdx.x * blockDim.x + threadIdx.x;
    if (idx >= BB * NP * DIM) return;
    int d = idx & 255;
    int q = (idx >> 8) % NP;
    int b = idx / (256 * NP);
    int c = d >> 6;
    int r = d & 63;
    int j = r >> 1;
    float pos = refp[(b * NQT + q) * 4 + c];
    float t = powf(10000.0f, (float)j / 32.0f);
    float arg = pos * 6.2831853071795864f / t;
    out[idx] = (r & 1) ? cosf(arg) : sinf(arg);
}

__global__ void copy_rows_kernel(const float* __restrict__ src, float* __restrict__ dst,
                                 int rowoff, int nrows) {
    int idx = blockIdx.x * blockDim.x + threadIdx.x;
    int total = BB * nrows * DIM;
    if (idx >= total) return;
    int d = idx & 255;
    int r = (idx >> 8) % nrows;
    int b = idx / (256 * nrows);
    dst[idx] = src[((size_t)(b * NQT + rowoff + r)) * DIM + d];
}

// Aggregating gather with fused softmax: block=(b,q), warp=head.
__global__ void gather2_kernel(const float* __restrict__ refp, const float* __restrict__ src) {
    int bq = blockIdx.x;
    int b = bq / NP, q = bq % NP;
    int h = threadIdx.x >> 5;
    int lane = threadIdx.x & 31;
    const float* r = refp + (size_t)(b * NQT + q) * 4;
    float rx = r[0], ry = r[1], rw = r[2], rh = r[3];
    const float* offp = g_off + (size_t)bq * 256;

    const float* lg = g_alog + (size_t)bq * 128 + h * 16;
    float logit[16];
    float mx = -1e30f;
    #pragma unroll
    for (int j = 0; j < 16; j++) { logit[j] = __ldg(lg + j); mx = fmaxf(mx, logit[j]); }
    float ssum = 0.f;
    #pragma unroll
    for (int j = 0; j < 16; j++) { logit[j] = expf(logit[j] - mx); ssum += logit[j]; }
    float sinv = 1.0f / ssum;

    float4 a0 = make_float4(0.f, 0.f, 0.f, 0.f);
    float4 a1 = make_float4(0.f, 0.f, 0.f, 0.f);
    float csum = 0.f;

    #pragma unroll
    for (int l = 0; l < 4; l++) {
        int wl = c_wl[l], hl = c_hl[l], st = c_start[l];
        float wlf = (float)wl, hlf = (float)hl;
        const float4* base = (const float4*)(src + ((size_t)b * STOT + st) * DIM);
        #pragma unroll
        for (int p = 0; p < 4; p++) {
            int oi = ((h * 4 + l) * 4 + p) * 2;
            float ox = offp[oi], oy = offp[oi + 1];
            float a = logit[l * 4 + p] * sinv;
            float x = (rx + ox * 0.125f * rw) * wlf - 0.5f;
            float y = (ry + oy * 0.125f * rh) * hlf - 0.5f;
            float x0 = floorf(x), y0 = floorf(y);
            float lx = x - x0, ly = y - y0;
            float wgt[4] = { (1.f - lx) * (1.f - ly), lx * (1.f - ly),
                             (1.f - lx) * ly,         lx * ly };
            float xs[4] = { x0, x0 + 1.f, x0, x0 + 1.f };
            float ys[4] = { y0, y0, y0 + 1.f, y0 + 1.f };
            #pragma unroll
            for (int c = 0; c < 4; c++) {
                float xi = xs[c], yi = ys[c];
                if (xi >= 0.f && xi <= wlf - 1.f && yi >= 0.f && yi <= hlf - 1.f) {
                    int xii = (int)xi, yii = (int)yi;
                    float coef = a * wgt[c];
                    const float4* rp = base + (size_t)(yii * wl + xii) * 64;
                    float4 v0 = rp[lane];
                    float4 v1 = rp[lane + 32];
                    a0.x += coef * v0.x; a0.y += coef * v0.y;
                    a0.z += coef * v0.z; a0.w += coef * v0.w;
                    a1.x += coef * v1.x; a1.y += coef * v1.y;
                    a1.z += coef * v1.z; a1.w += coef * v1.w;
                    csum += coef;
                }
            }
        }
    }
    float4* ag = (float4*)(g_agg + ((size_t)bq * HH + h) * DIM);
    ag[lane] = a0;
    ag[lane + 32] = a1;
    if (lane == 0) g_coef[bq * HH + h] = csum;
}

// Per-head projection: capre[bq][h*32+j] = agg[bq][h] . Wv[:, h*32+j] + coef*bv
__global__ void hproj_kernel(const float* __restrict__ Wv, const float* __restrict__ bv) {
    __shared__ float As[16][65];
    __shared__ float Bs[16][32];
    const int h = blockIdx.y;
    const int bm = blockIdx.x;
    const int tid = threadIdx.x;
    const int tx = tid & 7, ty = tid >> 3;
    float acc[2][4] = {};

    const int ar = tid >> 2, ac = (tid & 3) * 4;
    const int kr = tid >> 4, bc = (tid & 15) * 2;
    const int arow = bm * 64 + ar;

    for (int k0 = 0; k0 < DIM; k0 += 16) {
        float4 av = make_float4(0.f, 0.f, 0.f, 0.f);
        if (arow < BB * NP)
            av = *(const float4*)(g_agg + ((size_t)arow * HH + h) * DIM + k0 + ac);
        As[ac + 0][ar] = av.x; As[ac + 1][ar] = av.y;
        As[ac + 2][ar] = av.z; As[ac + 3][ar] = av.w;
        float2 bvv = *(const float2*)(Wv + (size_t)(k0 + kr) * DIM + h * 32 + bc);
        Bs[kr][bc] = bvv.x; Bs[kr][bc + 1] = bvv.y;
        __syncthreads();
        #pragma unroll
        for (int k = 0; k < 16; k++) {
            float x0 = As[k][ty * 2 + 0], x1 = As[k][ty * 2 + 1];
            float b0 = Bs[k][tx * 4 + 0], b1 = Bs[k][tx * 4 + 1];
            float b2 = Bs[k][tx * 4 + 2], b3 = Bs[k][tx * 4 + 3];
            acc[0][0] += x0 * b0; acc[0][1] += x0 * b1; acc[0][2] += x0 * b2; acc[0][3] += x0 * b3;
            acc[1][0] += x1 * b0; acc[1][1] += x1 * b1; acc[1][2] += x1 * b2; acc[1][3] += x1 * b3;
        }
        __syncthreads();
    }
    #pragma unroll
    for (int i = 0; i < 2; i++) {
        int row = bm * 64 + ty * 2 + i;
        if (row < BB * NP) {
            float cf = g_coef[row * HH + h];
            #pragma unroll
            for (int j = 0; j < 4; j++) {
                int col = h * 32 + tx * 4 + j;
                g_capre[(size_t)row * DIM + col] = acc[i][j] + cf * bv[col];
            }
        }
    }
}

// fused residual + layernorm (warp per row, in-place on g_prop)
__global__ void ln_kernel(const float* __restrict__ addv, const float* __restrict__ w,
                          const float* __restrict__ bia) {
    int row = blockIdx.x * 8 + (threadIdx.x >> 5);
    int lane = threadIdx.x & 31;
    if (row >= BB * NP) return;
    float x[8];
    float s = 0.f;
    #pragma unroll
    for (int i = 0; i < 8; i++) {
        int d = lane + 32 * i;
        x[i] = g_prop[(size_t)row * DIM + d] + addv[(size_t)row * DIM + d];
        s += x[i];
    }
    #pragma unroll
    for (int o = 16; o > 0; o >>= 1) s += __shfl_xor_sync(0xffffffff, s, o);
    float m = s / 256.0f;
    float v = 0.f;
    #pragma unroll
    for (int i = 0; i < 8; i++) { float dd = x[i] - m; v += dd * dd; }
    #pragma unroll
    for (int o = 16; o > 0; o >>= 1) v += __shfl_xor_sync(0xffffffff, v, o);
    v /= 256.0f;
    float inv = rsqrtf(v + 1e-5f);
    #pragma unroll
    for (int i = 0; i < 8; i++) {
        int d = lane + 32 * i;
        g_prop[(size_t)row * DIM + d] = (x[i] - m) * inv * w[d] + bia[d];
    }
}

// per (row, h2) L2 norm of a 128-dim half-row
__global__ void norm_kernel(const float* __restrict__ X, int rows, float* __restrict__ out) {
    int idx = blockIdx.x * blockDim.x + threadIdx.x;
    if (idx >= rows * NH2) return;
    int h = idx & 1, r = idx >> 1;
    const float* x = X + (size_t)r * DIM + h * DH2;
    float s = 0.f;
    #pragma unroll 8
    for (int d = 0; d < 128; d++) { float v = x[d]; s += v * v; }
    out[idx] = sqrtf(s);
}

// fused weight_attn: dots + softmax(mm) + cosine.  grid = (NP, 2, B), 128 threads.
__global__ void wattn_kernel(const float* __restrict__ Q, const float* __restrict__ K,
                             const float* __restrict__ qn, const float* __restrict__ kn,
                             int nk, float* __restrict__ cos_out, float* __restrict__ mm_out) {
    int qi = blockIdx.x, h = blockIdx.y, b = blockIdx.z;
    __shared__ float qv[128];
    __shared__ float sc[304];
    __shared__ float red[128];
    int t = threadIdx.x;
    int qrow = b * NP + qi;
    qv[t] = Q[(size_t)qrow * DIM + h * DH2 + t];
    __syncthreads();
    for (int k = t; k < nk; k += 128) {
        const float* kr = K + ((size_t)(b * nk + k)) * DIM + h * DH2;
        float dot = 0.f;
        #pragma unroll 8
        for (int d = 0; d < 128; d++) dot += qv[d] * kr[d];
        sc[k] = dot;
    }
    __syncthreads();
    const float scale = 0.088388347648318447f;   // 1/sqrt(128)
    float mx = -1e30f;
    for (int k = t; k < nk; k += 128) mx = fmaxf(mx, sc[k] * scale);
    red[t] = mx; __syncthreads();
    for (int s = 64; s > 0; s >>= 1) { if (t < s) red[t] = fmaxf(red[t], red[t + s]); __syncthreads(); }
    mx = red[0]; __syncthreads();
    float sum = 0.f;
    for (int k = t; k < nk; k += 128) sum += expf(sc[k] * scale - mx);
    red[t] = sum; __syncthreads();
    for (int s = 64; s > 0; s >>= 1) { if (t < s) red[t] += red[t + s]; __syncthreads(); }
    sum = red[0];
    float inv = 1.0f / sum;
    float qnv = qn[qrow * NH2 + h] + 1e-6f;
    size_t base = ((size_t)(b * NH2 + h) * NP + qi) * nk;
    for (int k = t; k < nk; k += 128) {
        mm_out[base + k] = expf(sc[k] * scale - mx) * inv;
        float knv = kn[(b * nk + k) * NH2 + h] + 1e-6f;
        cos_out[base + k] = sc[k] / (qnv * knv);
    }
}

__global__ void copy_prop_out(float* __restrict__ out) {
    int idx = blockIdx.x * blockDim.x + threadIdx.x;
    if (idx < BB * NP * DIM) out[OUT_PROP + idx] = g_prop[idx];
}
__global__ void copy_pref_out(const float* __restrict__ refp, float* __restrict__ out) {
    int idx = blockIdx.x * blockDim.x + threadIdx.x;
    if (idx >= BB * NP * 4) return;
    int c = idx & 3;
    int q = (idx >> 2) % NP;
    int b = idx / (4 * NP);
    out[OUT_PREF + idx] = refp[((size_t)(b * NQT + q)) * 4 + c];
}

// ---------------- host orchestration ----------------
static inline int cdiv(int a, int b) { return (a + b - 1) / b; }

extern "C" void kernel_launch(void* const* d_in, const int* in_sizes, int n_in,
                              void* d_out, int out_size) {
    const float* tgt   = (const float*)d_in[0];
    const float* refp  = (const float*)d_in[1];
    const float* src   = (const float*)d_in[2];
    const float* Woff  = (const float*)d_in[7];
    const float* boff  = (const float*)d_in[8];
    const float* Wa    = (const float*)d_in[9];
    const float* ba    = (const float*)d_in[10];
    const float* Wv    = (const float*)d_in[11];
    const float* bv    = (const float*)d_in[12];
    const float* Wout  = (const float*)d_in[13];
    const float* bout  = (const float*)d_in[14];
    const float* Wl1   = (const float*)d_in[15];
    const float* bl1   = (const float*)d_in[16];
    const float* Wl2   = (const float*)d_in[17];
    const float* bl2   = (const float*)d_in[18];
    const float* Wq    = (const float*)d_in[19];
    const float* bq    = (const float*)d_in[20];
    const float* Wk    = (const float*)d_in[21];
    const float* bk    = (const float*)d_in[22];
    const float* n1w   = (const float*)d_in[23];
    const float* n1b   = (const float*)d_in[24];
    const float* n3w   = (const float*)d_in[25];
    const float* n3b   = (const float*)d_in[26];
    float* out = (float*)d_out;

    float *pprop, *pppos, *poff, *palog, *pca, *pffn, *ptrack;
    float *pqh, *pkp, *pkt, *pqn, *pkpn, *pktn, *pcapre;
    cudaGetSymbolAddress((void**)&pprop,  g_prop);
    cudaGetSymbolAddress((void**)&pppos,  g_ppos);
    cudaGetSymbolAddress((void**)&poff,   g_off);
    cudaGetSymbolAddress((void**)&palog,  g_alog);
    cudaGetSymbolAddress((void**)&pcapre, g_capre);
    cudaGetSymbolAddress((void**)&pca,    g_ca);
    cudaGetSymbolAddress((void**)&pffn,   g_ffn);
    cudaGetSymbolAddress((void**)&ptrack, g_track);
    cudaGetSymbolAddress((void**)&pqh,    g_qh);
    cudaGetSymbolAddress((void**)&pkp,    g_kp);
    cudaGetSymbolAddress((void**)&pkt,    g_kt);
    cudaGetSymbolAddress((void**)&pqn,    g_qn);
    cudaGetSymbolAddress((void**)&pkpn,   g_kpn);
    cudaGetSymbolAddress((void**)&pktn,   g_ktn);

    auto gemm = [&](const float* A, const float* Bw, const float* bias, float* C,
                    int M, int N, int K, bool relu) {
        dim3 g(cdiv(M, 64), N / 64);
        if (relu) mma_gemm_kernel<true, false><<<g, 256>>>(A, nullptr, Bw, bias, C, M, N, K);
        else      mma_gemm_kernel<false, false><<<g, 256>>>(A, nullptr, Bw, bias, C, M, N, K);
    };
    auto gemm_add = [&](const float* A, const float* A2, const float* Bw, const float* bias,
                        float* C, int M, int N, int K) {
        dim3 g(cdiv(M, 64), N / 64);
        mma_gemm_kernel<false, true><<<g, 256>>>(A, A2, Bw, bias, C, M, N, K);
    };

    const int NPROPS = BB * NP;        // 2400 proposal rows
    const int NEL = NPROPS * DIM;      // 614400

    copy_rows_kernel<<<cdiv(NEL, 256), 256>>>(tgt, pprop, 0, NP);
    copy_rows_kernel<<<cdiv(BB * NT * DIM, 256), 256>>>(tgt, ptrack, NP, NT);
    posemb_kernel<<<cdiv(NEL, 256), 256>>>(refp, pppos);

    for (int l = 0; l < NLAY; l++) {
        // offsets + attention logits from q = prop + pos (add fused into A-load)
        gemm_add(pprop, pppos, Woff + (size_t)l * DIM * 256, boff + l * 256, poff,
                 NPROPS, 256, DIM);
        gemm_add(pprop, pppos, Wa + (size_t)l * DIM * 128, ba + l * 128, palog,
                 NPROPS, 128, DIM);
        // aggregate src rows with combined softmax*bilinear coefficients
        gather2_kernel<<<BB * NP, 256>>>(refp, src);
        // per-head projection through Wv (+ coef-weighted bias)
        dim3 hg(cdiv(NPROPS, 64), HH);
        hproj_kernel<<<hg, 256>>>(Wv + (size_t)l * DIM * DIM, bv + l * DIM);
        // output projection
        gemm(pcapre, Wout + (size_t)l * DIM * DIM, bout + l * DIM, pca, NPROPS, DIM, DIM, false);
        // residual + LN1
        ln_kernel<<<cdiv(NPROPS, 8), 256>>>(pca, n1w + l * DIM, n1b + l * DIM);
        // FFN
        gemm(pprop, Wl1 + (size_t)l * DIM * DFF, bl1 + l * DFF, pffn, NPROPS, DFF, DIM, true);
        gemm(pffn, Wl2 + (size_t)l * DFF * DIM, bl2 + l * DIM, pca, NPROPS, DIM, DFF, false);
        // residual + LN3
        ln_kernel<<<cdiv(NPROPS, 8), 256>>>(pca, n3w + l * DIM, n3b + l * DIM);
    }

    // weight_attn only matters for the last layer's weights
    const int L = NLAY - 1;
    gemm(pprop,  Wq + (size_t)L * DIM * DIM, bq + L * DIM, pqh, NPROPS, DIM, DIM, false);
    gemm(pprop,  Wk + (size_t)L * DIM * DIM, bk + L * DIM, pkp, NPROPS, DIM, DIM, false);
    gemm(ptrack, Wk + (size_t)L * DIM * DIM, bk + L * DIM, pkt, BB * NT, DIM, DIM, false);
    norm_kernel<<<cdiv(NPROPS * NH2, 256), 256>>>(pqh, NPROPS, pqn);
    norm_kernel<<<cdiv(NPROPS * NH2, 256), 256>>>(pkp, NPROPS, pkpn);
    norm_kernel<<<cdiv(BB * NT * NH2, 256), 256>>>(pkt, BB * NT, pktn);

    dim3 wg(NP, NH2, BB);
    wattn_kernel<<<wg, 128>>>(pqh, pkt, pqn, pktn, NT, out + OUT_PTCOS, out + OUT_PTMM);
    wattn_kernel<<<wg, 128>>>(pqh, pkp, pqn, pkpn, NP, out + OUT_PPCOS, out + OUT_PPMM);

    copy_prop_out<<<cdiv(NEL, 256), 256>>>(out);
    copy_pref_out<<<cdiv(BB * NP * 4, 256), 256>>>(refp, out);
}

// round 10
// speedup vs baseline: 1.7084x; 1.1279x over previous
#include <cuda_runtime.h>
#include <cuda_bf16.h>
#include <math.h>

// ---------------- problem constants ----------------
#define BB     8
#define NQT    350
#define NP     300
#define NT     50
#define DIM    256
#define HH     8
#define DH     32
#define NLAY   6
#define NH2    2
#define DH2    128
#define DFF    1024
#define STOT   20197
#define OA     384          // packed Woff|Wa output row stride

// output layout (tuple flattened in order)
#define OUT_PROP   0
#define OUT_PREF   614400
#define OUT_PTCOS  624000
#define OUT_PPCOS  864000
#define OUT_PTMM   2304000
#define OUT_PPMM   2544000

__device__ __constant__ int c_hl[4]    = {100, 50, 25, 13};
__device__ __constant__ int c_wl[4]    = {152, 76, 38, 19};
__device__ __constant__ int c_start[4] = {0, 15200, 19000, 19950};

// ---------------- scratch (device globals, no allocation) ----------------
__device__ float g_prop [BB * NP * DIM];
__device__ float g_ppos [BB * NP * DIM];
__device__ float g_off  [BB * NP * OA];     // packed: offsets [0..255], attn logits [256..383]
__device__ float g_agg  [(size_t)BB * NP * HH * DIM];
__device__ float g_coef [BB * NP * HH];
__device__ float g_capre[BB * NP * DIM];
__device__ float g_ca   [BB * NP * DIM];
__device__ float g_ffn  [BB * NP * DFF];
__device__ float g_track[BB * NT * DIM];
__device__ float g_qk   [BB * NP * 512];    // packed q|k projection of proposals
__device__ float g_kt   [BB * NT * DIM];
__device__ float g_qn   [BB * NP * NH2];
__device__ float g_kpn  [BB * NP * NH2];
__device__ float g_ktn  [BB * NT * NH2];

// pre-split bf16 weights (hi/lo)
#define S1 (NLAY * 256 * 384)     // Woff|Wa packed
#define S2 (NLAY * 256 * 256)     // Wout
#define S3 (NLAY * 256 * 1024)    // Wl1
#define S4 (NLAY * 1024 * 256)    // Wl2
#define S5 (256 * 512)            // Wq|Wk (last layer)
#define SB1 (NLAY * 384)
#define SB5 (512)
__device__ __nv_bfloat16 g_w1h[S1], g_w1l[S1];
__device__ __nv_bfloat16 g_w2h[S2], g_w2l[S2];
__device__ __nv_bfloat16 g_w3h[S3], g_w3l[S3];
__device__ __nv_bfloat16 g_w4h[S4], g_w4l[S4];
__device__ __nv_bfloat16 g_w5h[S5], g_w5l[S5];
__device__ float g_b1[SB1];
__device__ float g_b5[SB5];

__device__ __forceinline__ unsigned pack_bf2(__nv_bfloat16 x, __nv_bfloat16 y) {
    __nv_bfloat162 h2; h2.x = x; h2.y = y;
    return *(unsigned*)&h2;
}
__device__ __forceinline__ void split_store(float v, __nv_bfloat16* H, __nv_bfloat16* L, long i) {
    __nv_bfloat16 h = __float2bfloat16_rn(v);
    H[i] = h;
    L[i] = __float2bfloat16_rn(v - __bfloat162float(h));
}

// ---------------- one-shot weight conversion / packing ----------------
__global__ void convert_all(const float* __restrict__ Woff, const float* __restrict__ Wa,
                            const float* __restrict__ Wout, const float* __restrict__ Wl1,
                            const float* __restrict__ Wl2, const float* __restrict__ Wq,
                            const float* __restrict__ Wk, const float* __restrict__ boff,
                            const float* __restrict__ ba, const float* __restrict__ bqv,
                            const float* __restrict__ bkv) {
    long i = (long)blockIdx.x * blockDim.x + threadIdx.x;
    if (i < S1) {
        int l = (int)(i / 98304); int rem = (int)(i % 98304); int r = rem / 384; int c = rem % 384;
        float v = (c < 256) ? Woff[(size_t)l * 65536 + r * 256 + c]
                            : Wa[(size_t)l * 32768 + r * 128 + (c - 256)];
        split_store(v, g_w1h, g_w1l, i); return;
    }
    i -= S1;
    if (i < S2) { split_store(Wout[i], g_w2h, g_w2l, i); return; }
    i -= S2;
    if (i < S3) { split_store(Wl1[i], g_w3h, g_w3l, i); return; }
    i -= S3;
    if (i < S4) { split_store(Wl2[i], g_w4h, g_w4l, i); return; }
    i -= S4;
    if (i < S5) {
        int r = (int)(i / 512); int c = (int)(i % 512);
        float v = (c < 256) ? Wq[(size_t)(NLAY - 1) * 65536 + r * 256 + c]
                            : Wk[(size_t)(NLAY - 1) * 65536 + r * 256 + (c - 256)];
        split_store(v, g_w5h, g_w5l, i); return;
    }
    i -= S5;
    if (i < SB1) {
        int l = (int)(i / 384); int c = (int)(i % 384);
        g_b1[i] = (c < 256) ? boff[l * 256 + c] : ba[l * 128 + (c - 256)];
        return;
    }
    i -= SB1;
    if (i >= 0 && i < SB5) {
        g_b5[i] = (i < 256) ? bqv[(NLAY - 1) * 256 + i] : bkv[(NLAY - 1) * 256 + (i - 256)];
    }
}

// ---------------- bf16-split tensor-core GEMM (preconverted B, prefetch) ----------------
// C(MxN) = (A [+A2])(MxK) @ B(KxN as hi/lo bf16, ldb) + bias, opt ReLU.
// Block tile 64x64, BK=32, 256 threads = 8 warps (2 M x 4 N). N%64==0, K%32==0.
__device__ __forceinline__ void mma_bf16(float* c, const unsigned* a, const unsigned* b) {
    asm volatile(
        "mma.sync.aligned.m16n8k16.row.col.f32.bf16.bf16.f32 "
        "{%0,%1,%2,%3}, {%4,%5,%6,%7}, {%8,%9}, {%0,%1,%2,%3};"
        : "+f"(c[0]), "+f"(c[1]), "+f"(c[2]), "+f"(c[3])
        : "r"(a[0]), "r"(a[1]), "r"(a[2]), "r"(a[3]), "r"(b[0]), "r"(b[1]));
}

template <bool RELU, bool ADD2>
__global__ void __launch_bounds__(256) mma_gemm2_kernel(
        const float* __restrict__ A, const float* __restrict__ A2,
        const __nv_bfloat16* __restrict__ Bh, const __nv_bfloat16* __restrict__ Bl,
        const float* __restrict__ bias, float* __restrict__ C,
        int M, int N, int K, int ldb, int ldc) {
    __shared__ unsigned sAh[64][20], sAl[64][20];
    __shared__ unsigned sBh[16][72], sBl[16][72];

    const int tid = threadIdx.x;
    const int w = tid >> 5, lane = tid & 31;
    const int gid = lane >> 2, tig = lane & 3;
    const int wm = w >> 2, wn = w & 3;
    const int bm = blockIdx.x, bn = blockIdx.y;

    // A-load mapping: 4 rows (tid>>4 + 16i), k-pair = tid&15
    const int arowl = tid >> 4;
    const int akp = tid & 15;
    // B-load mapping: 4 cols (tid&15)*4, k-pair = tid>>4
    const int bn4 = (tid & 15) * 4;
    const int bkp = tid >> 4;
    const __nv_bfloat16* BhP = Bh + (size_t)bn * 64 + bn4;
    const __nv_bfloat16* BlP = Bl + (size_t)bn * 64 + bn4;

    float acc[2][2][4];
    #pragma unroll
    for (int i = 0; i < 2; i++)
        #pragma unroll
        for (int j = 0; j < 2; j++)
            #pragma unroll
            for (int r = 0; r < 4; r++) acc[i][j][r] = 0.f;

    float2 ra[4];
    unsigned long long rbh0, rbh1, rbl0, rbl1;

    auto loadTile = [&](int kb) {
        #pragma unroll
        for (int i = 0; i < 4; i++) {
            int grow = bm * 64 + arowl + 16 * i;
            float2 v = make_float2(0.f, 0.f);
            if (grow < M) {
                v = *(const float2*)(A + (size_t)grow * K + kb + 2 * akp);
                if (ADD2) {
                    float2 v2 = *(const float2*)(A2 + (size_t)grow * K + kb + 2 * akp);
                    v.x += v2.x; v.y += v2.y;
                }
            }
            ra[i] = v;
        }
        size_t bo = (size_t)(kb + 2 * bkp) * ldb;
        rbh0 = *(const unsigned long long*)(BhP + bo);
        rbh1 = *(const unsigned long long*)(BhP + bo + ldb);
        rbl0 = *(const unsigned long long*)(BlP + bo);
        rbl1 = *(const unsigned long long*)(BlP + bo + ldb);
    };
    auto storeTile = [&]() {
        #pragma unroll
        for (int i = 0; i < 4; i++) {
            int row = arowl + 16 * i;
            __nv_bfloat16 hx = __float2bfloat16_rn(ra[i].x);
            __nv_bfloat16 hy = __float2bfloat16_rn(ra[i].y);
            __nv_bfloat16 lx = __float2bfloat16_rn(ra[i].x - __bfloat162float(hx));
            __nv_bfloat16 ly = __float2bfloat16_rn(ra[i].y - __bfloat162float(hy));
            sAh[row][akp] = pack_bf2(hx, hy);
            sAl[row][akp] = pack_bf2(lx, ly);
        }
        unsigned x0 = (unsigned)rbh0, x1 = (unsigned)(rbh0 >> 32);
        unsigned y0 = (unsigned)rbh1, y1 = (unsigned)(rbh1 >> 32);
        uint4 ph;
        ph.x = __byte_perm(x0, y0, 0x5410); ph.y = __byte_perm(x0, y0, 0x7632);
        ph.z = __byte_perm(x1, y1, 0x5410); ph.w = __byte_perm(x1, y1, 0x7632);
        *(uint4*)&sBh[bkp][bn4] = ph;
        x0 = (unsigned)rbl0; x1 = (unsigned)(rbl0 >> 32);
        y0 = (unsigned)rbl1; y1 = (unsigned)(rbl1 >> 32);
        uint4 pl;
        pl.x = __byte_perm(x0, y0, 0x5410); pl.y = __byte_perm(x0, y0, 0x7632);
        pl.z = __byte_perm(x1, y1, 0x5410); pl.w = __byte_perm(x1, y1, 0x7632);
        *(uint4*)&sBl[bkp][bn4] = pl;
    };

    loadTile(0);
    for (int kb = 0; kb < K; kb += 32) {
        storeTile();
        __syncthreads();
        if (kb + 32 < K) loadTile(kb + 32);   // prefetch overlaps MMA below
        #pragma unroll
        for (int ks = 0; ks < 2; ks++) {
            const int kp0 = ks * 8;
            unsigned ah[2][4], al[2][4];
            #pragma unroll
            for (int mt = 0; mt < 2; mt++) {
                int r0 = wm * 32 + mt * 16;
                ah[mt][0] = sAh[r0 + gid    ][kp0 + tig];
                ah[mt][1] = sAh[r0 + gid + 8][kp0 + tig];
                ah[mt][2] = sAh[r0 + gid    ][kp0 + tig + 4];
                ah[mt][3] = sAh[r0 + gid + 8][kp0 + tig + 4];
                al[mt][0] = sAl[r0 + gid    ][kp0 + tig];
                al[mt][1] = sAl[r0 + gid + 8][kp0 + tig];
                al[mt][2] = sAl[r0 + gid    ][kp0 + tig + 4];
                al[mt][3] = sAl[r0 + gid + 8][kp0 + tig + 4];
            }
            unsigned bh[2][2], bl[2][2];
            #pragma unroll
            for (int nt = 0; nt < 2; nt++) {
                int c0 = wn * 16 + nt * 8 + gid;
                bh[nt][0] = sBh[kp0 + tig    ][c0];
                bh[nt][1] = sBh[kp0 + tig + 4][c0];
                bl[nt][0] = sBl[kp0 + tig    ][c0];
                bl[nt][1] = sBl[kp0 + tig + 4][c0];
            }
            #pragma unroll
            for (int mt = 0; mt < 2; mt++)
                #pragma unroll
                for (int nt = 0; nt < 2; nt++) {
                    mma_bf16(acc[mt][nt], ah[mt], bh[nt]);
                    mma_bf16(acc[mt][nt], ah[mt], bl[nt]);
                    mma_bf16(acc[mt][nt], al[mt], bh[nt]);
                }
        }
        __syncthreads();
    }

    #pragma unroll
    for (int mt = 0; mt < 2; mt++) {
        #pragma unroll
        for (int nt = 0; nt < 2; nt++) {
            int col = bn * 64 + wn * 16 + nt * 8 + tig * 2;
            float b0 = bias[col], b1 = bias[col + 1];
            int row0 = bm * 64 + wm * 32 + mt * 16 + gid;
            if (row0 < M) {
                float o0 = acc[mt][nt][0] + b0, o1 = acc[mt][nt][1] + b1;
                if (RELU) { o0 = fmaxf(o0, 0.f); o1 = fmaxf(o1, 0.f); }
                *(float2*)(C + (size_t)row0 * ldc + col) = make_float2(o0, o1);
            }
            int row1 = row0 + 8;
            if (row1 < M) {
                float o2 = acc[mt][nt][2] + b0, o3 = acc[mt][nt][3] + b1;
                if (RELU) { o2 = fmaxf(o2, 0.f); o3 = fmaxf(o3, 0.f); }
                *(float2*)(C + (size_t)row1 * ldc + col) = make_float2(o2, o3);
            }
        }
    }
}

// ---------------- misc kernels ----------------
__global__ void posemb_kernel(const float* __restrict__ refp, float* __restrict__ out) {
    int idx = blockIdx.x * blockDim.x + threadIdx.x;
    if (idx >= BB * NP * DIM) return;
    int d = idx & 255;
    int q = (idx >> 8) % NP;
    int b = idx / (256 * NP);
    int c = d >> 6;
    int r = d & 63;
    int j = r >> 1;
    float pos = refp[(b * NQT + q) * 4 + c];
    float t = powf(10000.0f, (float)j / 32.0f);
    float arg = pos * 6.2831853071795864f / t;
    out[idx] = (r & 1) ? cosf(arg) : sinf(arg);
}

__global__ void copy_rows_kernel(const float* __restrict__ src, float* __restrict__ dst,
                                 int rowoff, int nrows) {
    int idx = blockIdx.x * blockDim.x + threadIdx.x;
    int total = BB * nrows * DIM;
    if (idx >= total) return;
    int d = idx & 255;
    int r = (idx >> 8) % nrows;
    int b = idx / (256 * nrows);
    dst[idx] = src[((size_t)(b * NQT + rowoff + r)) * DIM + d];
}

// Aggregating gather with fused softmax: block=(b,q), warp=head.
__global__ void gather2_kernel(const float* __restrict__ refp, const float* __restrict__ src) {
    int bq = blockIdx.x;
    int b = bq / NP, q = bq % NP;
    int h = threadIdx.x >> 5;
    int lane = threadIdx.x & 31;
    const float* r = refp + (size_t)(b * NQT + q) * 4;
    float rx = r[0], ry = r[1], rw = r[2], rh = r[3];
    const float* offp = g_off + (size_t)bq * OA;

    const float* lg = g_off + (size_t)bq * OA + 256 + h * 16;
    float logit[16];
    float mx = -1e30f;
    #pragma unroll
    for (int j = 0; j < 16; j++) { logit[j] = __ldg(lg + j); mx = fmaxf(mx, logit[j]); }
    float ssum = 0.f;
    #pragma unroll
    for (int j = 0; j < 16; j++) { logit[j] = expf(logit[j] - mx); ssum += logit[j]; }
    float sinv = 1.0f / ssum;

    float4 a0 = make_float4(0.f, 0.f, 0.f, 0.f);
    float4 a1 = make_float4(0.f, 0.f, 0.f, 0.f);
    float csum = 0.f;

    #pragma unroll
    for (int l = 0; l < 4; l++) {
        int wl = c_wl[l], hl = c_hl[l], st = c_start[l];
        float wlf = (float)wl, hlf = (float)hl;
        const float4* base = (const float4*)(src + ((size_t)b * STOT + st) * DIM);
        #pragma unroll
        for (int p = 0; p < 4; p++) {
            int oi = ((h * 4 + l) * 4 + p) * 2;
            float ox = offp[oi], oy = offp[oi + 1];
            float a = logit[l * 4 + p] * sinv;
            float x = (rx + ox * 0.125f * rw) * wlf - 0.5f;
            float y = (ry + oy * 0.125f * rh) * hlf - 0.5f;
            float x0 = floorf(x), y0 = floorf(y);
            float lx = x - x0, ly = y - y0;
            float wgt[4] = { (1.f - lx) * (1.f - ly), lx * (1.f - ly),
                             (1.f - lx) * ly,         lx * ly };
            float xs[4] = { x0, x0 + 1.f, x0, x0 + 1.f };
            float ys[4] = { y0, y0, y0 + 1.f, y0 + 1.f };
            #pragma unroll
            for (int c = 0; c < 4; c++) {
                float xi = xs[c], yi = ys[c];
                if (xi >= 0.f && xi <= wlf - 1.f && yi >= 0.f && yi <= hlf - 1.f) {
                    int xii = (int)xi, yii = (int)yi;
                    float coef = a * wgt[c];
                    const float4* rp = base + (size_t)(yii * wl + xii) * 64;
                    float4 v0 = rp[lane];
                    float4 v1 = rp[lane + 32];
                    a0.x += coef * v0.x; a0.y += coef * v0.y;
                    a0.z += coef * v0.z; a0.w += coef * v0.w;
                    a1.x += coef * v1.x; a1.y += coef * v1.y;
                    a1.z += coef * v1.z; a1.w += coef * v1.w;
                    csum += coef;
                }
            }
        }
    }
    float4* ag = (float4*)(g_agg + ((size_t)bq * HH + h) * DIM);
    ag[lane] = a0;
    ag[lane + 32] = a1;
    if (lane == 0) g_coef[bq * HH + h] = csum;
}

// Per-head projection: capre[bq][h*32+j] = agg[bq][h] . Wv[:, h*32+j] + coef*bv
__global__ void hproj_kernel(const float* __restrict__ Wv, const float* __restrict__ bv) {
    __shared__ float As[16][65];
    __shared__ float Bs[16][32];
    const int h = blockIdx.y;
    const int bm = blockIdx.x;
    const int tid = threadIdx.x;
    const int tx = tid & 7, ty = tid >> 3;
    float acc[2][4] = {};

    const int ar = tid >> 2, ac = (tid & 3) * 4;
    const int kr = tid >> 4, bc = (tid & 15) * 2;
    const int arow = bm * 64 + ar;

    for (int k0 = 0; k0 < DIM; k0 += 16) {
        float4 av = make_float4(0.f, 0.f, 0.f, 0.f);
        if (arow < BB * NP)
            av = *(const float4*)(g_agg + ((size_t)arow * HH + h) * DIM + k0 + ac);
        As[ac + 0][ar] = av.x; As[ac + 1][ar] = av.y;
        As[ac + 2][ar] = av.z; As[ac + 3][ar] = av.w;
        float2 bvv = *(const float2*)(Wv + (size_t)(k0 + kr) * DIM + h * 32 + bc);
        Bs[kr][bc] = bvv.x; Bs[kr][bc + 1] = bvv.y;
        __syncthreads();
        #pragma unroll
        for (int k = 0; k < 16; k++) {
            float x0 = As[k][ty * 2 + 0], x1 = As[k][ty * 2 + 1];
            float b0 = Bs[k][tx * 4 + 0], b1 = Bs[k][tx * 4 + 1];
            float b2 = Bs[k][tx * 4 + 2], b3 = Bs[k][tx * 4 + 3];
            acc[0][0] += x0 * b0; acc[0][1] += x0 * b1; acc[0][2] += x0 * b2; acc[0][3] += x0 * b3;
            acc[1][0] += x1 * b0; acc[1][1] += x1 * b1; acc[1][2] += x1 * b2; acc[1][3] += x1 * b3;
        }
        __syncthreads();
    }
    #pragma unroll
    for (int i = 0; i < 2; i++) {
        int row = bm * 64 + ty * 2 + i;
        if (row < BB * NP) {
            float cf = g_coef[row * HH + h];
            #pragma unroll
            for (int j = 0; j < 4; j++) {
                int col = h * 32 + tx * 4 + j;
                g_capre[(size_t)row * DIM + col] = acc[i][j] + cf * bv[col];
            }
        }
    }
}

// fused residual + layernorm (warp per row, in-place on g_prop)
__global__ void ln_kernel(const float* __restrict__ addv, const float* __restrict__ w,
                          const float* __restrict__ bia) {
    int row = blockIdx.x * 8 + (threadIdx.x >> 5);
    int lane = threadIdx.x & 31;
    if (row >= BB * NP) return;
    float x[8];
    float s = 0.f;
    #pragma unroll
    for (int i = 0; i < 8; i++) {
        int d = lane + 32 * i;
        x[i] = g_prop[(size_t)row * DIM + d] + addv[(size_t)row * DIM + d];
        s += x[i];
    }
    #pragma unroll
    for (int o = 16; o > 0; o >>= 1) s += __shfl_xor_sync(0xffffffff, s, o);
    float m = s / 256.0f;
    float v = 0.f;
    #pragma unroll
    for (int i = 0; i < 8; i++) { float dd = x[i] - m; v += dd * dd; }
    #pragma unroll
    for (int o = 16; o > 0; o >>= 1) v += __shfl_xor_sync(0xffffffff, v, o);
    v /= 256.0f;
    float inv = rsqrtf(v + 1e-5f);
    #pragma unroll
    for (int i = 0; i < 8; i++) {
        int d = lane + 32 * i;
        g_prop[(size_t)row * DIM + d] = (x[i] - m) * inv * w[d] + bia[d];
    }
}

// per (row, h2) L2 norm of a 128-dim half-row (row stride ld)
__global__ void norm_kernel(const float* __restrict__ X, int rows, int ld,
                            float* __restrict__ out) {
    int idx = blockIdx.x * blockDim.x + threadIdx.x;
    if (idx >= rows * NH2) return;
    int h = idx & 1, r = idx >> 1;
    const float* x = X + (size_t)r * ld + h * DH2;
    float s = 0.f;
    #pragma unroll 8
    for (int d = 0; d < 128; d++) { float v = x[d]; s += v * v; }
    out[idx] = sqrtf(s);
}

// fused weight_attn: dots + softmax(mm) + cosine.  grid = (NP, 2, B), 128 threads.
__global__ void wattn_kernel(const float* __restrict__ Q, const float* __restrict__ K,
                             const float* __restrict__ qn, const float* __restrict__ kn,
                             int nk, int ldq, int ldk,
                             float* __restrict__ cos_out, float* __restrict__ mm_out) {
    int qi = blockIdx.x, h = blockIdx.y, b = blockIdx.z;
    __shared__ float qv[128];
    __shared__ float sc[304];
    __shared__ float red[128];
    int t = threadIdx.x;
    int qrow = b * NP + qi;
    qv[t] = Q[(size_t)qrow * ldq + h * DH2 + t];
    __syncthreads();
    for (int k = t; k < nk; k += 128) {
        const float* kr = K + ((size_t)(b * nk + k)) * ldk + h * DH2;
        float dot = 0.f;
        #pragma unroll 8
        for (int d = 0; d < 128; d++) dot += qv[d] * kr[d];
        sc[k] = dot;
    }
    __syncthreads();
    const float scale = 0.088388347648318447f;   // 1/sqrt(128)
    float mx = -1e30f;
    for (int k = t; k < nk; k += 128) mx = fmaxf(mx, sc[k] * scale);
    red[t] = mx; __syncthreads();
    for (int s = 64; s > 0; s >>= 1) { if (t < s) red[t] = fmaxf(red[t], red[t + s]); __syncthreads(); }
    mx = red[0]; __syncthreads();
    float sum = 0.f;
    for (int k = t; k < nk; k += 128) sum += expf(sc[k] * scale - mx);
    red[t] = sum; __syncthreads();
    for (int s = 64; s > 0; s >>= 1) { if (t < s) red[t] += red[t + s]; __syncthreads(); }
    sum = red[0];
    float inv = 1.0f / sum;
    float qnv = qn[qrow * NH2 + h] + 1e-6f;
    size_t base = ((size_t)(b * NH2 + h) * NP + qi) * nk;
    for (int k = t; k < nk; k += 128) {
        mm_out[base + k] = expf(sc[k] * scale - mx) * inv;
        float knv = kn[(b * nk + k) * NH2 + h] + 1e-6f;
        cos_out[base + k] = sc[k] / (qnv * knv);
    }
}

__global__ void copy_prop_out(float* __restrict__ out) {
    int idx = blockIdx.x * blockDim.x + threadIdx.x;
    if (idx < BB * NP * DIM) out[OUT_PROP + idx] = g_prop[idx];
}
__global__ void copy_pref_out(const float* __restrict__ refp, float* __restrict__ out) {
    int idx = blockIdx.x * blockDim.x + threadIdx.x;
    if (idx >= BB * NP * 4) return;
    int c = idx & 3;
    int q = (idx >> 2) % NP;
    int b = idx / (4 * NP);
    out[OUT_PREF + idx] = refp[((size_t)(b * NQT + q)) * 4 + c];
}

// ---------------- host orchestration ----------------
static inline int cdiv(int a, int b) { return (a + b - 1) / b; }

extern "C" void kernel_launch(void* const* d_in, const int* in_sizes, int n_in,
                              void* d_out, int out_size) {
    const float* tgt   = (const float*)d_in[0];
    const float* refp  = (const float*)d_in[1];
    const float* src   = (const float*)d_in[2];
    const float* Woff  = (const float*)d_in[7];
    const float* boff  = (const float*)d_in[8];
    const float* Wa    = (const float*)d_in[9];
    const float* ba    = (const float*)d_in[10];
    const float* Wv    = (const float*)d_in[11];
    const float* bv    = (const float*)d_in[12];
    const float* Wout  = (const float*)d_in[13];
    const float* bout  = (const float*)d_in[14];
    const float* Wl1   = (const float*)d_in[15];
    const float* bl1   = (const float*)d_in[16];
    const float* Wl2   = (const float*)d_in[17];
    const float* bl2   = (const float*)d_in[18];
    const float* Wq    = (const float*)d_in[19];
    const float* bq    = (const float*)d_in[20];
    const float* Wk    = (const float*)d_in[21];
    const float* bk    = (const float*)d_in[22];
    const float* n1w   = (const float*)d_in[23];
    const float* n1b   = (const float*)d_in[24];
    const float* n3w   = (const float*)d_in[25];
    const float* n3b   = (const float*)d_in[26];
    float* out = (float*)d_out;

    float *pprop, *pppos, *poff, *pca, *pffn, *ptrack, *pqk, *pkt;
    float *pqn, *pkpn, *pktn, *pcapre, *pb1, *pb5;
    __nv_bfloat16 *w1h, *w1l, *w2h, *w2l, *w3h, *w3l, *w4h, *w4l, *w5h, *w5l;
    cudaGetSymbolAddress((void**)&pprop,  g_prop);
    cudaGetSymbolAddress((void**)&pppos,  g_ppos);
    cudaGetSymbolAddress((void**)&poff,   g_off);
    cudaGetSymbolAddress((void**)&pcapre, g_capre);
    cudaGetSymbolAddress((void**)&pca,    g_ca);
    cudaGetSymbolAddress((void**)&pffn,   g_ffn);
    cudaGetSymbolAddress((void**)&ptrack, g_track);
    cudaGetSymbolAddress((void**)&pqk,    g_qk);
    cudaGetSymbolAddress((void**)&pkt,    g_kt);
    cudaGetSymbolAddress((void**)&pqn,    g_qn);
    cudaGetSymbolAddress((void**)&pkpn,   g_kpn);
    cudaGetSymbolAddress((void**)&pktn,   g_ktn);
    cudaGetSymbolAddress((void**)&pb1,    g_b1);
    cudaGetSymbolAddress((void**)&pb5,    g_b5);
    cudaGetSymbolAddress((void**)&w1h,    g_w1h);
    cudaGetSymbolAddress((void**)&w1l,    g_w1l);
    cudaGetSymbolAddress((void**)&w2h,    g_w2h);
    cudaGetSymbolAddress((void**)&w2l,    g_w2l);
    cudaGetSymbolAddress((void**)&w3h,    g_w3h);
    cudaGetSymbolAddress((void**)&w3l,    g_w3l);
    cudaGetSymbolAddress((void**)&w4h,    g_w4h);
    cudaGetSymbolAddress((void**)&w4l,    g_w4l);
    cudaGetSymbolAddress((void**)&w5h,    g_w5h);
    cudaGetSymbolAddress((void**)&w5l,    g_w5l);

    const int NPROPS = BB * NP;        // 2400
    const int NEL = NPROPS * DIM;

    auto gemm = [&](const float* A, const __nv_bfloat16* Bh, const __nv_bfloat16* Bl,
                    const float* bias, float* C, int M, int N, int K, int ldb, int ldc,
                    bool relu) {
        dim3 g(cdiv(M, 64), N / 64);
        if (relu) mma_gemm2_kernel<true, false><<<g, 256>>>(A, nullptr, Bh, Bl, bias, C, M, N, K, ldb, ldc);
        else      mma_gemm2_kernel<false, false><<<g, 256>>>(A, nullptr, Bh, Bl, bias, C, M, N, K, ldb, ldc);
    };
    auto gemm_add = [&](const float* A, const float* A2, const __nv_bfloat16* Bh,
                        const __nv_bfloat16* Bl, const float* bias, float* C,
                        int M, int N, int K, int ldb, int ldc) {
        dim3 g(cdiv(M, 64), N / 64);
        mma_gemm2_kernel<false, true><<<g, 256>>>(A, A2, Bh, Bl, bias, C, M, N, K, ldb, ldc);
    };

    // one-shot weight split/pack
    const long TOTC = (long)S1 + S2 + S3 + S4 + S5 + SB1 + SB5;
    convert_all<<<(unsigned)cdiv((int)TOTC, 256), 256>>>(Woff, Wa, Wout, Wl1, Wl2,
                                                         Wq, Wk, boff, ba, bq, bk);

    copy_rows_kernel<<<cdiv(NEL, 256), 256>>>(tgt, pprop, 0, NP);
    copy_rows_kernel<<<cdiv(BB * NT * DIM, 256), 256>>>(tgt, ptrack, NP, NT);
    posemb_kernel<<<cdiv(NEL, 256), 256>>>(refp, pppos);

    for (int l = 0; l < NLAY; l++) {
        // packed offsets+logits from q = prop + pos
        gemm_add(pprop, pppos, w1h + (size_t)l * 98304, w1l + (size_t)l * 98304,
                 pb1 + l * 384, poff, NPROPS, 384, DIM, 384, OA);
        // aggregate src rows with combined softmax*bilinear coefficients
        gather2_kernel<<<BB * NP, 256>>>(refp, src);
        // per-head projection through Wv (+ coef-weighted bias)
        dim3 hg(cdiv(NPROPS, 64), HH);
        hproj_kernel<<<hg, 256>>>(Wv + (size_t)l * DIM * DIM, bv + l * DIM);
        // output projection
        gemm(pcapre, w2h + (size_t)l * 65536, w2l + (size_t)l * 65536,
             bout + l * 256, pca, NPROPS, 256, 256, 256, 256, false);
        ln_kernel<<<cdiv(NPROPS, 8), 256>>>(pca, n1w + l * DIM, n1b + l * DIM);
        // FFN
        gemm(pprop, w3h + (size_t)l * 262144, w3l + (size_t)l * 262144,
             bl1 + l * DFF, pffn, NPROPS, DFF, 256, DFF, DFF, true);
        gemm(pffn, w4h + (size_t)l * 262144, w4l + (size_t)l * 262144,
             bl2 + l * 256, pca, NPROPS, 256, DFF, 256, 256, false);
        ln_kernel<<<cdiv(NPROPS, 8), 256>>>(pca, n3w + l * DIM, n3b + l * DIM);
    }

    // weight_attn (only last layer's weights matter)
    const int L = NLAY - 1;
    gemm(pprop, w5h, w5l, pb5, pqk, NPROPS, 512, 256, 512, 512, false);
    gemm(ptrack, w5h + 256, w5l + 256, bk + L * 256, pkt, BB * NT, 256, 256, 512, 256, false);
    norm_kernel<<<cdiv(NPROPS * NH2, 256), 256>>>(pqk, NPROPS, 512, pqn);
    norm_kernel<<<cdiv(NPROPS * NH2, 256), 256>>>(pqk + 256, NPROPS, 512, pkpn);
    norm_kernel<<<cdiv(BB * NT * NH2, 256), 256>>>(pkt, BB * NT, 256, pktn);

    dim3 wg(NP, NH2, BB);
    wattn_kernel<<<wg, 128>>>(pqk, pkt, pqn, pktn, NT, 512, 256,
                              out + OUT_PTCOS, out + OUT_PTMM);
    wattn_kernel<<<wg, 128>>>(pqk, pqk + 256, pqn, pkpn, NP, 512, 512,
                              out + OUT_PPCOS, out + OUT_PPMM);

    copy_prop_out<<<cdiv(NEL, 256), 256>>>(out);
    copy_pref_out<<<cdiv(BB * NP * 4, 256), 256>>>(refp, out);
}

// round 11
// speedup vs baseline: 2.6911x; 1.5752x over previous
#include <cuda_runtime.h>
#include <cuda_bf16.h>
#include <math.h>

// ---------------- problem constants ----------------
#define BB     8
#define NQT    350
#define NP     300
#define NT     50
#define DIM    256
#define HH     8
#define DH     32
#define NLAY   6
#define NH2    2
#define DH2    128
#define DFF    1024
#define STOT   20197
#define OA     384          // packed Woff|Wa output row stride
#define QT     16           // wattn q-tile

// output layout (tuple flattened in order)
#define OUT_PROP   0
#define OUT_PREF   614400
#define OUT_PTCOS  624000
#define OUT_PPCOS  864000
#define OUT_PTMM   2304000
#define OUT_PPMM   2544000

__device__ __constant__ int c_hl[4]    = {100, 50, 25, 13};
__device__ __constant__ int c_wl[4]    = {152, 76, 38, 19};
__device__ __constant__ int c_start[4] = {0, 15200, 19000, 19950};

// ---------------- scratch (device globals, no allocation) ----------------
__device__ float g_prop [BB * NP * DIM];
__device__ float g_ppos [BB * NP * DIM];
__device__ float g_off  [BB * NP * OA];     // packed: offsets [0..255], attn logits [256..383]
__device__ float g_agg  [(size_t)BB * NP * HH * DIM];
__device__ float g_coef [BB * NP * HH];
__device__ float g_capre[BB * NP * DIM];
__device__ float g_ca   [BB * NP * DIM];
__device__ float g_ffn  [BB * NP * DFF];
__device__ float g_track[BB * NT * DIM];
__device__ float g_qk   [BB * NP * 512];    // packed q|k projection of proposals
__device__ float g_kt   [BB * NT * DIM];
__device__ float g_qn   [BB * NP * NH2];
__device__ float g_kpn  [BB * NP * NH2];
__device__ float g_ktn  [BB * NT * NH2];

// pre-split bf16 weights (hi/lo)
#define S1 (NLAY * 256 * 384)     // Woff|Wa packed
#define S2 (NLAY * 256 * 256)     // Wout
#define S3 (NLAY * 256 * 1024)    // Wl1
#define S4 (NLAY * 1024 * 256)    // Wl2
#define S5 (256 * 512)            // Wq|Wk (last layer)
#define SB1 (NLAY * 384)
#define SB5 (512)
__device__ __nv_bfloat16 g_w1h[S1], g_w1l[S1];
__device__ __nv_bfloat16 g_w2h[S2], g_w2l[S2];
__device__ __nv_bfloat16 g_w3h[S3], g_w3l[S3];
__device__ __nv_bfloat16 g_w4h[S4], g_w4l[S4];
__device__ __nv_bfloat16 g_w5h[S5], g_w5l[S5];
__device__ float g_b1[SB1];
__device__ float g_b5[SB5];

__device__ __forceinline__ unsigned pack_bf2(__nv_bfloat16 x, __nv_bfloat16 y) {
    __nv_bfloat162 h2; h2.x = x; h2.y = y;
    return *(unsigned*)&h2;
}
__device__ __forceinline__ void split_store(float v, __nv_bfloat16* H, __nv_bfloat16* L, long i) {
    __nv_bfloat16 h = __float2bfloat16_rn(v);
    H[i] = h;
    L[i] = __float2bfloat16_rn(v - __bfloat162float(h));
}

// ---------------- fused setup: prop copy + track copy + posemb ----------------
__global__ void setup_kernel(const float* __restrict__ tgt, const float* __restrict__ refp) {
    int idx = blockIdx.x * blockDim.x + threadIdx.x;
    if (idx < BB * NP * DIM) {
        int d = idx & 255;
        int q = (idx >> 8) % NP;
        int b = idx / (256 * NP);
        g_prop[idx] = tgt[((size_t)(b * NQT + q)) * DIM + d];
        int c = d >> 6;
        int r = d & 63;
        int j = r >> 1;
        float pos = refp[(b * NQT + q) * 4 + c];
        float t = powf(10000.0f, (float)j / 32.0f);
        float arg = pos * 6.2831853071795864f / t;
        g_ppos[idx] = (r & 1) ? cosf(arg) : sinf(arg);
    }
    if (idx < BB * NT * DIM) {
        int d = idx & 255;
        int r = (idx >> 8) % NT;
        int b = idx / (256 * NT);
        g_track[idx] = tgt[((size_t)(b * NQT + NP + r)) * DIM + d];
    }
}

// ---------------- one-shot weight conversion / packing ----------------
__global__ void convert_all(const float* __restrict__ Woff, const float* __restrict__ Wa,
                            const float* __restrict__ Wout, const float* __restrict__ Wl1,
                            const float* __restrict__ Wl2, const float* __restrict__ Wq,
                            const float* __restrict__ Wk, const float* __restrict__ boff,
                            const float* __restrict__ ba, const float* __restrict__ bqv,
                            const float* __restrict__ bkv) {
    long i = (long)blockIdx.x * blockDim.x + threadIdx.x;
    if (i < S1) {
        int l = (int)(i / 98304); int rem = (int)(i % 98304); int r = rem / 384; int c = rem % 384;
        float v = (c < 256) ? Woff[(size_t)l * 65536 + r * 256 + c]
                            : Wa[(size_t)l * 32768 + r * 128 + (c - 256)];
        split_store(v, g_w1h, g_w1l, i); return;
    }
    i -= S1;
    if (i < S2) { split_store(Wout[i], g_w2h, g_w2l, i); return; }
    i -= S2;
    if (i < S3) { split_store(Wl1[i], g_w3h, g_w3l, i); return; }
    i -= S3;
    if (i < S4) { split_store(Wl2[i], g_w4h, g_w4l, i); return; }
    i -= S4;
    if (i < S5) {
        int r = (int)(i / 512); int c = (int)(i % 512);
        float v = (c < 256) ? Wq[(size_t)(NLAY - 1) * 65536 + r * 256 + c]
                            : Wk[(size_t)(NLAY - 1) * 65536 + r * 256 + (c - 256)];
        split_store(v, g_w5h, g_w5l, i); return;
    }
    i -= S5;
    if (i < SB1) {
        int l = (int)(i / 384); int c = (int)(i % 384);
        g_b1[i] = (c < 256) ? boff[l * 256 + c] : ba[l * 128 + (c - 256)];
        return;
    }
    i -= SB1;
    if (i >= 0 && i < SB5) {
        g_b5[i] = (i < 256) ? bqv[(NLAY - 1) * 256 + i] : bkv[(NLAY - 1) * 256 + (i - 256)];
    }
}

// ---------------- bf16-split tensor-core GEMM (double-buffered, 1 sync/iter) ----------------
__device__ __forceinline__ void mma_bf16(float* c, const unsigned* a, const unsigned* b) {
    asm volatile(
        "mma.sync.aligned.m16n8k16.row.col.f32.bf16.bf16.f32 "
        "{%0,%1,%2,%3}, {%4,%5,%6,%7}, {%8,%9}, {%0,%1,%2,%3};"
        : "+f"(c[0]), "+f"(c[1]), "+f"(c[2]), "+f"(c[3])
        : "r"(a[0]), "r"(a[1]), "r"(a[2]), "r"(a[3]), "r"(b[0]), "r"(b[1]));
}

template <bool RELU, bool ADD2>
__global__ void __launch_bounds__(256) mma_gemm2_kernel(
        const float* __restrict__ A, const float* __restrict__ A2,
        const __nv_bfloat16* __restrict__ Bh, const __nv_bfloat16* __restrict__ Bl,
        const float* __restrict__ bias, float* __restrict__ C,
        int M, int N, int K, int ldb, int ldc) {
    __shared__ unsigned sAh[2][64][20], sAl[2][64][20];
    __shared__ unsigned sBh[2][16][72], sBl[2][16][72];

    const int tid = threadIdx.x;
    const int w = tid >> 5, lane = tid & 31;
    const int gid = lane >> 2, tig = lane & 3;
    const int wm = w >> 2, wn = w & 3;
    const int bm = blockIdx.x, bn = blockIdx.y;

    const int arowl = tid >> 4;
    const int akp = tid & 15;
    const int bn4 = (tid & 15) * 4;
    const int bkp = tid >> 4;
    const __nv_bfloat16* BhP = Bh + (size_t)bn * 64 + bn4;
    const __nv_bfloat16* BlP = Bl + (size_t)bn * 64 + bn4;

    float acc[2][2][4];
    #pragma unroll
    for (int i = 0; i < 2; i++)
        #pragma unroll
        for (int j = 0; j < 2; j++)
            #pragma unroll
            for (int r = 0; r < 4; r++) acc[i][j][r] = 0.f;

    float2 ra[4];
    unsigned long long rbh0, rbh1, rbl0, rbl1;

    auto loadTile = [&](int kb) {
        #pragma unroll
        for (int i = 0; i < 4; i++) {
            int grow = bm * 64 + arowl + 16 * i;
            float2 v = make_float2(0.f, 0.f);
            if (grow < M) {
                v = *(const float2*)(A + (size_t)grow * K + kb + 2 * akp);
                if (ADD2) {
                    float2 v2 = *(const float2*)(A2 + (size_t)grow * K + kb + 2 * akp);
                    v.x += v2.x; v.y += v2.y;
                }
            }
            ra[i] = v;
        }
        size_t bo = (size_t)(kb + 2 * bkp) * ldb;
        rbh0 = *(const unsigned long long*)(BhP + bo);
        rbh1 = *(const unsigned long long*)(BhP + bo + ldb);
        rbl0 = *(const unsigned long long*)(BlP + bo);
        rbl1 = *(const unsigned long long*)(BlP + bo + ldb);
    };
    auto storeTile = [&](int buf) {
        #pragma unroll
        for (int i = 0; i < 4; i++) {
            int row = arowl + 16 * i;
            __nv_bfloat16 hx = __float2bfloat16_rn(ra[i].x);
            __nv_bfloat16 hy = __float2bfloat16_rn(ra[i].y);
            __nv_bfloat16 lx = __float2bfloat16_rn(ra[i].x - __bfloat162float(hx));
            __nv_bfloat16 ly = __float2bfloat16_rn(ra[i].y - __bfloat162float(hy));
            sAh[buf][row][akp] = pack_bf2(hx, hy);
            sAl[buf][row][akp] = pack_bf2(lx, ly);
        }
        unsigned x0 = (unsigned)rbh0, x1 = (unsigned)(rbh0 >> 32);
        unsigned y0 = (unsigned)rbh1, y1 = (unsigned)(rbh1 >> 32);
        uint4 ph;
        ph.x = __byte_perm(x0, y0, 0x5410); ph.y = __byte_perm(x0, y0, 0x7632);
        ph.z = __byte_perm(x1, y1, 0x5410); ph.w = __byte_perm(x1, y1, 0x7632);
        *(uint4*)&sBh[buf][bkp][bn4] = ph;
        x0 = (unsigned)rbl0; x1 = (unsigned)(rbl0 >> 32);
        y0 = (unsigned)rbl1; y1 = (unsigned)(rbl1 >> 32);
        uint4 pl;
        pl.x = __byte_perm(x0, y0, 0x5410); pl.y = __byte_perm(x0, y0, 0x7632);
        pl.z = __byte_perm(x1, y1, 0x5410); pl.w = __byte_perm(x1, y1, 0x7632);
        *(uint4*)&sBl[buf][bkp][bn4] = pl;
    };
    auto compute = [&](int buf) {
        #pragma unroll
        for (int ks = 0; ks < 2; ks++) {
            const int kp0 = ks * 8;
            unsigned ah[2][4], al[2][4];
            #pragma unroll
            for (int mt = 0; mt < 2; mt++) {
                int r0 = wm * 32 + mt * 16;
                ah[mt][0] = sAh[buf][r0 + gid    ][kp0 + tig];
                ah[mt][1] = sAh[buf][r0 + gid + 8][kp0 + tig];
                ah[mt][2] = sAh[buf][r0 + gid    ][kp0 + tig + 4];
                ah[mt][3] = sAh[buf][r0 + gid + 8][kp0 + tig + 4];
                al[mt][0] = sAl[buf][r0 + gid    ][kp0 + tig];
                al[mt][1] = sAl[buf][r0 + gid + 8][kp0 + tig];
                al[mt][2] = sAl[buf][r0 + gid    ][kp0 + tig + 4];
                al[mt][3] = sAl[buf][r0 + gid + 8][kp0 + tig + 4];
            }
            unsigned bh[2][2], bl[2][2];
            #pragma unroll
            for (int nt = 0; nt < 2; nt++) {
                int c0 = wn * 16 + nt * 8 + gid;
                bh[nt][0] = sBh[buf][kp0 + tig    ][c0];
                bh[nt][1] = sBh[buf][kp0 + tig + 4][c0];
                bl[nt][0] = sBl[buf][kp0 + tig    ][c0];
                bl[nt][1] = sBl[buf][kp0 + tig + 4][c0];
            }
            #pragma unroll
            for (int mt = 0; mt < 2; mt++)
                #pragma unroll
                for (int nt = 0; nt < 2; nt++) {
                    mma_bf16(acc[mt][nt], ah[mt], bh[nt]);
                    mma_bf16(acc[mt][nt], ah[mt], bl[nt]);
                    mma_bf16(acc[mt][nt], al[mt], bh[nt]);
                }
        }
    };

    loadTile(0);
    storeTile(0);
    __syncthreads();
    int cur = 0;
    for (int kb = 0; kb < K; kb += 32) {
        bool nxt = (kb + 32 < K);
        if (nxt) loadTile(kb + 32);
        compute(cur);
        if (nxt) storeTile(cur ^ 1);
        __syncthreads();
        cur ^= 1;
    }

    #pragma unroll
    for (int mt = 0; mt < 2; mt++) {
        #pragma unroll
        for (int nt = 0; nt < 2; nt++) {
            int col = bn * 64 + wn * 16 + nt * 8 + tig * 2;
            float b0 = bias[col], b1 = bias[col + 1];
            int row0 = bm * 64 + wm * 32 + mt * 16 + gid;
            if (row0 < M) {
                float o0 = acc[mt][nt][0] + b0, o1 = acc[mt][nt][1] + b1;
                if (RELU) { o0 = fmaxf(o0, 0.f); o1 = fmaxf(o1, 0.f); }
                *(float2*)(C + (size_t)row0 * ldc + col) = make_float2(o0, o1);
            }
            int row1 = row0 + 8;
            if (row1 < M) {
                float o2 = acc[mt][nt][2] + b0, o3 = acc[mt][nt][3] + b1;
                if (RELU) { o2 = fmaxf(o2, 0.f); o3 = fmaxf(o3, 0.f); }
                *(float2*)(C + (size_t)row1 * ldc + col) = make_float2(o2, o3);
            }
        }
    }
}

// Aggregating gather with fused softmax: block=(b,q), warp=head.
__global__ void gather2_kernel(const float* __restrict__ refp, const float* __restrict__ src) {
    int bq = blockIdx.x;
    int b = bq / NP, q = bq % NP;
    int h = threadIdx.x >> 5;
    int lane = threadIdx.x & 31;
    const float* r = refp + (size_t)(b * NQT + q) * 4;
    float rx = r[0], ry = r[1], rw = r[2], rh = r[3];
    const float* offp = g_off + (size_t)bq * OA;

    const float* lg = g_off + (size_t)bq * OA + 256 + h * 16;
    float logit[16];
    float mx = -1e30f;
    #pragma unroll
    for (int j = 0; j < 16; j++) { logit[j] = __ldg(lg + j); mx = fmaxf(mx, logit[j]); }
    float ssum = 0.f;
    #pragma unroll
    for (int j = 0; j < 16; j++) { logit[j] = expf(logit[j] - mx); ssum += logit[j]; }
    float sinv = 1.0f / ssum;

    float4 a0 = make_float4(0.f, 0.f, 0.f, 0.f);
    float4 a1 = make_float4(0.f, 0.f, 0.f, 0.f);
    float csum = 0.f;

    #pragma unroll
    for (int l = 0; l < 4; l++) {
        int wl = c_wl[l], hl = c_hl[l], st = c_start[l];
        float wlf = (float)wl, hlf = (float)hl;
        const float4* base = (const float4*)(src + ((size_t)b * STOT + st) * DIM);
        #pragma unroll
        for (int p = 0; p < 4; p++) {
            int oi = ((h * 4 + l) * 4 + p) * 2;
            float ox = offp[oi], oy = offp[oi + 1];
            float a = logit[l * 4 + p] * sinv;
            float x = (rx + ox * 0.125f * rw) * wlf - 0.5f;
            float y = (ry + oy * 0.125f * rh) * hlf - 0.5f;
            float x0 = floorf(x), y0 = floorf(y);
            float lx = x - x0, ly = y - y0;
            float wgt[4] = { (1.f - lx) * (1.f - ly), lx * (1.f - ly),
                             (1.f - lx) * ly,         lx * ly };
            float xs[4] = { x0, x0 + 1.f, x0, x0 + 1.f };
            float ys[4] = { y0, y0, y0 + 1.f, y0 + 1.f };
            #pragma unroll
            for (int c = 0; c < 4; c++) {
                float xi = xs[c], yi = ys[c];
                if (xi >= 0.f && xi <= wlf - 1.f && yi >= 0.f && yi <= hlf - 1.f) {
                    int xii = (int)xi, yii = (int)yi;
                    float coef = a * wgt[c];
                    const float4* rp = base + (size_t)(yii * wl + xii) * 64;
                    float4 v0 = rp[lane];
                    float4 v1 = rp[lane + 32];
                    a0.x += coef * v0.x; a0.y += coef * v0.y;
                    a0.z += coef * v0.z; a0.w += coef * v0.w;
                    a1.x += coef * v1.x; a1.y += coef * v1.y;
                    a1.z += coef * v1.z; a1.w += coef * v1.w;
                    csum += coef;
                }
            }
        }
    }
    float4* ag = (float4*)(g_agg + ((size_t)bq * HH + h) * DIM);
    ag[lane] = a0;
    ag[lane + 32] = a1;
    if (lane == 0) g_coef[bq * HH + h] = csum;
}

// Per-head projection: capre[bq][h*32+j] = agg[bq][h] . Wv[:, h*32+j] + coef*bv
__global__ void hproj_kernel(const float* __restrict__ Wv, const float* __restrict__ bv) {
    __shared__ float As[16][65];
    __shared__ float Bs[16][32];
    const int h = blockIdx.y;
    const int bm = blockIdx.x;
    const int tid = threadIdx.x;
    const int tx = tid & 7, ty = tid >> 3;
    float acc[2][4] = {};

    const int ar = tid >> 2, ac = (tid & 3) * 4;
    const int kr = tid >> 4, bc = (tid & 15) * 2;
    const int arow = bm * 64 + ar;

    for (int k0 = 0; k0 < DIM; k0 += 16) {
        float4 av = make_float4(0.f, 0.f, 0.f, 0.f);
        if (arow < BB * NP)
            av = *(const float4*)(g_agg + ((size_t)arow * HH + h) * DIM + k0 + ac);
        As[ac + 0][ar] = av.x; As[ac + 1][ar] = av.y;
        As[ac + 2][ar] = av.z; As[ac + 3][ar] = av.w;
        float2 bvv = *(const float2*)(Wv + (size_t)(k0 + kr) * DIM + h * 32 + bc);
        Bs[kr][bc] = bvv.x; Bs[kr][bc + 1] = bvv.y;
        __syncthreads();
        #pragma unroll
        for (int k = 0; k < 16; k++) {
            float x0 = As[k][ty * 2 + 0], x1 = As[k][ty * 2 + 1];
            float b0 = Bs[k][tx * 4 + 0], b1 = Bs[k][tx * 4 + 1];
            float b2 = Bs[k][tx * 4 + 2], b3 = Bs[k][tx * 4 + 3];
            acc[0][0] += x0 * b0; acc[0][1] += x0 * b1; acc[0][2] += x0 * b2; acc[0][3] += x0 * b3;
            acc[1][0] += x1 * b0; acc[1][1] += x1 * b1; acc[1][2] += x1 * b2; acc[1][3] += x1 * b3;
        }
        __syncthreads();
    }
    #pragma unroll
    for (int i = 0; i < 2; i++) {
        int row = bm * 64 + ty * 2 + i;
        if (row < BB * NP) {
            float cf = g_coef[row * HH + h];
            #pragma unroll
            for (int j = 0; j < 4; j++) {
                int col = h * 32 + tx * 4 + j;
                g_capre[(size_t)row * DIM + col] = acc[i][j] + cf * bv[col];
            }
        }
    }
}

// fused residual + layernorm (warp per row, in-place on g_prop, optional mirror to out)
__global__ void ln_kernel(const float* __restrict__ addv, const float* __restrict__ w,
                          const float* __restrict__ bia, float* __restrict__ outw) {
    int row = blockIdx.x * 8 + (threadIdx.x >> 5);
    int lane = threadIdx.x & 31;
    if (row >= BB * NP) return;
    float x[8];
    float s = 0.f;
    #pragma unroll
    for (int i = 0; i < 8; i++) {
        int d = lane + 32 * i;
        x[i] = g_prop[(size_t)row * DIM + d] + addv[(size_t)row * DIM + d];
        s += x[i];
    }
    #pragma unroll
    for (int o = 16; o > 0; o >>= 1) s += __shfl_xor_sync(0xffffffff, s, o);
    float m = s / 256.0f;
    float v = 0.f;
    #pragma unroll
    for (int i = 0; i < 8; i++) { float dd = x[i] - m; v += dd * dd; }
    #pragma unroll
    for (int o = 16; o > 0; o >>= 1) v += __shfl_xor_sync(0xffffffff, v, o);
    v /= 256.0f;
    float inv = rsqrtf(v + 1e-5f);
    #pragma unroll
    for (int i = 0; i < 8; i++) {
        int d = lane + 32 * i;
        float val = (x[i] - m) * inv * w[d] + bia[d];
        g_prop[(size_t)row * DIM + d] = val;
        if (outw) outw[(size_t)row * DIM + d] = val;
    }
}

// per (row, h2) L2 norm of a 128-dim half-row (row stride ld)
__global__ void norm_kernel(const float* __restrict__ X, int rows, int ld,
                            float* __restrict__ out) {
    int idx = blockIdx.x * blockDim.x + threadIdx.x;
    if (idx >= rows * NH2) return;
    int h = idx & 1, r = idx >> 1;
    const float* x = X + (size_t)r * ld + h * DH2;
    float s = 0.f;
    #pragma unroll 8
    for (int d = 0; d < 128; d++) { float v = x[d]; s += v * v; }
    out[idx] = sqrtf(s);
}

// Tiled weight_attn: block = (q-tile of 16, h, b); Q-tile + K staged in smem.
__global__ void __launch_bounds__(256) wattn2_kernel(
        const float* __restrict__ Q, const float* __restrict__ K,
        const float* __restrict__ qn, const float* __restrict__ kn,
        int nk, int ldq, int ldk,
        float* __restrict__ cos_out, float* __restrict__ mm_out) {
    int qt = blockIdx.x, h = blockIdx.y, b = blockIdx.z;
    int q0 = qt * QT;
    __shared__ float qv[QT][129];
    __shared__ float kt[32][129];
    __shared__ float sc[QT][304];
    int t = threadIdx.x;

    for (int i = t; i < QT * 128; i += 256) {
        int r = i >> 7, d = i & 127;
        int row = q0 + r;
        qv[r][d] = (row < NP) ? Q[(size_t)(b * NP + row) * ldq + h * DH2 + d] : 0.f;
    }
    __syncthreads();

    for (int kb = 0; kb < nk; kb += 32) {
        for (int i = t; i < 32 * 128; i += 256) {
            int r = i >> 7, d = i & 127;
            int krow = kb + r;
            kt[r][d] = (krow < nk) ? K[(size_t)(b * nk + krow) * ldk + h * DH2 + d] : 0.f;
        }
        __syncthreads();
        #pragma unroll
        for (int p = 0; p < 2; p++) {
            int pid = t + p * 256;
            int qq = pid >> 5, kk = pid & 31;
            float dot = 0.f;
            #pragma unroll 16
            for (int d = 0; d < 128; d++) dot += qv[qq][d] * kt[kk][d];
            if (kb + kk < nk) sc[qq][kb + kk] = dot;
        }
        __syncthreads();
    }

    const float scale = 0.088388347648318447f;   // 1/sqrt(128)
    int w = t >> 5, lane = t & 31;
    for (int r = w; r < QT; r += 8) {
        int row = q0 + r;
        if (row >= NP) continue;
        float mx = -1e30f;
        for (int k = lane; k < nk; k += 32) mx = fmaxf(mx, sc[r][k] * scale);
        #pragma unroll
        for (int o = 16; o > 0; o >>= 1) mx = fmaxf(mx, __shfl_xor_sync(0xffffffff, mx, o));
        float sum = 0.f;
        for (int k = lane; k < nk; k += 32) sum += expf(sc[r][k] * scale - mx);
        #pragma unroll
        for (int o = 16; o > 0; o >>= 1) sum += __shfl_xor_sync(0xffffffff, sum, o);
        float inv = 1.0f / sum;
        float qnv = qn[(b * NP + row) * NH2 + h] + 1e-6f;
        size_t base = ((size_t)(b * NH2 + h) * NP + row) * nk;
        for (int k = lane; k < nk; k += 32) {
            mm_out[base + k] = expf(sc[r][k] * scale - mx) * inv;
            float knv = kn[(b * nk + k) * NH2 + h] + 1e-6f;
            cos_out[base + k] = sc[r][k] / (qnv * knv);
        }
    }
}

__global__ void copy_pref_out(const float* __restrict__ refp, float* __restrict__ out) {
    int idx = blockIdx.x * blockDim.x + threadIdx.x;
    if (idx >= BB * NP * 4) return;
    int c = idx & 3;
    int q = (idx >> 2) % NP;
    int b = idx / (4 * NP);
    out[OUT_PREF + idx] = refp[((size_t)(b * NQT + q)) * 4 + c];
}

// ---------------- host orchestration ----------------
static inline int cdiv(int a, int b) { return (a + b - 1) / b; }

extern "C" void kernel_launch(void* const* d_in, const int* in_sizes, int n_in,
                              void* d_out, int out_size) {
    const float* tgt   = (const float*)d_in[0];
    const float* refp  = (const float*)d_in[1];
    const float* src   = (const float*)d_in[2];
    const float* Woff  = (const float*)d_in[7];
    const float* boff  = (const float*)d_in[8];
    const float* Wa    = (const float*)d_in[9];
    const float* ba    = (const float*)d_in[10];
    const float* Wv    = (const float*)d_in[11];
    const float* bv    = (const float*)d_in[12];
    const float* Wout  = (const float*)d_in[13];
    const float* bout  = (const float*)d_in[14];
    const float* Wl1   = (const float*)d_in[15];
    const float* bl1   = (const float*)d_in[16];
    const float* Wl2   = (const float*)d_in[17];
    const float* bl2   = (const float*)d_in[18];
    const float* Wq    = (const float*)d_in[19];
    const float* bq    = (const float*)d_in[20];
    const float* Wk    = (const float*)d_in[21];
    const float* bk    = (const float*)d_in[22];
    const float* n1w   = (const float*)d_in[23];
    const float* n1b   = (const float*)d_in[24];
    const float* n3w   = (const float*)d_in[25];
    const float* n3b   = (const float*)d_in[26];
    float* out = (float*)d_out;

    float *pprop, *pppos, *poff, *pca, *pffn, *ptrack, *pqk, *pkt;
    float *pqn, *pkpn, *pktn, *pcapre, *pb1, *pb5;
    __nv_bfloat16 *w1h, *w1l, *w2h, *w2l, *w3h, *w3l, *w4h, *w4l, *w5h, *w5l;
    cudaGetSymbolAddress((void**)&pprop,  g_prop);
    cudaGetSymbolAddress((void**)&pppos,  g_ppos);
    cudaGetSymbolAddress((void**)&poff,   g_off);
    cudaGetSymbolAddress((void**)&pcapre, g_capre);
    cudaGetSymbolAddress((void**)&pca,    g_ca);
    cudaGetSymbolAddress((void**)&pffn,   g_ffn);
    cudaGetSymbolAddress((void**)&ptrack, g_track);
    cudaGetSymbolAddress((void**)&pqk,    g_qk);
    cudaGetSymbolAddress((void**)&pkt,    g_kt);
    cudaGetSymbolAddress((void**)&pqn,    g_qn);
    cudaGetSymbolAddress((void**)&pkpn,   g_kpn);
    cudaGetSymbolAddress((void**)&pktn,   g_ktn);
    cudaGetSymbolAddress((void**)&pb1,    g_b1);
    cudaGetSymbolAddress((void**)&pb5,    g_b5);
    cudaGetSymbolAddress((void**)&w1h,    g_w1h);
    cudaGetSymbolAddress((void**)&w1l,    g_w1l);
    cudaGetSymbolAddress((void**)&w2h,    g_w2h);
    cudaGetSymbolAddress((void**)&w2l,    g_w2l);
    cudaGetSymbolAddress((void**)&w3h,    g_w3h);
    cudaGetSymbolAddress((void**)&w3l,    g_w3l);
    cudaGetSymbolAddress((void**)&w4h,    g_w4h);
    cudaGetSymbolAddress((void**)&w4l,    g_w4l);
    cudaGetSymbolAddress((void**)&w5h,    g_w5h);
    cudaGetSymbolAddress((void**)&w5l,    g_w5l);

    const int NPROPS = BB * NP;        // 2400
    const int NEL = NPROPS * DIM;

    auto gemm = [&](const float* A, const __nv_bfloat16* Bh, const __nv_bfloat16* Bl,
                    const float* bias, float* C, int M, int N, int K, int ldb, int ldc,
                    bool relu) {
        dim3 g(cdiv(M, 64), N / 64);
        if (relu) mma_gemm2_kernel<true, false><<<g, 256>>>(A, nullptr, Bh, Bl, bias, C, M, N, K, ldb, ldc);
        else      mma_gemm2_kernel<false, false><<<g, 256>>>(A, nullptr, Bh, Bl, bias, C, M, N, K, ldb, ldc);
    };
    auto gemm_add = [&](const float* A, const float* A2, const __nv_bfloat16* Bh,
                        const __nv_bfloat16* Bl, const float* bias, float* C,
                        int M, int N, int K, int ldb, int ldc) {
        dim3 g(cdiv(M, 64), N / 64);
        mma_gemm2_kernel<false, true><<<g, 256>>>(A, A2, Bh, Bl, bias, C, M, N, K, ldb, ldc);
    };

    // launch 1: fused setup (prop copy + track copy + posemb)
    setup_kernel<<<cdiv(NEL, 256), 256>>>(tgt, refp);
    // launch 2: one-shot weight split/pack
    const long TOTC = (long)S1 + S2 + S3 + S4 + S5 + SB1 + SB5;
    convert_all<<<(unsigned)cdiv((int)TOTC, 256), 256>>>(Woff, Wa, Wout, Wl1, Wl2,
                                                         Wq, Wk, boff, ba, bq, bk);

    for (int l = 0; l < NLAY; l++) {
        // launch 3 (layer 0): packed offsets+logits from q = prop + pos
        gemm_add(pprop, pppos, w1h + (size_t)l * 98304, w1l + (size_t)l * 98304,
                 pb1 + l * 384, poff, NPROPS, 384, DIM, 384, OA);
        // launch 4 (layer 0): gather — lands in the ncu capture slot
        gather2_kernel<<<BB * NP, 256>>>(refp, src);
        dim3 hg(cdiv(NPROPS, 64), HH);
        hproj_kernel<<<hg, 256>>>(Wv + (size_t)l * DIM * DIM, bv + l * DIM);
        gemm(pcapre, w2h + (size_t)l * 65536, w2l + (size_t)l * 65536,
             bout + l * 256, pca, NPROPS, 256, 256, 256, 256, false);
        ln_kernel<<<cdiv(NPROPS, 8), 256>>>(pca, n1w + l * DIM, n1b + l * DIM, nullptr);
        gemm(pprop, w3h + (size_t)l * 262144, w3l + (size_t)l * 262144,
             bl1 + l * DFF, pffn, NPROPS, DFF, 256, DFF, DFF, true);
        gemm(pffn, w4h + (size_t)l * 262144, w4l + (size_t)l * 262144,
             bl2 + l * 256, pca, NPROPS, 256, DFF, 256, 256, false);
        ln_kernel<<<cdiv(NPROPS, 8), 256>>>(pca, n3w + l * DIM, n3b + l * DIM,
                                            (l == NLAY - 1) ? (out + OUT_PROP) : nullptr);
    }

    // weight_attn (only last layer's weights matter)
    const int L = NLAY - 1;
    gemm(pprop, w5h, w5l, pb5, pqk, NPROPS, 512, 256, 512, 512, false);
    gemm(ptrack, w5h + 256, w5l + 256, bk + L * 256, pkt, BB * NT, 256, 256, 512, 256, false);
    norm_kernel<<<cdiv(NPROPS * NH2, 256), 256>>>(pqk, NPROPS, 512, pqn);
    norm_kernel<<<cdiv(NPROPS * NH2, 256), 256>>>(pqk + 256, NPROPS, 512, pkpn);
    norm_kernel<<<cdiv(BB * NT * NH2, 256), 256>>>(pkt, BB * NT, 256, pktn);

    dim3 wg(cdiv(NP, QT), NH2, BB);
    wattn2_kernel<<<wg, 256>>>(pqk, pkt, pqn, pktn, NT, 512, 256,
                               out + OUT_PTCOS, out + OUT_PTMM);
    wattn2_kernel<<<wg, 256>>>(pqk, pqk + 256, pqn, pkpn, NP, 512, 512,
                               out + OUT_PPCOS, out + OUT_PPMM);

    copy_pref_out<<<cdiv(BB * NP * 4, 256), 256>>>(refp, out);
}

// round 14
// speedup vs baseline: 2.9034x; 1.0789x over previous
#include <cuda_runtime.h>
#include <cuda_bf16.h>
#include <math.h>

// ---------------- problem constants ----------------
#define BB     8
#define NQT    350
#define NP     300
#define NT     50
#define DIM    256
#define HH     8
#define DH     32
#define NLAY   6
#define NH2    2
#define DH2    128
#define DFF    1024
#define STOT   20197
#define OA     384          // packed Woff|Wa output row stride
#define QT     16           // wattn q-tile

// output layout (tuple flattened in order)
#define OUT_PROP   0
#define OUT_PREF   614400
#define OUT_PTCOS  624000
#define OUT_PPCOS  864000
#define OUT_PTMM   2304000
#define OUT_PPMM   2544000

__device__ __constant__ int c_hl[4]    = {100, 50, 25, 13};
__device__ __constant__ int c_wl[4]    = {152, 76, 38, 19};
__device__ __constant__ int c_start[4] = {0, 15200, 19000, 19950};

// ---------------- scratch (device globals, no allocation) ----------------
__device__ float g_prop [BB * NP * DIM];
__device__ float g_ppos [BB * NP * DIM];
__device__ float g_off  [BB * NP * OA];     // packed: offsets [0..255], attn logits [256..383]
__device__ float g_agg  [(size_t)BB * NP * HH * DIM];
__device__ float g_coef [BB * NP * HH];
__device__ float g_capre[BB * NP * DIM];
__device__ float g_ca   [BB * NP * DIM];
__device__ float g_ffn  [BB * NP * DFF];
__device__ float g_track[BB * NT * DIM];
__device__ float g_qk   [BB * NP * 512];    // packed q|k projection of proposals
__device__ float g_kt   [BB * NT * DIM];
__device__ float g_qn   [BB * NP * NH2];
__device__ float g_kpn  [BB * NP * NH2];
__device__ float g_ktn  [BB * NT * NH2];

// pre-split bf16 weights (hi/lo)
#define S1 (NLAY * 256 * 384)     // Woff|Wa packed
#define S2 (NLAY * 256 * 256)     // Wout
#define S3 (NLAY * 256 * 1024)    // Wl1
#define S4 (NLAY * 1024 * 256)    // Wl2
#define S5 (256 * 512)            // Wq|Wk (last layer)
#define SB1 (NLAY * 384)
#define SB5 (512)
__device__ __nv_bfloat16 g_w1h[S1], g_w1l[S1];
__device__ __nv_bfloat16 g_w2h[S2], g_w2l[S2];
__device__ __nv_bfloat16 g_w3h[S3], g_w3l[S3];
__device__ __nv_bfloat16 g_w4h[S4], g_w4l[S4];
__device__ __nv_bfloat16 g_w5h[S5], g_w5l[S5];
__device__ float g_b1[SB1];
__device__ float g_b5[SB5];

__device__ __forceinline__ unsigned pack_bf2(__nv_bfloat16 x, __nv_bfloat16 y) {
    __nv_bfloat162 h2; h2.x = x; h2.y = y;
    return *(unsigned*)&h2;
}
__device__ __forceinline__ void split_store(float v, __nv_bfloat16* H, __nv_bfloat16* L, long i) {
    __nv_bfloat16 h = __float2bfloat16_rn(v);
    H[i] = h;
    L[i] = __float2bfloat16_rn(v - __bfloat162float(h));
}

// ---------------- fused setup: prop copy + track copy + posemb ----------------
__global__ void setup_kernel(const float* __restrict__ tgt, const float* __restrict__ refp) {
    int idx = blockIdx.x * blockDim.x + threadIdx.x;
    if (idx < BB * NP * DIM) {
        int d = idx & 255;
        int q = (idx >> 8) % NP;
        int b = idx / (256 * NP);
        g_prop[idx] = tgt[((size_t)(b * NQT + q)) * DIM + d];
        int c = d >> 6;
        int r = d & 63;
        int j = r >> 1;
        float pos = refp[(b * NQT + q) * 4 + c];
        float t = powf(10000.0f, (float)j / 32.0f);
        float arg = pos * 6.2831853071795864f / t;
        g_ppos[idx] = (r & 1) ? cosf(arg) : sinf(arg);
    }
    if (idx < BB * NT * DIM) {
        int d = idx & 255;
        int r = (idx >> 8) % NT;
        int b = idx / (256 * NT);
        g_track[idx] = tgt[((size_t)(b * NQT + NP + r)) * DIM + d];
    }
}

// ---------------- one-shot weight conversion / packing ----------------
__global__ void convert_all(const float* __restrict__ Woff, const float* __restrict__ Wa,
                            const float* __restrict__ Wout, const float* __restrict__ Wl1,
                            const float* __restrict__ Wl2, const float* __restrict__ Wq,
                            const float* __restrict__ Wk, const float* __restrict__ boff,
                            const float* __restrict__ ba, const float* __restrict__ bqv,
                            const float* __restrict__ bkv) {
    long i = (long)blockIdx.x * blockDim.x + threadIdx.x;
    if (i < S1) {
        int l = (int)(i / 98304); int rem = (int)(i % 98304); int r = rem / 384; int c = rem % 384;
        float v = (c < 256) ? Woff[(size_t)l * 65536 + r * 256 + c]
                            : Wa[(size_t)l * 32768 + r * 128 + (c - 256)];
        split_store(v, g_w1h, g_w1l, i); return;
    }
    i -= S1;
    if (i < S2) { split_store(Wout[i], g_w2h, g_w2l, i); return; }
    i -= S2;
    if (i < S3) { split_store(Wl1[i], g_w3h, g_w3l, i); return; }
    i -= S3;
    if (i < S4) { split_store(Wl2[i], g_w4h, g_w4l, i); return; }
    i -= S4;
    if (i < S5) {
        int r = (int)(i / 512); int c = (int)(i % 512);
        float v = (c < 256) ? Wq[(size_t)(NLAY - 1) * 65536 + r * 256 + c]
                            : Wk[(size_t)(NLAY - 1) * 65536 + r * 256 + (c - 256)];
        split_store(v, g_w5h, g_w5l, i); return;
    }
    i -= S5;
    if (i < SB1) {
        int l = (int)(i / 384); int c = (int)(i % 384);
        g_b1[i] = (c < 256) ? boff[l * 256 + c] : ba[l * 128 + (c - 256)];
        return;
    }
    i -= SB1;
    if (i >= 0 && i < SB5) {
        g_b5[i] = (i < 256) ? bqv[(NLAY - 1) * 256 + i] : bkv[(NLAY - 1) * 256 + (i - 256)];
    }
}

// ---------------- bf16-split tensor-core GEMM (double-buffered, 1 sync/iter) ----------------
__device__ __forceinline__ void mma_bf16(float* c, const unsigned* a, const unsigned* b) {
    asm volatile(
        "mma.sync.aligned.m16n8k16.row.col.f32.bf16.bf16.f32 "
        "{%0,%1,%2,%3}, {%4,%5,%6,%7}, {%8,%9}, {%0,%1,%2,%3};"
        : "+f"(c[0]), "+f"(c[1]), "+f"(c[2]), "+f"(c[3])
        : "r"(a[0]), "r"(a[1]), "r"(a[2]), "r"(a[3]), "r"(b[0]), "r"(b[1]));
}

template <bool RELU, bool ADD2>
__global__ void __launch_bounds__(256) mma_gemm2_kernel(
        const float* __restrict__ A, const float* __restrict__ A2,
        const __nv_bfloat16* __restrict__ Bh, const __nv_bfloat16* __restrict__ Bl,
        const float* __restrict__ bias, float* __restrict__ C,
        int M, int N, int K, int ldb, int ldc) {
    __shared__ unsigned sAh[2][64][20], sAl[2][64][20];
    __shared__ unsigned sBh[2][16][72], sBl[2][16][72];

    const int tid = threadIdx.x;
    const int w = tid >> 5, lane = tid & 31;
    const int gid = lane >> 2, tig = lane & 3;
    const int wm = w >> 2, wn = w & 3;
    const int bm = blockIdx.x, bn = blockIdx.y;

    const int arowl = tid >> 4;
    const int akp = tid & 15;
    const int bn4 = (tid & 15) * 4;
    const int bkp = tid >> 4;
    const __nv_bfloat16* BhP = Bh + (size_t)bn * 64 + bn4;
    const __nv_bfloat16* BlP = Bl + (size_t)bn * 64 + bn4;

    float acc[2][2][4];
    #pragma unroll
    for (int i = 0; i < 2; i++)
        #pragma unroll
        for (int j = 0; j < 2; j++)
            #pragma unroll
            for (int r = 0; r < 4; r++) acc[i][j][r] = 0.f;

    float2 ra[4];
    unsigned long long rbh0, rbh1, rbl0, rbl1;

    auto loadTile = [&](int kb) {
        #pragma unroll
        for (int i = 0; i < 4; i++) {
            int grow = bm * 64 + arowl + 16 * i;
            float2 v = make_float2(0.f, 0.f);
            if (grow < M) {
                v = *(const float2*)(A + (size_t)grow * K + kb + 2 * akp);
                if (ADD2) {
                    float2 v2 = *(const float2*)(A2 + (size_t)grow * K + kb + 2 * akp);
                    v.x += v2.x; v.y += v2.y;
                }
            }
            ra[i] = v;
        }
        size_t bo = (size_t)(kb + 2 * bkp) * ldb;
        rbh0 = *(const unsigned long long*)(BhP + bo);
        rbh1 = *(const unsigned long long*)(BhP + bo + ldb);
        rbl0 = *(const unsigned long long*)(BlP + bo);
        rbl1 = *(const unsigned long long*)(BlP + bo + ldb);
    };
    auto storeTile = [&](int buf) {
        #pragma unroll
        for (int i = 0; i < 4; i++) {
            int row = arowl + 16 * i;
            __nv_bfloat16 hx = __float2bfloat16_rn(ra[i].x);
            __nv_bfloat16 hy = __float2bfloat16_rn(ra[i].y);
            __nv_bfloat16 lx = __float2bfloat16_rn(ra[i].x - __bfloat162float(hx));
            __nv_bfloat16 ly = __float2bfloat16_rn(ra[i].y - __bfloat162float(hy));
            sAh[buf][row][akp] = pack_bf2(hx, hy);
            sAl[buf][row][akp] = pack_bf2(lx, ly);
        }
        unsigned x0 = (unsigned)rbh0, x1 = (unsigned)(rbh0 >> 32);
        unsigned y0 = (unsigned)rbh1, y1 = (unsigned)(rbh1 >> 32);
        uint4 ph;
        ph.x = __byte_perm(x0, y0, 0x5410); ph.y = __byte_perm(x0, y0, 0x7632);
        ph.z = __byte_perm(x1, y1, 0x5410); ph.w = __byte_perm(x1, y1, 0x7632);
        *(uint4*)&sBh[buf][bkp][bn4] = ph;
        x0 = (unsigned)rbl0; x1 = (unsigned)(rbl0 >> 32);
        y0 = (unsigned)rbl1; y1 = (unsigned)(rbl1 >> 32);
        uint4 pl;
        pl.x = __byte_perm(x0, y0, 0x5410); pl.y = __byte_perm(x0, y0, 0x7632);
        pl.z = __byte_perm(x1, y1, 0x5410); pl.w = __byte_perm(x1, y1, 0x7632);
        *(uint4*)&sBl[buf][bkp][bn4] = pl;
    };
    auto compute = [&](int buf) {
        #pragma unroll
        for (int ks = 0; ks < 2; ks++) {
            const int kp0 = ks * 8;
            unsigned ah[2][4], al[2][4];
            #pragma unroll
            for (int mt = 0; mt < 2; mt++) {
                int r0 = wm * 32 + mt * 16;
                ah[mt][0] = sAh[buf][r0 + gid    ][kp0 + tig];
                ah[mt][1] = sAh[buf][r0 + gid + 8][kp0 + tig];
                ah[mt][2] = sAh[buf][r0 + gid    ][kp0 + tig + 4];
                ah[mt][3] = sAh[buf][r0 + gid + 8][kp0 + tig + 4];
                al[mt][0] = sAl[buf][r0 + gid    ][kp0 + tig];
                al[mt][1] = sAl[buf][r0 + gid + 8][kp0 + tig];
                al[mt][2] = sAl[buf][r0 + gid    ][kp0 + tig + 4];
                al[mt][3] = sAl[buf][r0 + gid + 8][kp0 + tig + 4];
            }
            unsigned bh[2][2], bl[2][2];
            #pragma unroll
            for (int nt = 0; nt < 2; nt++) {
                int c0 = wn * 16 + nt * 8 + gid;
                bh[nt][0] = sBh[buf][kp0 + tig    ][c0];
                bh[nt][1] = sBh[buf][kp0 + tig + 4][c0];
                bl[nt][0] = sBl[buf][kp0 + tig    ][c0];
                bl[nt][1] = sBl[buf][kp0 + tig + 4][c0];
            }
            #pragma unroll
            for (int mt = 0; mt < 2; mt++)
                #pragma unroll
                for (int nt = 0; nt < 2; nt++) {
                    mma_bf16(acc[mt][nt], ah[mt], bh[nt]);
                    mma_bf16(acc[mt][nt], ah[mt], bl[nt]);
                    mma_bf16(acc[mt][nt], al[mt], bh[nt]);
                }
        }
    };

    loadTile(0);
    storeTile(0);
    __syncthreads();
    int cur = 0;
    for (int kb = 0; kb < K; kb += 32) {
        bool nxt = (kb + 32 < K);
        if (nxt) loadTile(kb + 32);
        compute(cur);
        if (nxt) storeTile(cur ^ 1);
        __syncthreads();
        cur ^= 1;
    }

    #pragma unroll
    for (int mt = 0; mt < 2; mt++) {
        #pragma unroll
        for (int nt = 0; nt < 2; nt++) {
            int col = bn * 64 + wn * 16 + nt * 8 + tig * 2;
            float b0 = bias[col], b1 = bias[col + 1];
            int row0 = bm * 64 + wm * 32 + mt * 16 + gid;
            if (row0 < M) {
                float o0 = acc[mt][nt][0] + b0, o1 = acc[mt][nt][1] + b1;
                if (RELU) { o0 = fmaxf(o0, 0.f); o1 = fmaxf(o1, 0.f); }
                *(float2*)(C + (size_t)row0 * ldc + col) = make_float2(o0, o1);
            }
            int row1 = row0 + 8;
            if (row1 < M) {
                float o2 = acc[mt][nt][2] + b0, o3 = acc[mt][nt][3] + b1;
                if (RELU) { o2 = fmaxf(o2, 0.f); o3 = fmaxf(o3, 0.f); }
                *(float2*)(C + (size_t)row1 * ldc + col) = make_float2(o2, o3);
            }
        }
    }
}

// Aggregating gather, warp-cooperative softmax (reduced reg pressure): block=(b,q), warp=head.
__global__ void __launch_bounds__(256, 6) gather2_kernel(
        const float* __restrict__ refp, const float* __restrict__ src) {
    __shared__ float s_attn[HH][16];
    int bq = blockIdx.x;
    int b = bq / NP, q = bq % NP;
    int h = threadIdx.x >> 5;
    int lane = threadIdx.x & 31;
    const float* r = refp + (size_t)(b * NQT + q) * 4;
    float rx = r[0], ry = r[1], rw = r[2], rh = r[3];
    const float* offp = g_off + (size_t)bq * OA;

    // warp softmax over this head's 16 logits (lanes 0..15 hold one each)
    {
        const float* lg = offp + 256 + h * 16;
        float v = (lane < 16) ? __ldg(lg + lane) : -1e30f;
        float mx = v;
        #pragma unroll
        for (int o = 16; o > 0; o >>= 1) mx = fmaxf(mx, __shfl_xor_sync(0xffffffff, mx, o));
        float e = (lane < 16) ? expf(v - mx) : 0.f;
        float s = e;
        #pragma unroll
        for (int o = 16; o > 0; o >>= 1) s += __shfl_xor_sync(0xffffffff, s, o);
        if (lane < 16) s_attn[h][lane] = e / s;
    }
    __syncwarp();

    float4 a0 = make_float4(0.f, 0.f, 0.f, 0.f);
    float4 a1 = make_float4(0.f, 0.f, 0.f, 0.f);
    float csum = 0.f;

    #pragma unroll
    for (int l = 0; l < 4; l++) {
        int wl = c_wl[l], hl = c_hl[l], st = c_start[l];
        float wlf = (float)wl, hlf = (float)hl;
        const float4* base = (const float4*)(src + ((size_t)b * STOT + st) * DIM);
        #pragma unroll
        for (int p = 0; p < 4; p++) {
            int oi = ((h * 4 + l) * 4 + p) * 2;
            float ox = offp[oi], oy = offp[oi + 1];
            float a = s_attn[h][l * 4 + p];
            float x = (rx + ox * 0.125f * rw) * wlf - 0.5f;
            float y = (ry + oy * 0.125f * rh) * hlf - 0.5f;
            float x0 = floorf(x), y0 = floorf(y);
            float lx = x - x0, ly = y - y0;
            float wgt[4] = { (1.f - lx) * (1.f - ly), lx * (1.f - ly),
                             (1.f - lx) * ly,         lx * ly };
            float xs[4] = { x0, x0 + 1.f, x0, x0 + 1.f };
            float ys[4] = { y0, y0, y0 + 1.f, y0 + 1.f };
            #pragma unroll
            for (int c = 0; c < 4; c++) {
                float xi = xs[c], yi = ys[c];
                if (xi >= 0.f && xi <= wlf - 1.f && yi >= 0.f && yi <= hlf - 1.f) {
                    int xii = (int)xi, yii = (int)yi;
                    float coef = a * wgt[c];
                    const float4* rp = base + (size_t)(yii * wl + xii) * 64;
                    float4 v0 = rp[lane];
                    float4 v1 = rp[lane + 32];
                    a0.x += coef * v0.x; a0.y += coef * v0.y;
                    a0.z += coef * v0.z; a0.w += coef * v0.w;
                    a1.x += coef * v1.x; a1.y += coef * v1.y;
                    a1.z += coef * v1.z; a1.w += coef * v1.w;
                    csum += coef;
                }
            }
        }
    }
    float4* ag = (float4*)(g_agg + ((size_t)bq * HH + h) * DIM);
    ag[lane] = a0;
    ag[lane + 32] = a1;
    if (lane == 0) g_coef[bq * HH + h] = csum;
}

// Per-head projection: capre[bq][h*32+j] = agg[bq][h] . Wv[:, h*32+j] + coef*bv
__global__ void hproj_kernel(const float* __restrict__ Wv, const float* __restrict__ bv) {
    __shared__ float As[16][65];
    __shared__ float Bs[16][32];
    const int h = blockIdx.y;
    const int bm = blockIdx.x;
    const int tid = threadIdx.x;
    const int tx = tid & 7, ty = tid >> 3;
    float acc[2][4] = {};

    const int ar = tid >> 2, ac = (tid & 3) * 4;
    const int kr = tid >> 4, bc = (tid & 15) * 2;
    const int arow = bm * 64 + ar;

    for (int k0 = 0; k0 < DIM; k0 += 16) {
        float4 av = make_float4(0.f, 0.f, 0.f, 0.f);
        if (arow < BB * NP)
            av = *(const float4*)(g_agg + ((size_t)arow * HH + h) * DIM + k0 + ac);
        As[ac + 0][ar] = av.x; As[ac + 1][ar] = av.y;
        As[ac + 2][ar] = av.z; As[ac + 3][ar] = av.w;
        float2 bvv = *(const float2*)(Wv + (size_t)(k0 + kr) * DIM + h * 32 + bc);
        Bs[kr][bc] = bvv.x; Bs[kr][bc + 1] = bvv.y;
        __syncthreads();
        #pragma unroll
        for (int k = 0; k < 16; k++) {
            float x0 = As[k][ty * 2 + 0], x1 = As[k][ty * 2 + 1];
            float b0 = Bs[k][tx * 4 + 0], b1 = Bs[k][tx * 4 + 1];
            float b2 = Bs[k][tx * 4 + 2], b3 = Bs[k][tx * 4 + 3];
            acc[0][0] += x0 * b0; acc[0][1] += x0 * b1; acc[0][2] += x0 * b2; acc[0][3] += x0 * b3;
            acc[1][0] += x1 * b0; acc[1][1] += x1 * b1; acc[1][2] += x1 * b2; acc[1][3] += x1 * b3;
        }
        __syncthreads();
    }
    #pragma unroll
    for (int i = 0; i < 2; i++) {
        int row = bm * 64 + ty * 2 + i;
        if (row < BB * NP) {
            float cf = g_coef[row * HH + h];
            #pragma unroll
            for (int j = 0; j < 4; j++) {
                int col = h * 32 + tx * 4 + j;
                g_capre[(size_t)row * DIM + col] = acc[i][j] + cf * bv[col];
            }
        }
    }
}

// fused residual + layernorm (warp per row, in-place on g_prop, optional mirror to out)
__global__ void ln_kernel(const float* __restrict__ addv, const float* __restrict__ w,
                          const float* __restrict__ bia, float* __restrict__ outw) {
    int row = blockIdx.x * 8 + (threadIdx.x >> 5);
    int lane = threadIdx.x & 31;
    if (row >= BB * NP) return;
    float x[8];
    float s = 0.f;
    #pragma unroll
    for (int i = 0; i < 8; i++) {
        int d = lane + 32 * i;
        x[i] = g_prop[(size_t)row * DIM + d] + addv[(size_t)row * DIM + d];
        s += x[i];
    }
    #pragma unroll
    for (int o = 16; o > 0; o >>= 1) s += __shfl_xor_sync(0xffffffff, s, o);
    float m = s / 256.0f;
    float v = 0.f;
    #pragma unroll
    for (int i = 0; i < 8; i++) { float dd = x[i] - m; v += dd * dd; }
    #pragma unroll
    for (int o = 16; o > 0; o >>= 1) v += __shfl_xor_sync(0xffffffff, v, o);
    v /= 256.0f;
    float inv = rsqrtf(v + 1e-5f);
    #pragma unroll
    for (int i = 0; i < 8; i++) {
        int d = lane + 32 * i;
        float val = (x[i] - m) * inv * w[d] + bia[d];
        g_prop[(size_t)row * DIM + d] = val;
        if (outw) outw[(size_t)row * DIM + d] = val;
    }
}

// combined L2 norms for qh / kp / kt halves
__global__ void norms_kernel() {
    int idx = blockIdx.x * blockDim.x + threadIdx.x;
    const int NQ = BB * NP * NH2;           // 4800
    const int NK = BB * NT * NH2;           // 800
    const float* x; float* o;
    if (idx < NQ) {
        int h = idx & 1, r = idx >> 1;
        x = g_qk + (size_t)r * 512 + h * DH2; o = g_qn + idx;
    } else if (idx < 2 * NQ) {
        int i2 = idx - NQ;
        int h = i2 & 1, r = i2 >> 1;
        x = g_qk + (size_t)r * 512 + 256 + h * DH2; o = g_kpn + i2;
    } else if (idx < 2 * NQ + NK) {
        int i2 = idx - 2 * NQ;
        int h = i2 & 1, r = i2 >> 1;
        x = g_kt + (size_t)r * 256 + h * DH2; o = g_ktn + i2;
    } else return;
    float s = 0.f;
    #pragma unroll 8
    for (int d = 0; d < 128; d++) { float v = x[d]; s += v * v; }
    *o = sqrtf(s);
}

// Tiled weight_attn: block = (q-tile of 16, h, b); Q-tile + K staged in smem.
__global__ void __launch_bounds__(256) wattn2_kernel(
        const float* __restrict__ Q, const float* __restrict__ K,
        const float* __restrict__ qn, const float* __restrict__ kn,
        int nk, int ldq, int ldk,
        float* __restrict__ cos_out, float* __restrict__ mm_out) {
    int qt = blockIdx.x, h = blockIdx.y, b = blockIdx.z;
    int q0 = qt * QT;
    __shared__ float qv[QT][129];
    __shared__ float kt[32][129];
    __shared__ float sc[QT][304];
    int t = threadIdx.x;

    for (int i = t; i < QT * 128; i += 256) {
        int r = i >> 7, d = i & 127;
        int row = q0 + r;
        qv[r][d] = (row < NP) ? Q[(size_t)(b * NP + row) * ldq + h * DH2 + d] : 0.f;
    }
    __syncthreads();

    for (int kb = 0; kb < nk; kb += 32) {
        for (int i = t; i < 32 * 128; i += 256) {
            int r = i >> 7, d = i & 127;
            int krow = kb + r;
            kt[r][d] = (krow < nk) ? K[(size_t)(b * nk + krow) * ldk + h * DH2 + d] : 0.f;
        }
        __syncthreads();
        #pragma unroll
        for (int p = 0; p < 2; p++) {
            int pid = t + p * 256;
            int qq = pid >> 5, kk = pid & 31;
            float dot = 0.f;
            #pragma unroll 16
            for (int d = 0; d < 128; d++) dot += qv[qq][d] * kt[kk][d];
            if (kb + kk < nk) sc[qq][kb + kk] = dot;
        }
        __syncthreads();
    }

    const float scale = 0.088388347648318447f;   // 1/sqrt(128)
    int w = t >> 5, lane = t & 31;
    for (int r = w; r < QT; r += 8) {
        int row = q0 + r;
        if (row >= NP) continue;
        float mx = -1e30f;
        for (int k = lane; k < nk; k += 32) mx = fmaxf(mx, sc[r][k] * scale);
        #pragma unroll
        for (int o = 16; o > 0; o >>= 1) mx = fmaxf(mx, __shfl_xor_sync(0xffffffff, mx, o));
        float sum = 0.f;
        for (int k = lane; k < nk; k += 32) sum += expf(sc[r][k] * scale - mx);
        #pragma unroll
        for (int o = 16; o > 0; o >>= 1) sum += __shfl_xor_sync(0xffffffff, sum, o);
        float inv = 1.0f / sum;
        float qnv = qn[(b * NP + row) * NH2 + h] + 1e-6f;
        size_t base = ((size_t)(b * NH2 + h) * NP + row) * nk;
        for (int k = lane; k < nk; k += 32) {
            mm_out[base + k] = expf(sc[r][k] * scale - mx) * inv;
            float knv = kn[(b * nk + k) * NH2 + h] + 1e-6f;
            cos_out[base + k] = sc[r][k] / (qnv * knv);
        }
    }
}

__global__ void copy_pref_out(const float* __restrict__ refp, float* __restrict__ out) {
    int idx = blockIdx.x * blockDim.x + threadIdx.x;
    if (idx >= BB * NP * 4) return;
    int c = idx & 3;
    int q = (idx >> 2) % NP;
    int b = idx / (4 * NP);
    out[OUT_PREF + idx] = refp[((size_t)(b * NQT + q)) * 4 + c];
}

// ---------------- host orchestration ----------------
static inline int cdiv(int a, int b) { return (a + b - 1) / b; }

extern "C" void kernel_launch(void* const* d_in, const int* in_sizes, int n_in,
                              void* d_out, int out_size) {
    const float* tgt   = (const float*)d_in[0];
    const float* refp  = (const float*)d_in[1];
    const float* src   = (const float*)d_in[2];
    const float* Woff  = (const float*)d_in[7];
    const float* boff  = (const float*)d_in[8];
    const float* Wa    = (const float*)d_in[9];
    const float* ba    = (const float*)d_in[10];
    const float* Wv    = (const float*)d_in[11];
    const float* bv    = (const float*)d_in[12];
    const float* Wout  = (const float*)d_in[13];
    const float* bout  = (const float*)d_in[14];
    const float* Wl1   = (const float*)d_in[15];
    const float* bl1   = (const float*)d_in[16];
    const float* Wl2   = (const float*)d_in[17];
    const float* bl2   = (const float*)d_in[18];
    const float* Wq    = (const float*)d_in[19];
    const float* bq    = (const float*)d_in[20];
    const float* Wk    = (const float*)d_in[21];
    const float* bk    = (const float*)d_in[22];
    const float* n1w   = (const float*)d_in[23];
    const float* n1b   = (const float*)d_in[24];
    const float* n3w   = (const float*)d_in[25];
    const float* n3b   = (const float*)d_in[26];
    float* out = (float*)d_out;

    float *pprop, *pppos, *poff, *pca, *pffn, *ptrack, *pqk, *pkt;
    float *pqn, *pkpn, *pktn, *pcapre, *pb1, *pb5;
    __nv_bfloat16 *w1h, *w1l, *w2h, *w2l, *w3h, *w3l, *w4h, *w4l, *w5h, *w5l;
    cudaGetSymbolAddress((void**)&pprop,  g_prop);
    cudaGetSymbolAddress((void**)&pppos,  g_ppos);
    cudaGetSymbolAddress((void**)&poff,   g_off);      // <-- the R12 regression: device symbol
    cudaGetSymbolAddress((void**)&pcapre, g_capre);    //     must be resolved via the runtime,
    cudaGetSymbolAddress((void**)&pca,    g_ca);       //     never passed from host directly
    cudaGetSymbolAddress((void**)&pffn,   g_ffn);
    cudaGetSymbolAddress((void**)&ptrack, g_track);
    cudaGetSymbolAddress((void**)&pqk,    g_qk);
    cudaGetSymbolAddress((void**)&pkt,    g_kt);
    cudaGetSymbolAddress((void**)&pqn,    g_qn);
    cudaGetSymbolAddress((void**)&pkpn,   g_kpn);
    cudaGetSymbolAddress((void**)&pktn,   g_ktn);
    cudaGetSymbolAddress((void**)&pb1,    g_b1);
    cudaGetSymbolAddress((void**)&pb5,    g_b5);
    cudaGetSymbolAddress((void**)&w1h,    g_w1h);
    cudaGetSymbolAddress((void**)&w1l,    g_w1l);
    cudaGetSymbolAddress((void**)&w2h,    g_w2h);
    cudaGetSymbolAddress((void**)&w2l,    g_w2l);
    cudaGetSymbolAddress((void**)&w3h,    g_w3h);
    cudaGetSymbolAddress((void**)&w3l,    g_w3l);
    cudaGetSymbolAddress((void**)&w4h,    g_w4h);
    cudaGetSymbolAddress((void**)&w4l,    g_w4l);
    cudaGetSymbolAddress((void**)&w5h,    g_w5h);
    cudaGetSymbolAddress((void**)&w5l,    g_w5l);

    const int NPROPS = BB * NP;        // 2400
    const int NEL = NPROPS * DIM;

    auto gemm = [&](const float* A, const __nv_bfloat16* Bh, const __nv_bfloat16* Bl,
                    const float* bias, float* C, int M, int N, int K, int ldb, int ldc,
                    bool relu) {
        dim3 g(cdiv(M, 64), N / 64);
        if (relu) mma_gemm2_kernel<true, false><<<g, 256>>>(A, nullptr, Bh, Bl, bias, C, M, N, K, ldb, ldc);
        else      mma_gemm2_kernel<false, false><<<g, 256>>>(A, nullptr, Bh, Bl, bias, C, M, N, K, ldb, ldc);
    };
    auto gemm_add = [&](const float* A, const float* A2, const __nv_bfloat16* Bh,
                        const __nv_bfloat16* Bl, const float* bias, float* C,
                        int M, int N, int K, int ldb, int ldc) {
        dim3 g(cdiv(M, 64), N / 64);
        mma_gemm2_kernel<false, true><<<g, 256>>>(A, A2, Bh, Bl, bias, C, M, N, K, ldb, ldc);
    };

    // launch 1: fused setup
    setup_kernel<<<cdiv(NEL, 256), 256>>>(tgt, refp);
    // launch 2: one-shot weight split/pack
    const long TOTC = (long)S1 + S2 + S3 + S4 + S5 + SB1 + SB5;
    convert_all<<<(unsigned)cdiv((int)TOTC, 256), 256>>>(Woff, Wa, Wout, Wl1, Wl2,
                                                         Wq, Wk, boff, ba, bq, bk);

    for (int l = 0; l < NLAY; l++) {
        // packed offsets+logits from q = prop + pos  (output: DEVICE address poff)
        gemm_add(pprop, pppos, w1h + (size_t)l * 98304, w1l + (size_t)l * 98304,
                 pb1 + l * 384, poff, NPROPS, 384, DIM, 384, OA);
        // gather (profiled slot on layer 0)
        gather2_kernel<<<BB * NP, 256>>>(refp, src);
        // per-head projection through Wv (+ coef-weighted bias)
        dim3 hg(cdiv(NPROPS, 64), HH);
        hproj_kernel<<<hg, 256>>>(Wv + (size_t)l * DIM * DIM, bv + l * DIM);
        // output projection
        gemm(pcapre, w2h + (size_t)l * 65536, w2l + (size_t)l * 65536,
             bout + l * 256, pca, NPROPS, 256, 256, 256, 256, false);
        ln_kernel<<<cdiv(NPROPS, 8), 256>>>(pca, n1w + l * DIM, n1b + l * DIM, nullptr);
        // FFN
        gemm(pprop, w3h + (size_t)l * 262144, w3l + (size_t)l * 262144,
             bl1 + l * DFF, pffn, NPROPS, DFF, 256, DFF, DFF, true);
        gemm(pffn, w4h + (size_t)l * 262144, w4l + (size_t)l * 262144,
             bl2 + l * 256, pca, NPROPS, 256, DFF, 256, 256, false);
        ln_kernel<<<cdiv(NPROPS, 8), 256>>>(pca, n3w + l * DIM, n3b + l * DIM,
                                            (l == NLAY - 1) ? (out + OUT_PROP) : nullptr);
    }

    // weight_attn (only last layer's weights matter)
    const int L = NLAY - 1;
    gemm(pprop, w5h, w5l, pb5, pqk, NPROPS, 512, 256, 512, 512, false);
    gemm(ptrack, w5h + 256, w5l + 256, bk + L * 256, pkt, BB * NT, 256, 256, 512, 256, false);
    norms_kernel<<<cdiv(2 * NPROPS * NH2 + BB * NT * NH2, 256), 256>>>();

    dim3 wg2(cdiv(NP, QT), NH2, BB);
    wattn2_kernel<<<wg2, 256>>>(pqk, pkt, pqn, pktn, NT, 512, 256,
                                out + OUT_PTCOS, out + OUT_PTMM);
    wattn2_kernel<<<wg2, 256>>>(pqk, pqk + 256, pqn, pkpn, NP, 512, 512,
                                out + OUT_PPCOS, out + OUT_PPMM);

    copy_pref_out<<<cdiv(BB * NP * 4, 256), 256>>>(refp, out);
}

// round 15
// speedup vs baseline: 2.9644x; 1.0210x over previous
#include <cuda_runtime.h>
#include <cuda_bf16.h>
#include <math.h>

// ---------------- problem constants ----------------
#define BB     8
#define NQT    350
#define NP     300
#define NT     50
#define DIM    256
#define HH     8
#define DH     32
#define NLAY   6
#define NH2    2
#define DH2    128
#define DFF    1024
#define STOT   20197
#define OA     384          // packed Woff|Wa output row stride
#define QT     16           // wattn q-tile

// output layout (tuple flattened in order)
#define OUT_PROP   0
#define OUT_PREF   614400
#define OUT_PTCOS  624000
#define OUT_PPCOS  864000
#define OUT_PTMM   2304000
#define OUT_PPMM   2544000

__device__ __constant__ int c_hl[4]    = {100, 50, 25, 13};
__device__ __constant__ int c_wl[4]    = {152, 76, 38, 19};
__device__ __constant__ int c_start[4] = {0, 15200, 19000, 19950};

// ---------------- scratch (device globals, no allocation) ----------------
__device__ float g_prop [BB * NP * DIM];
__device__ float g_ppos [BB * NP * DIM];
__device__ float g_off  [BB * NP * OA];     // packed: offsets [0..255], attn logits [256..383]
__device__ float g_agg  [(size_t)BB * NP * HH * DIM];
__device__ float g_coef [BB * NP * HH];
__device__ float g_capre[BB * NP * DIM];
__device__ float g_ca   [BB * NP * DIM];
__device__ float g_ffn  [BB * NP * DFF];
__device__ float g_track[BB * NT * DIM];
__device__ float g_qk   [BB * NP * 512];    // packed q|k projection of proposals
__device__ float g_kt   [BB * NT * DIM];
__device__ float g_qn   [BB * NP * NH2];
__device__ float g_kpn  [BB * NP * NH2];
__device__ float g_ktn  [BB * NT * NH2];

// pre-split bf16 weights (hi/lo)
#define S1 (NLAY * 256 * 384)     // Woff|Wa packed
#define S2 (NLAY * 256 * 256)     // Wout
#define S3 (NLAY * 256 * 1024)    // Wl1
#define S4 (NLAY * 1024 * 256)    // Wl2
#define S5 (256 * 512)            // Wq|Wk (last layer)
#define SB1 (NLAY * 384)
#define SB5 (512)
__device__ __nv_bfloat16 g_w1h[S1], g_w1l[S1];
__device__ __nv_bfloat16 g_w2h[S2], g_w2l[S2];
__device__ __nv_bfloat16 g_w3h[S3], g_w3l[S3];
__device__ __nv_bfloat16 g_w4h[S4], g_w4l[S4];
__device__ __nv_bfloat16 g_w5h[S5], g_w5l[S5];
__device__ float g_b1[SB1];
__device__ float g_b5[SB5];

__device__ __forceinline__ unsigned pack_bf2(__nv_bfloat16 x, __nv_bfloat16 y) {
    __nv_bfloat162 h2; h2.x = x; h2.y = y;
    return *(unsigned*)&h2;
}
__device__ __forceinline__ void split_store(float v, __nv_bfloat16* H, __nv_bfloat16* L, long i) {
    __nv_bfloat16 h = __float2bfloat16_rn(v);
    H[i] = h;
    L[i] = __float2bfloat16_rn(v - __bfloat162float(h));
}

// ---------------- fused setup: prop copy + track copy + posemb ----------------
__global__ void setup_kernel(const float* __restrict__ tgt, const float* __restrict__ refp) {
    int idx = blockIdx.x * blockDim.x + threadIdx.x;
    if (idx < BB * NP * DIM) {
        int d = idx & 255;
        int q = (idx >> 8) % NP;
        int b = idx / (256 * NP);
        g_prop[idx] = tgt[((size_t)(b * NQT + q)) * DIM + d];
        int c = d >> 6;
        int r = d & 63;
        int j = r >> 1;
        float pos = refp[(b * NQT + q) * 4 + c];
        float t = powf(10000.0f, (float)j / 32.0f);
        float arg = pos * 6.2831853071795864f / t;
        g_ppos[idx] = (r & 1) ? cosf(arg) : sinf(arg);
    }
    if (idx < BB * NT * DIM) {
        int d = idx & 255;
        int r = (idx >> 8) % NT;
        int b = idx / (256 * NT);
        g_track[idx] = tgt[((size_t)(b * NQT + NP + r)) * DIM + d];
    }
}

// ---------------- one-shot weight conversion / packing ----------------
__global__ void convert_all(const float* __restrict__ Woff, const float* __restrict__ Wa,
                            const float* __restrict__ Wout, const float* __restrict__ Wl1,
                            const float* __restrict__ Wl2, const float* __restrict__ Wq,
                            const float* __restrict__ Wk, const float* __restrict__ boff,
                            const float* __restrict__ ba, const float* __restrict__ bqv,
                            const float* __restrict__ bkv) {
    long i = (long)blockIdx.x * blockDim.x + threadIdx.x;
    if (i < S1) {
        int l = (int)(i / 98304); int rem = (int)(i % 98304); int r = rem / 384; int c = rem % 384;
        float v = (c < 256) ? Woff[(size_t)l * 65536 + r * 256 + c]
                            : Wa[(size_t)l * 32768 + r * 128 + (c - 256)];
        split_store(v, g_w1h, g_w1l, i); return;
    }
    i -= S1;
    if (i < S2) { split_store(Wout[i], g_w2h, g_w2l, i); return; }
    i -= S2;
    if (i < S3) { split_store(Wl1[i], g_w3h, g_w3l, i); return; }
    i -= S3;
    if (i < S4) { split_store(Wl2[i], g_w4h, g_w4l, i); return; }
    i -= S4;
    if (i < S5) {
        int r = (int)(i / 512); int c = (int)(i % 512);
        float v = (c < 256) ? Wq[(size_t)(NLAY - 1) * 65536 + r * 256 + c]
                            : Wk[(size_t)(NLAY - 1) * 65536 + r * 256 + (c - 256)];
        split_store(v, g_w5h, g_w5l, i); return;
    }
    i -= S5;
    if (i < SB1) {
        int l = (int)(i / 384); int c = (int)(i % 384);
        g_b1[i] = (c < 256) ? boff[l * 256 + c] : ba[l * 128 + (c - 256)];
        return;
    }
    i -= SB1;
    if (i >= 0 && i < SB5) {
        g_b5[i] = (i < 256) ? bqv[(NLAY - 1) * 256 + i] : bkv[(NLAY - 1) * 256 + (i - 256)];
    }
}

// ---------------- bf16-split tensor-core GEMM (double-buffered, 1 sync/iter) ----------------
__device__ __forceinline__ void mma_bf16(float* c, const unsigned* a, const unsigned* b) {
    asm volatile(
        "mma.sync.aligned.m16n8k16.row.col.f32.bf16.bf16.f32 "
        "{%0,%1,%2,%3}, {%4,%5,%6,%7}, {%8,%9}, {%0,%1,%2,%3};"
        : "+f"(c[0]), "+f"(c[1]), "+f"(c[2]), "+f"(c[3])
        : "r"(a[0]), "r"(a[1]), "r"(a[2]), "r"(a[3]), "r"(b[0]), "r"(b[1]));
}

template <bool RELU, bool ADD2>
__global__ void __launch_bounds__(256) mma_gemm2_kernel(
        const float* __restrict__ A, const float* __restrict__ A2,
        const __nv_bfloat16* __restrict__ Bh, const __nv_bfloat16* __restrict__ Bl,
        const float* __restrict__ bias, float* __restrict__ C,
        int M, int N, int K, int ldb, int ldc) {
    __shared__ unsigned sAh[2][64][20], sAl[2][64][20];
    __shared__ unsigned sBh[2][16][72], sBl[2][16][72];

    const int tid = threadIdx.x;
    const int w = tid >> 5, lane = tid & 31;
    const int gid = lane >> 2, tig = lane & 3;
    const int wm = w >> 2, wn = w & 3;
    const int bm = blockIdx.x, bn = blockIdx.y;

    const int arowl = tid >> 4;
    const int akp = tid & 15;
    const int bn4 = (tid & 15) * 4;
    const int bkp = tid >> 4;
    const __nv_bfloat16* BhP = Bh + (size_t)bn * 64 + bn4;
    const __nv_bfloat16* BlP = Bl + (size_t)bn * 64 + bn4;

    float acc[2][2][4];
    #pragma unroll
    for (int i = 0; i < 2; i++)
        #pragma unroll
        for (int j = 0; j < 2; j++)
            #pragma unroll
            for (int r = 0; r < 4; r++) acc[i][j][r] = 0.f;

    float2 ra[4];
    unsigned long long rbh0, rbh1, rbl0, rbl1;

    auto loadTile = [&](int kb) {
        #pragma unroll
        for (int i = 0; i < 4; i++) {
            int grow = bm * 64 + arowl + 16 * i;
            float2 v = make_float2(0.f, 0.f);
            if (grow < M) {
                v = *(const float2*)(A + (size_t)grow * K + kb + 2 * akp);
                if (ADD2) {
                    float2 v2 = *(const float2*)(A2 + (size_t)grow * K + kb + 2 * akp);
                    v.x += v2.x; v.y += v2.y;
                }
            }
            ra[i] = v;
        }
        size_t bo = (size_t)(kb + 2 * bkp) * ldb;
        rbh0 = *(const unsigned long long*)(BhP + bo);
        rbh1 = *(const unsigned long long*)(BhP + bo + ldb);
        rbl0 = *(const unsigned long long*)(BlP + bo);
        rbl1 = *(const unsigned long long*)(BlP + bo + ldb);
    };
    auto storeTile = [&](int buf) {
        #pragma unroll
        for (int i = 0; i < 4; i++) {
            int row = arowl + 16 * i;
            __nv_bfloat16 hx = __float2bfloat16_rn(ra[i].x);
            __nv_bfloat16 hy = __float2bfloat16_rn(ra[i].y);
            __nv_bfloat16 lx = __float2bfloat16_rn(ra[i].x - __bfloat162float(hx));
            __nv_bfloat16 ly = __float2bfloat16_rn(ra[i].y - __bfloat162float(hy));
            sAh[buf][row][akp] = pack_bf2(hx, hy);
            sAl[buf][row][akp] = pack_bf2(lx, ly);
        }
        unsigned x0 = (unsigned)rbh0, x1 = (unsigned)(rbh0 >> 32);
        unsigned y0 = (unsigned)rbh1, y1 = (unsigned)(rbh1 >> 32);
        uint4 ph;
        ph.x = __byte_perm(x0, y0, 0x5410); ph.y = __byte_perm(x0, y0, 0x7632);
        ph.z = __byte_perm(x1, y1, 0x5410); ph.w = __byte_perm(x1, y1, 0x7632);
        *(uint4*)&sBh[buf][bkp][bn4] = ph;
        x0 = (unsigned)rbl0; x1 = (unsigned)(rbl0 >> 32);
        y0 = (unsigned)rbl1; y1 = (unsigned)(rbl1 >> 32);
        uint4 pl;
        pl.x = __byte_perm(x0, y0, 0x5410); pl.y = __byte_perm(x0, y0, 0x7632);
        pl.z = __byte_perm(x1, y1, 0x5410); pl.w = __byte_perm(x1, y1, 0x7632);
        *(uint4*)&sBl[buf][bkp][bn4] = pl;
    };
    auto compute = [&](int buf) {
        #pragma unroll
        for (int ks = 0; ks < 2; ks++) {
            const int kp0 = ks * 8;
            unsigned ah[2][4], al[2][4];
            #pragma unroll
            for (int mt = 0; mt < 2; mt++) {
                int r0 = wm * 32 + mt * 16;
                ah[mt][0] = sAh[buf][r0 + gid    ][kp0 + tig];
                ah[mt][1] = sAh[buf][r0 + gid + 8][kp0 + tig];
                ah[mt][2] = sAh[buf][r0 + gid    ][kp0 + tig + 4];
                ah[mt][3] = sAh[buf][r0 + gid + 8][kp0 + tig + 4];
                al[mt][0] = sAl[buf][r0 + gid    ][kp0 + tig];
                al[mt][1] = sAl[buf][r0 + gid + 8][kp0 + tig];
                al[mt][2] = sAl[buf][r0 + gid    ][kp0 + tig + 4];
                al[mt][3] = sAl[buf][r0 + gid + 8][kp0 + tig + 4];
            }
            unsigned bh[2][2], bl[2][2];
            #pragma unroll
            for (int nt = 0; nt < 2; nt++) {
                int c0 = wn * 16 + nt * 8 + gid;
                bh[nt][0] = sBh[buf][kp0 + tig    ][c0];
                bh[nt][1] = sBh[buf][kp0 + tig + 4][c0];
                bl[nt][0] = sBl[buf][kp0 + tig    ][c0];
                bl[nt][1] = sBl[buf][kp0 + tig + 4][c0];
            }
            #pragma unroll
            for (int mt = 0; mt < 2; mt++)
                #pragma unroll
                for (int nt = 0; nt < 2; nt++) {
                    mma_bf16(acc[mt][nt], ah[mt], bh[nt]);
                    mma_bf16(acc[mt][nt], ah[mt], bl[nt]);
                    mma_bf16(acc[mt][nt], al[mt], bh[nt]);
                }
        }
    };

    loadTile(0);
    storeTile(0);
    __syncthreads();
    int cur = 0;
    for (int kb = 0; kb < K; kb += 32) {
        bool nxt = (kb + 32 < K);
        if (nxt) loadTile(kb + 32);
        compute(cur);
        if (nxt) storeTile(cur ^ 1);
        __syncthreads();
        cur ^= 1;
    }

    #pragma unroll
    for (int mt = 0; mt < 2; mt++) {
        #pragma unroll
        for (int nt = 0; nt < 2; nt++) {
            int col = bn * 64 + wn * 16 + nt * 8 + tig * 2;
            float b0 = bias[col], b1 = bias[col + 1];
            int row0 = bm * 64 + wm * 32 + mt * 16 + gid;
            if (row0 < M) {
                float o0 = acc[mt][nt][0] + b0, o1 = acc[mt][nt][1] + b1;
                if (RELU) { o0 = fmaxf(o0, 0.f); o1 = fmaxf(o1, 0.f); }
                *(float2*)(C + (size_t)row0 * ldc + col) = make_float2(o0, o1);
            }
            int row1 = row0 + 8;
            if (row1 < M) {
                float o2 = acc[mt][nt][2] + b0, o3 = acc[mt][nt][3] + b1;
                if (RELU) { o2 = fmaxf(o2, 0.f); o3 = fmaxf(o3, 0.f); }
                *(float2*)(C + (size_t)row1 * ldc + col) = make_float2(o2, o3);
            }
        }
    }
}

// Aggregating gather, warp-cooperative coords: block=(b,q), warp=head.
// Lane j<16 computes point j's 4 corner (idx, coef); corner loop broadcasts via shfl.
__global__ void __launch_bounds__(256, 6) gather2_kernel(
        const float* __restrict__ refp, const float* __restrict__ src) {
    int bq = blockIdx.x;
    int b = bq / NP, q = bq % NP;
    int h = threadIdx.x >> 5;
    int lane = threadIdx.x & 31;
    const float* offp = g_off + (size_t)bq * OA;

    // warp softmax over this head's 16 logits; lane j<16 ends with aw = softmax_j
    float aw;
    {
        const float* lg = offp + 256 + h * 16;
        float v = (lane < 16) ? __ldg(lg + lane) : -1e30f;
        float mx = v;
        #pragma unroll
        for (int o = 16; o > 0; o >>= 1) mx = fmaxf(mx, __shfl_xor_sync(0xffffffff, mx, o));
        float e = (lane < 16) ? expf(v - mx) : 0.f;
        float s = e;
        #pragma unroll
        for (int o = 16; o > 0; o >>= 1) s += __shfl_xor_sync(0xffffffff, s, o);
        aw = e / s;
    }

    // lane j<16: compute point j's corners (l = j>>2, p = j&3)
    int idxc[4];
    float coefc[4];
    float csp = 0.f;
    if (lane < 16) {
        int l = lane >> 2;
        int wl = c_wl[l], hl = c_hl[l], st = c_start[l];
        float wlf = (float)wl, hlf = (float)hl;
        const float* r = refp + (size_t)(b * NQT + q) * 4;
        float rx = r[0], ry = r[1], rw = r[2], rh = r[3];
        int oi = ((h * 4 + l) * 4 + (lane & 3)) * 2;
        float ox = offp[oi], oy = offp[oi + 1];
        float x = (rx + ox * 0.125f * rw) * wlf - 0.5f;
        float y = (ry + oy * 0.125f * rh) * hlf - 0.5f;
        float x0 = floorf(x), y0 = floorf(y);
        float lx = x - x0, ly = y - y0;
        float wgt[4] = { (1.f - lx) * (1.f - ly), lx * (1.f - ly),
                         (1.f - lx) * ly,         lx * ly };
        float xs[4] = { x0, x0 + 1.f, x0, x0 + 1.f };
        float ys[4] = { y0, y0, y0 + 1.f, y0 + 1.f };
        #pragma unroll
        for (int c = 0; c < 4; c++) {
            float xi = xs[c], yi = ys[c];
            bool valid = (xi >= 0.f && xi <= wlf - 1.f && yi >= 0.f && yi <= hlf - 1.f);
            float cf = valid ? aw * wgt[c] : 0.f;
            idxc[c] = valid ? (st + (int)yi * wl + (int)xi) : 0;
            coefc[c] = cf;
            csp += cf;
        }
    } else {
        idxc[0] = idxc[1] = idxc[2] = idxc[3] = 0;
        coefc[0] = coefc[1] = coefc[2] = coefc[3] = 0.f;
    }
    // coef-sum reduce (upper lanes contribute 0)
    float csum = csp;
    #pragma unroll
    for (int o = 16; o > 0; o >>= 1) csum += __shfl_xor_sync(0xffffffff, csum, o);

    float4 a0 = make_float4(0.f, 0.f, 0.f, 0.f);
    float4 a1 = make_float4(0.f, 0.f, 0.f, 0.f);
    const float4* srcb = (const float4*)(src + (size_t)b * STOT * DIM);

    for (int j = 0; j < 16; j++) {
        #pragma unroll
        for (int c = 0; c < 4; c++) {
            float coef = __shfl_sync(0xffffffff, coefc[c], j);
            int idx    = __shfl_sync(0xffffffff, idxc[c], j);
            if (coef != 0.f) {                      // warp-uniform branch
                const float4* rp = srcb + (size_t)idx * 64;
                float4 v0 = rp[lane];
                float4 v1 = rp[lane + 32];
                a0.x += coef * v0.x; a0.y += coef * v0.y;
                a0.z += coef * v0.z; a0.w += coef * v0.w;
                a1.x += coef * v1.x; a1.y += coef * v1.y;
                a1.z += coef * v1.z; a1.w += coef * v1.w;
            }
        }
    }
    float4* ag = (float4*)(g_agg + ((size_t)bq * HH + h) * DIM);
    ag[lane] = a0;
    ag[lane + 32] = a1;
    if (lane == 0) g_coef[bq * HH + h] = csum;
}

// Per-head projection: capre[bq][h*32+j] = agg[bq][h] . Wv[:, h*32+j] + coef*bv
__global__ void hproj_kernel(const float* __restrict__ Wv, const float* __restrict__ bv) {
    __shared__ float As[16][65];
    __shared__ float Bs[16][32];
    const int h = blockIdx.y;
    const int bm = blockIdx.x;
    const int tid = threadIdx.x;
    const int tx = tid & 7, ty = tid >> 3;
    float acc[2][4] = {};

    const int ar = tid >> 2, ac = (tid & 3) * 4;
    const int kr = tid >> 4, bc = (tid & 15) * 2;
    const int arow = bm * 64 + ar;

    for (int k0 = 0; k0 < DIM; k0 += 16) {
        float4 av = make_float4(0.f, 0.f, 0.f, 0.f);
        if (arow < BB * NP)
            av = *(const float4*)(g_agg + ((size_t)arow * HH + h) * DIM + k0 + ac);
        As[ac + 0][ar] = av.x; As[ac + 1][ar] = av.y;
        As[ac + 2][ar] = av.z; As[ac + 3][ar] = av.w;
        float2 bvv = *(const float2*)(Wv + (size_t)(k0 + kr) * DIM + h * 32 + bc);
        Bs[kr][bc] = bvv.x; Bs[kr][bc + 1] = bvv.y;
        __syncthreads();
        #pragma unroll
        for (int k = 0; k < 16; k++) {
            float x0 = As[k][ty * 2 + 0], x1 = As[k][ty * 2 + 1];
            float b0 = Bs[k][tx * 4 + 0], b1 = Bs[k][tx * 4 + 1];
            float b2 = Bs[k][tx * 4 + 2], b3 = Bs[k][tx * 4 + 3];
            acc[0][0] += x0 * b0; acc[0][1] += x0 * b1; acc[0][2] += x0 * b2; acc[0][3] += x0 * b3;
            acc[1][0] += x1 * b0; acc[1][1] += x1 * b1; acc[1][2] += x1 * b2; acc[1][3] += x1 * b3;
        }
        __syncthreads();
    }
    #pragma unroll
    for (int i = 0; i < 2; i++) {
        int row = bm * 64 + ty * 2 + i;
        if (row < BB * NP) {
            float cf = g_coef[row * HH + h];
            #pragma unroll
            for (int j = 0; j < 4; j++) {
                int col = h * 32 + tx * 4 + j;
                g_capre[(size_t)row * DIM + col] = acc[i][j] + cf * bv[col];
            }
        }
    }
}

// fused residual + layernorm (warp per row, in-place on g_prop, optional mirror to out)
__global__ void ln_kernel(const float* __restrict__ addv, const float* __restrict__ w,
                          const float* __restrict__ bia, float* __restrict__ outw) {
    int row = blockIdx.x * 8 + (threadIdx.x >> 5);
    int lane = threadIdx.x & 31;
    if (row >= BB * NP) return;
    float x[8];
    float s = 0.f;
    #pragma unroll
    for (int i = 0; i < 8; i++) {
        int d = lane + 32 * i;
        x[i] = g_prop[(size_t)row * DIM + d] + addv[(size_t)row * DIM + d];
        s += x[i];
    }
    #pragma unroll
    for (int o = 16; o > 0; o >>= 1) s += __shfl_xor_sync(0xffffffff, s, o);
    float m = s / 256.0f;
    float v = 0.f;
    #pragma unroll
    for (int i = 0; i < 8; i++) { float dd = x[i] - m; v += dd * dd; }
    #pragma unroll
    for (int o = 16; o > 0; o >>= 1) v += __shfl_xor_sync(0xffffffff, v, o);
    v /= 256.0f;
    float inv = rsqrtf(v + 1e-5f);
    #pragma unroll
    for (int i = 0; i < 8; i++) {
        int d = lane + 32 * i;
        float val = (x[i] - m) * inv * w[d] + bia[d];
        g_prop[(size_t)row * DIM + d] = val;
        if (outw) outw[(size_t)row * DIM + d] = val;
    }
}

// combined L2 norms for qh / kp / kt halves
__global__ void norms_kernel() {
    int idx = blockIdx.x * blockDim.x + threadIdx.x;
    const int NQ = BB * NP * NH2;           // 4800
    const int NK = BB * NT * NH2;           // 800
    const float* x; float* o;
    if (idx < NQ) {
        int h = idx & 1, r = idx >> 1;
        x = g_qk + (size_t)r * 512 + h * DH2; o = g_qn + idx;
    } else if (idx < 2 * NQ) {
        int i2 = idx - NQ;
        int h = i2 & 1, r = i2 >> 1;
        x = g_qk + (size_t)r * 512 + 256 + h * DH2; o = g_kpn + i2;
    } else if (idx < 2 * NQ + NK) {
        int i2 = idx - 2 * NQ;
        int h = i2 & 1, r = i2 >> 1;
        x = g_kt + (size_t)r * 256 + h * DH2; o = g_ktn + i2;
    } else return;
    float s = 0.f;
    #pragma unroll 8
    for (int d = 0; d < 128; d++) { float v = x[d]; s += v * v; }
    *o = sqrtf(s);
}

// Tiled weight_attn: block = (q-tile of 16, h, b); Q-tile + K staged in smem.
__global__ void __launch_bounds__(256) wattn2_kernel(
        const float* __restrict__ Q, const float* __restrict__ K,
        const float* __restrict__ qn, const float* __restrict__ kn,
        int nk, int ldq, int ldk,
        float* __restrict__ cos_out, float* __restrict__ mm_out) {
    int qt = blockIdx.x, h = blockIdx.y, b = blockIdx.z;
    int q0 = qt * QT;
    __shared__ float qv[QT][129];
    __shared__ float kt[32][129];
    __shared__ float sc[QT][304];
    int t = threadIdx.x;

    for (int i = t; i < QT * 128; i += 256) {
        int r = i >> 7, d = i & 127;
        int row = q0 + r;
        qv[r][d] = (row < NP) ? Q[(size_t)(b * NP + row) * ldq + h * DH2 + d] : 0.f;
    }
    __syncthreads();

    for (int kb = 0; kb < nk; kb += 32) {
        for (int i = t; i < 32 * 128; i += 256) {
            int r = i >> 7, d = i & 127;
            int krow = kb + r;
            kt[r][d] = (krow < nk) ? K[(size_t)(b * nk + krow) * ldk + h * DH2 + d] : 0.f;
        }
        __syncthreads();
        #pragma unroll
        for (int p = 0; p < 2; p++) {
            int pid = t + p * 256;
            int qq = pid >> 5, kk = pid & 31;
            float dot = 0.f;
            #pragma unroll 16
            for (int d = 0; d < 128; d++) dot += qv[qq][d] * kt[kk][d];
            if (kb + kk < nk) sc[qq][kb + kk] = dot;
        }
        __syncthreads();
    }

    const float scale = 0.088388347648318447f;   // 1/sqrt(128)
    int w = t >> 5, lane = t & 31;
    for (int r = w; r < QT; r += 8) {
        int row = q0 + r;
        if (row >= NP) continue;
        float mx = -1e30f;
        for (int k = lane; k < nk; k += 32) mx = fmaxf(mx, sc[r][k] * scale);
        #pragma unroll
        for (int o = 16; o > 0; o >>= 1) mx = fmaxf(mx, __shfl_xor_sync(0xffffffff, mx, o));
        float sum = 0.f;
        for (int k = lane; k < nk; k += 32) sum += expf(sc[r][k] * scale - mx);
        #pragma unroll
        for (int o = 16; o > 0; o >>= 1) sum += __shfl_xor_sync(0xffffffff, sum, o);
        float inv = 1.0f / sum;
        float qnv = qn[(b * NP + row) * NH2 + h] + 1e-6f;
        size_t base = ((size_t)(b * NH2 + h) * NP + row) * nk;
        for (int k = lane; k < nk; k += 32) {
            mm_out[base + k] = expf(sc[r][k] * scale - mx) * inv;
            float knv = kn[(b * nk + k) * NH2 + h] + 1e-6f;
            cos_out[base + k] = sc[r][k] / (qnv * knv);
        }
    }
}

__global__ void copy_pref_out(const float* __restrict__ refp, float* __restrict__ out) {
    int idx = blockIdx.x * blockDim.x + threadIdx.x;
    if (idx >= BB * NP * 4) return;
    int c = idx & 3;
    int q = (idx >> 2) % NP;
    int b = idx / (4 * NP);
    out[OUT_PREF + idx] = refp[((size_t)(b * NQT + q)) * 4 + c];
}

// ---------------- host orchestration ----------------
static inline int cdiv(int a, int b) { return (a + b - 1) / b; }

extern "C" void kernel_launch(void* const* d_in, const int* in_sizes, int n_in,
                              void* d_out, int out_size) {
    const float* tgt   = (const float*)d_in[0];
    const float* refp  = (const float*)d_in[1];
    const float* src   = (const float*)d_in[2];
    const float* Woff  = (const float*)d_in[7];
    const float* boff  = (const float*)d_in[8];
    const float* Wa    = (const float*)d_in[9];
    const float* ba    = (const float*)d_in[10];
    const float* Wv    = (const float*)d_in[11];
    const float* bv    = (const float*)d_in[12];
    const float* Wout  = (const float*)d_in[13];
    const float* bout  = (const float*)d_in[14];
    const float* Wl1   = (const float*)d_in[15];
    const float* bl1   = (const float*)d_in[16];
    const float* Wl2   = (const float*)d_in[17];
    const float* bl2   = (const float*)d_in[18];
    const float* Wq    = (const float*)d_in[19];
    const float* bq    = (const float*)d_in[20];
    const float* Wk    = (const float*)d_in[21];
    const float* bk    = (const float*)d_in[22];
    const float* n1w   = (const float*)d_in[23];
    const float* n1b   = (const float*)d_in[24];
    const float* n3w   = (const float*)d_in[25];
    const float* n3b   = (const float*)d_in[26];
    float* out = (float*)d_out;

    float *pprop, *pppos, *poff, *pca, *pffn, *ptrack, *pqk, *pkt;
    float *pqn, *pkpn, *pktn, *pcapre, *pb1, *pb5;
    __nv_bfloat16 *w1h, *w1l, *w2h, *w2l, *w3h, *w3l, *w4h, *w4l, *w5h, *w5l;
    cudaGetSymbolAddress((void**)&pprop,  g_prop);
    cudaGetSymbolAddress((void**)&pppos,  g_ppos);
    cudaGetSymbolAddress((void**)&poff,   g_off);
    cudaGetSymbolAddress((void**)&pcapre, g_capre);
    cudaGetSymbolAddress((void**)&pca,    g_ca);
    cudaGetSymbolAddress((void**)&pffn,   g_ffn);
    cudaGetSymbolAddress((void**)&ptrack, g_track);
    cudaGetSymbolAddress((void**)&pqk,    g_qk);
    cudaGetSymbolAddress((void**)&pkt,    g_kt);
    cudaGetSymbolAddress((void**)&pqn,    g_qn);
    cudaGetSymbolAddress((void**)&pkpn,   g_kpn);
    cudaGetSymbolAddress((void**)&pktn,   g_ktn);
    cudaGetSymbolAddress((void**)&pb1,    g_b1);
    cudaGetSymbolAddress((void**)&pb5,    g_b5);
    cudaGetSymbolAddress((void**)&w1h,    g_w1h);
    cudaGetSymbolAddress((void**)&w1l,    g_w1l);
    cudaGetSymbolAddress((void**)&w2h,    g_w2h);
    cudaGetSymbolAddress((void**)&w2l,    g_w2l);
    cudaGetSymbolAddress((void**)&w3h,    g_w3h);
    cudaGetSymbolAddress((void**)&w3l,    g_w3l);
    cudaGetSymbolAddress((void**)&w4h,    g_w4h);
    cudaGetSymbolAddress((void**)&w4l,    g_w4l);
    cudaGetSymbolAddress((void**)&w5h,    g_w5h);
    cudaGetSymbolAddress((void**)&w5l,    g_w5l);

    const int NPROPS = BB * NP;        // 2400
    const int NEL = NPROPS * DIM;

    auto gemm = [&](const float* A, const __nv_bfloat16* Bh, const __nv_bfloat16* Bl,
                    const float* bias, float* C, int M, int N, int K, int ldb, int ldc,
                    bool relu) {
        dim3 g(cdiv(M, 64), N / 64);
        if (relu) mma_gemm2_kernel<true, false><<<g, 256>>>(A, nullptr, Bh, Bl, bias, C, M, N, K, ldb, ldc);
        else      mma_gemm2_kernel<false, false><<<g, 256>>>(A, nullptr, Bh, Bl, bias, C, M, N, K, ldb, ldc);
    };
    auto gemm_add = [&](const float* A, const float* A2, const __nv_bfloat16* Bh,
                        const __nv_bfloat16* Bl, const float* bias, float* C,
                        int M, int N, int K, int ldb, int ldc) {
        dim3 g(cdiv(M, 64), N / 64);
        mma_gemm2_kernel<false, true><<<g, 256>>>(A, A2, Bh, Bl, bias, C, M, N, K, ldb, ldc);
    };

    // launch 1: fused setup
    setup_kernel<<<cdiv(NEL, 256), 256>>>(tgt, refp);
    // launch 2: one-shot weight split/pack
    const long TOTC = (long)S1 + S2 + S3 + S4 + S5 + SB1 + SB5;
    convert_all<<<(unsigned)cdiv((int)TOTC, 256), 256>>>(Woff, Wa, Wout, Wl1, Wl2,
                                                         Wq, Wk, boff, ba, bq, bk);

    for (int l = 0; l < NLAY; l++) {
        // packed offsets+logits from q = prop + pos
        gemm_add(pprop, pppos, w1h + (size_t)l * 98304, w1l + (size_t)l * 98304,
                 pb1 + l * 384, poff, NPROPS, 384, DIM, 384, OA);
        // gather (profiled slot on layer 0)
        gather2_kernel<<<BB * NP, 256>>>(refp, src);
        // per-head projection through Wv (+ coef-weighted bias)
        dim3 hg(cdiv(NPROPS, 64), HH);
        hproj_kernel<<<hg, 256>>>(Wv + (size_t)l * DIM * DIM, bv + l * DIM);
        // output projection
        gemm(pcapre, w2h + (size_t)l * 65536, w2l + (size_t)l * 65536,
             bout + l * 256, pca, NPROPS, 256, 256, 256, 256, false);
        ln_kernel<<<cdiv(NPROPS, 8), 256>>>(pca, n1w + l * DIM, n1b + l * DIM, nullptr);
        // FFN
        gemm(pprop, w3h + (size_t)l * 262144, w3l + (size_t)l * 262144,
             bl1 + l * DFF, pffn, NPROPS, DFF, 256, DFF, DFF, true);
        gemm(pffn, w4h + (size_t)l * 262144, w4l + (size_t)l * 262144,
             bl2 + l * 256, pca, NPROPS, 256, DFF, 256, 256, false);
        ln_kernel<<<cdiv(NPROPS, 8), 256>>>(pca, n3w + l * DIM, n3b + l * DIM,
                                            (l == NLAY - 1) ? (out + OUT_PROP) : nullptr);
    }

    // weight_attn (only last layer's weights matter)
    const int L = NLAY - 1;
    gemm(pprop, w5h, w5l, pb5, pqk, NPROPS, 512, 256, 512, 512, false);
    gemm(ptrack, w5h + 256, w5l + 256, bk + L * 256, pkt, BB * NT, 256, 256, 512, 256, false);
    norms_kernel<<<cdiv(2 * NPROPS * NH2 + BB * NT * NH2, 256), 256>>>();

    dim3 wg2(cdiv(NP, QT), NH2, BB);
    wattn2_kernel<<<wg2, 256>>>(pqk, pkt, pqn, pktn, NT, 512, 256,
                                out + OUT_PTCOS, out + OUT_PTMM);
    wattn2_kernel<<<wg2, 256>>>(pqk, pqk + 256, pqn, pkpn, NP, 512, 512,
                                out + OUT_PPCOS, out + OUT_PPMM);

    copy_pref_out<<<cdiv(BB * NP * 4, 256), 256>>>(refp, out);
}

// round 16
// speedup vs baseline: 3.0027x; 1.0129x over previous
#include <cuda_runtime.h>
#include <cuda_bf16.h>
#include <cuda_fp16.h>
#include <math.h>

// ---------------- problem constants ----------------
#define BB     8
#define NQT    350
#define NP     300
#define NT     50
#define DIM    256
#define HH     8
#define DH     32
#define NLAY   6
#define NH2    2
#define DH2    128
#define DFF    1024
#define STOT   20197
#define OA     384          // packed Woff|Wa output row stride
#define QT     16           // wattn q-tile

// output layout (tuple flattened in order)
#define OUT_PROP   0
#define OUT_PREF   614400
#define OUT_PTCOS  624000
#define OUT_PPCOS  864000
#define OUT_PTMM   2304000
#define OUT_PPMM   2544000

__device__ __constant__ int c_hl[4]    = {100, 50, 25, 13};
__device__ __constant__ int c_wl[4]    = {152, 76, 38, 19};
__device__ __constant__ int c_start[4] = {0, 15200, 19000, 19950};

// ---------------- scratch (device globals, no allocation) ----------------
__device__ float g_prop [BB * NP * DIM];
__device__ float g_ppos [BB * NP * DIM];
__device__ float g_off  [BB * NP * OA];     // packed: offsets [0..255], attn logits [256..383]
__device__ float g_agg  [(size_t)BB * NP * HH * DIM];
__device__ float g_coef [BB * NP * HH];
__device__ float g_capre[BB * NP * DIM];
__device__ float g_ca   [BB * NP * DIM];
__device__ float g_ffn  [BB * NP * DFF];
__device__ float g_track[BB * NT * DIM];
__device__ float g_qk   [BB * NP * 512];    // packed q|k projection of proposals
__device__ float g_kt   [BB * NT * DIM];
__device__ float g_qn   [BB * NP * NH2];
__device__ float g_kpn  [BB * NP * NH2];
__device__ float g_ktn  [BB * NT * NH2];
__device__ __half g_srch[(size_t)BB * STOT * DIM];   // fp16-staged src (83 MB)

// pre-split bf16 weights (hi/lo)
#define S1 (NLAY * 256 * 384)     // Woff|Wa packed
#define S2 (NLAY * 256 * 256)     // Wout
#define S3 (NLAY * 256 * 1024)    // Wl1
#define S4 (NLAY * 1024 * 256)    // Wl2
#define S5 (256 * 512)            // Wq|Wk (last layer)
#define SB1 (NLAY * 384)
#define SB5 (512)
__device__ __nv_bfloat16 g_w1h[S1], g_w1l[S1];
__device__ __nv_bfloat16 g_w2h[S2], g_w2l[S2];
__device__ __nv_bfloat16 g_w3h[S3], g_w3l[S3];
__device__ __nv_bfloat16 g_w4h[S4], g_w4l[S4];
__device__ __nv_bfloat16 g_w5h[S5], g_w5l[S5];
__device__ float g_b1[SB1];
__device__ float g_b5[SB5];

__device__ __forceinline__ unsigned pack_bf2(__nv_bfloat16 x, __nv_bfloat16 y) {
    __nv_bfloat162 h2; h2.x = x; h2.y = y;
    return *(unsigned*)&h2;
}
__device__ __forceinline__ void split_store(float v, __nv_bfloat16* H, __nv_bfloat16* L, long i) {
    __nv_bfloat16 h = __float2bfloat16_rn(v);
    H[i] = h;
    L[i] = __float2bfloat16_rn(v - __bfloat162float(h));
}

// ---------------- one-shot src -> fp16 staging ----------------
__global__ void convert_src(const float* __restrict__ src) {
    size_t i = (size_t)blockIdx.x * blockDim.x + threadIdx.x;   // 8 elems per thread
    const size_t TOT = (size_t)BB * STOT * DIM;
    size_t base = i * 8;
    if (base >= TOT) return;
    float4 v0 = *(const float4*)(src + base);
    float4 v1 = *(const float4*)(src + base + 4);
    __half2 h[4];
    h[0] = __floats2half2_rn(v0.x, v0.y);
    h[1] = __floats2half2_rn(v0.z, v0.w);
    h[2] = __floats2half2_rn(v1.x, v1.y);
    h[3] = __floats2half2_rn(v1.z, v1.w);
    *(uint4*)(g_srch + base) = *(uint4*)h;
}

// ---------------- fused setup: prop copy + track copy + posemb ----------------
__global__ void setup_kernel(const float* __restrict__ tgt, const float* __restrict__ refp) {
    int idx = blockIdx.x * blockDim.x + threadIdx.x;
    if (idx < BB * NP * DIM) {
        int d = idx & 255;
        int q = (idx >> 8) % NP;
        int b = idx / (256 * NP);
        g_prop[idx] = tgt[((size_t)(b * NQT + q)) * DIM + d];
        int c = d >> 6;
        int r = d & 63;
        int j = r >> 1;
        float pos = refp[(b * NQT + q) * 4 + c];
        float t = powf(10000.0f, (float)j / 32.0f);
        float arg = pos * 6.2831853071795864f / t;
        g_ppos[idx] = (r & 1) ? cosf(arg) : sinf(arg);
    }
    if (idx < BB * NT * DIM) {
        int d = idx & 255;
        int r = (idx >> 8) % NT;
        int b = idx / (256 * NT);
        g_track[idx] = tgt[((size_t)(b * NQT + NP + r)) * DIM + d];
    }
}

// ---------------- one-shot weight conversion / packing ----------------
__global__ void convert_all(const float* __restrict__ Woff, const float* __restrict__ Wa,
                            const float* __restrict__ Wout, const float* __restrict__ Wl1,
                            const float* __restrict__ Wl2, const float* __restrict__ Wq,
                            const float* __restrict__ Wk, const float* __restrict__ boff,
                            const float* __restrict__ ba, const float* __restrict__ bqv,
                            const float* __restrict__ bkv) {
    long i = (long)blockIdx.x * blockDim.x + threadIdx.x;
    if (i < S1) {
        int l = (int)(i / 98304); int rem = (int)(i % 98304); int r = rem / 384; int c = rem % 384;
        float v = (c < 256) ? Woff[(size_t)l * 65536 + r * 256 + c]
                            : Wa[(size_t)l * 32768 + r * 128 + (c - 256)];
        split_store(v, g_w1h, g_w1l, i); return;
    }
    i -= S1;
    if (i < S2) { split_store(Wout[i], g_w2h, g_w2l, i); return; }
    i -= S2;
    if (i < S3) { split_store(Wl1[i], g_w3h, g_w3l, i); return; }
    i -= S3;
    if (i < S4) { split_store(Wl2[i], g_w4h, g_w4l, i); return; }
    i -= S4;
    if (i < S5) {
        int r = (int)(i / 512); int c = (int)(i % 512);
        float v = (c < 256) ? Wq[(size_t)(NLAY - 1) * 65536 + r * 256 + c]
                            : Wk[(size_t)(NLAY - 1) * 65536 + r * 256 + (c - 256)];
        split_store(v, g_w5h, g_w5l, i); return;
    }
    i -= S5;
    if (i < SB1) {
        int l = (int)(i / 384); int c = (int)(i % 384);
        g_b1[i] = (c < 256) ? boff[l * 256 + c] : ba[l * 128 + (c - 256)];
        return;
    }
    i -= SB1;
    if (i >= 0 && i < SB5) {
        g_b5[i] = (i < 256) ? bqv[(NLAY - 1) * 256 + i] : bkv[(NLAY - 1) * 256 + (i - 256)];
    }
}

// ---------------- bf16-split tensor-core GEMM (double-buffered, 1 sync/iter) ----------------
__device__ __forceinline__ void mma_bf16(float* c, const unsigned* a, const unsigned* b) {
    asm volatile(
        "mma.sync.aligned.m16n8k16.row.col.f32.bf16.bf16.f32 "
        "{%0,%1,%2,%3}, {%4,%5,%6,%7}, {%8,%9}, {%0,%1,%2,%3};"
        : "+f"(c[0]), "+f"(c[1]), "+f"(c[2]), "+f"(c[3])
        : "r"(a[0]), "r"(a[1]), "r"(a[2]), "r"(a[3]), "r"(b[0]), "r"(b[1]));
}

template <bool RELU, bool ADD2>
__global__ void __launch_bounds__(256) mma_gemm2_kernel(
        const float* __restrict__ A, const float* __restrict__ A2,
        const __nv_bfloat16* __restrict__ Bh, const __nv_bfloat16* __restrict__ Bl,
        const float* __restrict__ bias, float* __restrict__ C,
        int M, int N, int K, int ldb, int ldc) {
    __shared__ unsigned sAh[2][64][20], sAl[2][64][20];
    __shared__ unsigned sBh[2][16][72], sBl[2][16][72];

    const int tid = threadIdx.x;
    const int w = tid >> 5, lane = tid & 31;
    const int gid = lane >> 2, tig = lane & 3;
    const int wm = w >> 2, wn = w & 3;
    const int bm = blockIdx.x, bn = blockIdx.y;

    const int arowl = tid >> 4;
    const int akp = tid & 15;
    const int bn4 = (tid & 15) * 4;
    const int bkp = tid >> 4;
    const __nv_bfloat16* BhP = Bh + (size_t)bn * 64 + bn4;
    const __nv_bfloat16* BlP = Bl + (size_t)bn * 64 + bn4;

    float acc[2][2][4];
    #pragma unroll
    for (int i = 0; i < 2; i++)
        #pragma unroll
        for (int j = 0; j < 2; j++)
            #pragma unroll
            for (int r = 0; r < 4; r++) acc[i][j][r] = 0.f;

    float2 ra[4];
    unsigned long long rbh0, rbh1, rbl0, rbl1;

    auto loadTile = [&](int kb) {
        #pragma unroll
        for (int i = 0; i < 4; i++) {
            int grow = bm * 64 + arowl + 16 * i;
            float2 v = make_float2(0.f, 0.f);
            if (grow < M) {
                v = *(const float2*)(A + (size_t)grow * K + kb + 2 * akp);
                if (ADD2) {
                    float2 v2 = *(const float2*)(A2 + (size_t)grow * K + kb + 2 * akp);
                    v.x += v2.x; v.y += v2.y;
                }
            }
            ra[i] = v;
        }
        size_t bo = (size_t)(kb + 2 * bkp) * ldb;
        rbh0 = *(const unsigned long long*)(BhP + bo);
        rbh1 = *(const unsigned long long*)(BhP + bo + ldb);
        rbl0 = *(const unsigned long long*)(BlP + bo);
        rbl1 = *(const unsigned long long*)(BlP + bo + ldb);
    };
    auto storeTile = [&](int buf) {
        #pragma unroll
        for (int i = 0; i < 4; i++) {
            int row = arowl + 16 * i;
            __nv_bfloat16 hx = __float2bfloat16_rn(ra[i].x);
            __nv_bfloat16 hy = __float2bfloat16_rn(ra[i].y);
            __nv_bfloat16 lx = __float2bfloat16_rn(ra[i].x - __bfloat162float(hx));
            __nv_bfloat16 ly = __float2bfloat16_rn(ra[i].y - __bfloat162float(hy));
            sAh[buf][row][akp] = pack_bf2(hx, hy);
            sAl[buf][row][akp] = pack_bf2(lx, ly);
        }
        unsigned x0 = (unsigned)rbh0, x1 = (unsigned)(rbh0 >> 32);
        unsigned y0 = (unsigned)rbh1, y1 = (unsigned)(rbh1 >> 32);
        uint4 ph;
        ph.x = __byte_perm(x0, y0, 0x5410); ph.y = __byte_perm(x0, y0, 0x7632);
        ph.z = __byte_perm(x1, y1, 0x5410); ph.w = __byte_perm(x1, y1, 0x7632);
        *(uint4*)&sBh[buf][bkp][bn4] = ph;
        x0 = (unsigned)rbl0; x1 = (unsigned)(rbl0 >> 32);
        y0 = (unsigned)rbl1; y1 = (unsigned)(rbl1 >> 32);
        uint4 pl;
        pl.x = __byte_perm(x0, y0, 0x5410); pl.y = __byte_perm(x0, y0, 0x7632);
        pl.z = __byte_perm(x1, y1, 0x5410); pl.w = __byte_perm(x1, y1, 0x7632);
        *(uint4*)&sBl[buf][bkp][bn4] = pl;
    };
    auto compute = [&](int buf) {
        #pragma unroll
        for (int ks = 0; ks < 2; ks++) {
            const int kp0 = ks * 8;
            unsigned ah[2][4], al[2][4];
            #pragma unroll
            for (int mt = 0; mt < 2; mt++) {
                int r0 = wm * 32 + mt * 16;
                ah[mt][0] = sAh[buf][r0 + gid    ][kp0 + tig];
                ah[mt][1] = sAh[buf][r0 + gid + 8][kp0 + tig];
                ah[mt][2] = sAh[buf][r0 + gid    ][kp0 + tig + 4];
                ah[mt][3] = sAh[buf][r0 + gid + 8][kp0 + tig + 4];
                al[mt][0] = sAl[buf][r0 + gid    ][kp0 + tig];
                al[mt][1] = sAl[buf][r0 + gid + 8][kp0 + tig];
                al[mt][2] = sAl[buf][r0 + gid    ][kp0 + tig + 4];
                al[mt][3] = sAl[buf][r0 + gid + 8][kp0 + tig + 4];
            }
            unsigned bh[2][2], bl[2][2];
            #pragma unroll
            for (int nt = 0; nt < 2; nt++) {
                int c0 = wn * 16 + nt * 8 + gid;
                bh[nt][0] = sBh[buf][kp0 + tig    ][c0];
                bh[nt][1] = sBh[buf][kp0 + tig + 4][c0];
                bl[nt][0] = sBl[buf][kp0 + tig    ][c0];
                bl[nt][1] = sBl[buf][kp0 + tig + 4][c0];
            }
            #pragma unroll
            for (int mt = 0; mt < 2; mt++)
                #pragma unroll
                for (int nt = 0; nt < 2; nt++) {
                    mma_bf16(acc[mt][nt], ah[mt], bh[nt]);
                    mma_bf16(acc[mt][nt], ah[mt], bl[nt]);
                    mma_bf16(acc[mt][nt], al[mt], bh[nt]);
                }
        }
    };

    loadTile(0);
    storeTile(0);
    __syncthreads();
    int cur = 0;
    for (int kb = 0; kb < K; kb += 32) {
        bool nxt = (kb + 32 < K);
        if (nxt) loadTile(kb + 32);
        compute(cur);
        if (nxt) storeTile(cur ^ 1);
        __syncthreads();
        cur ^= 1;
    }

    #pragma unroll
    for (int mt = 0; mt < 2; mt++) {
        #pragma unroll
        for (int nt = 0; nt < 2; nt++) {
            int col = bn * 64 + wn * 16 + nt * 8 + tig * 2;
            float b0 = bias[col], b1 = bias[col + 1];
            int row0 = bm * 64 + wm * 32 + mt * 16 + gid;
            if (row0 < M) {
                float o0 = acc[mt][nt][0] + b0, o1 = acc[mt][nt][1] + b1;
                if (RELU) { o0 = fmaxf(o0, 0.f); o1 = fmaxf(o1, 0.f); }
                *(float2*)(C + (size_t)row0 * ldc + col) = make_float2(o0, o1);
            }
            int row1 = row0 + 8;
            if (row1 < M) {
                float o2 = acc[mt][nt][2] + b0, o3 = acc[mt][nt][3] + b1;
                if (RELU) { o2 = fmaxf(o2, 0.f); o3 = fmaxf(o3, 0.f); }
                *(float2*)(C + (size_t)row1 * ldc + col) = make_float2(o2, o3);
            }
        }
    }
}

// Aggregating gather over fp16-staged src: block=(b,q), warp=head.
// Lane j<16 computes point j's 4 corner (idx, coef); corner loop broadcasts via shfl.
// Each lane loads one float4 (= 8 halfs = channels 8*lane..8*lane+7) per corner.
__global__ void __launch_bounds__(256, 6) gather2_kernel(const float* __restrict__ refp) {
    int bq = blockIdx.x;
    int b = bq / NP, q = bq % NP;
    int h = threadIdx.x >> 5;
    int lane = threadIdx.x & 31;
    const float* offp = g_off + (size_t)bq * OA;

    // warp softmax over this head's 16 logits; lane j<16 ends with aw = softmax_j
    float aw;
    {
        const float* lg = offp + 256 + h * 16;
        float v = (lane < 16) ? __ldg(lg + lane) : -1e30f;
        float mx = v;
        #pragma unroll
        for (int o = 16; o > 0; o >>= 1) mx = fmaxf(mx, __shfl_xor_sync(0xffffffff, mx, o));
        float e = (lane < 16) ? expf(v - mx) : 0.f;
        float s = e;
        #pragma unroll
        for (int o = 16; o > 0; o >>= 1) s += __shfl_xor_sync(0xffffffff, s, o);
        aw = e / s;
    }

    // lane j<16: compute point j's corners (l = j>>2, p = j&3)
    int idxc[4];
    float coefc[4];
    float csp = 0.f;
    if (lane < 16) {
        int l = lane >> 2;
        int wl = c_wl[l], hl = c_hl[l], st = c_start[l];
        float wlf = (float)wl, hlf = (float)hl;
        const float* r = refp + (size_t)(b * NQT + q) * 4;
        float rx = r[0], ry = r[1], rw = r[2], rh = r[3];
        int oi = ((h * 4 + l) * 4 + (lane & 3)) * 2;
        float ox = offp[oi], oy = offp[oi + 1];
        float x = (rx + ox * 0.125f * rw) * wlf - 0.5f;
        float y = (ry + oy * 0.125f * rh) * hlf - 0.5f;
        float x0 = floorf(x), y0 = floorf(y);
        float lx = x - x0, ly = y - y0;
        float wgt[4] = { (1.f - lx) * (1.f - ly), lx * (1.f - ly),
                         (1.f - lx) * ly,         lx * ly };
        float xs[4] = { x0, x0 + 1.f, x0, x0 + 1.f };
        float ys[4] = { y0, y0, y0 + 1.f, y0 + 1.f };
        #pragma unroll
        for (int c = 0; c < 4; c++) {
            float xi = xs[c], yi = ys[c];
            bool valid = (xi >= 0.f && xi <= wlf - 1.f && yi >= 0.f && yi <= hlf - 1.f);
            float cf = valid ? aw * wgt[c] : 0.f;
            idxc[c] = valid ? (st + (int)yi * wl + (int)xi) : 0;
            coefc[c] = cf;
            csp += cf;
        }
    } else {
        idxc[0] = idxc[1] = idxc[2] = idxc[3] = 0;
        coefc[0] = coefc[1] = coefc[2] = coefc[3] = 0.f;
    }
    // coef-sum reduce (upper lanes contribute 0)
    float csum = csp;
    #pragma unroll
    for (int o = 16; o > 0; o >>= 1) csum += __shfl_xor_sync(0xffffffff, csum, o);

    float a[8];
    #pragma unroll
    for (int i = 0; i < 8; i++) a[i] = 0.f;
    const __half* srcb = g_srch + (size_t)b * STOT * DIM;

    for (int j = 0; j < 16; j++) {
        #pragma unroll
        for (int c = 0; c < 4; c++) {
            float coef = __shfl_sync(0xffffffff, coefc[c], j);
            int idx    = __shfl_sync(0xffffffff, idxc[c], j);
            if (coef != 0.f) {                      // warp-uniform branch
                const float4* rp = (const float4*)(srcb + (size_t)idx * DIM);
                float4 hv = rp[lane];               // 8 halfs: channels 8*lane..+7
                const __half2* hp = (const __half2*)&hv;
                float2 f0 = __half22float2(hp[0]);
                float2 f1 = __half22float2(hp[1]);
                float2 f2 = __half22float2(hp[2]);
                float2 f3 = __half22float2(hp[3]);
                a[0] += coef * f0.x; a[1] += coef * f0.y;
                a[2] += coef * f1.x; a[3] += coef * f1.y;
                a[4] += coef * f2.x; a[5] += coef * f2.y;
                a[6] += coef * f3.x; a[7] += coef * f3.y;
            }
        }
    }
    float4* ag = (float4*)(g_agg + ((size_t)bq * HH + h) * DIM);
    ag[2 * lane]     = make_float4(a[0], a[1], a[2], a[3]);
    ag[2 * lane + 1] = make_float4(a[4], a[5], a[6], a[7]);
    if (lane == 0) g_coef[bq * HH + h] = csum;
}

// Per-head projection: capre[bq][h*32+j] = agg[bq][h] . Wv[:, h*32+j] + coef*bv
__global__ void hproj_kernel(const float* __restrict__ Wv, const float* __restrict__ bv) {
    __shared__ float As[16][65];
    __shared__ float Bs[16][32];
    const int h = blockIdx.y;
    const int bm = blockIdx.x;
    const int tid = threadIdx.x;
    const int tx = tid & 7, ty = tid >> 3;
    float acc[2][4] = {};

    const int ar = tid >> 2, ac = (tid & 3) * 4;
    const int kr = tid >> 4, bc = (tid & 15) * 2;
    const int arow = bm * 64 + ar;

    for (int k0 = 0; k0 < DIM; k0 += 16) {
        float4 av = make_float4(0.f, 0.f, 0.f, 0.f);
        if (arow < BB * NP)
            av = *(const float4*)(g_agg + ((size_t)arow * HH + h) * DIM + k0 + ac);
        As[ac + 0][ar] = av.x; As[ac + 1][ar] = av.y;
        As[ac + 2][ar] = av.z; As[ac + 3][ar] = av.w;
        float2 bvv = *(const float2*)(Wv + (size_t)(k0 + kr) * DIM + h * 32 + bc);
        Bs[kr][bc] = bvv.x; Bs[kr][bc + 1] = bvv.y;
        __syncthreads();
        #pragma unroll
        for (int k = 0; k < 16; k++) {
            float x0 = As[k][ty * 2 + 0], x1 = As[k][ty * 2 + 1];
            float b0 = Bs[k][tx * 4 + 0], b1 = Bs[k][tx * 4 + 1];
            float b2 = Bs[k][tx * 4 + 2], b3 = Bs[k][tx * 4 + 3];
            acc[0][0] += x0 * b0; acc[0][1] += x0 * b1; acc[0][2] += x0 * b2; acc[0][3] += x0 * b3;
            acc[1][0] += x1 * b0; acc[1][1] += x1 * b1; acc[1][2] += x1 * b2; acc[1][3] += x1 * b3;
        }
        __syncthreads();
    }
    #pragma unroll
    for (int i = 0; i < 2; i++) {
        int row = bm * 64 + ty * 2 + i;
        if (row < BB * NP) {
            float cf = g_coef[row * HH + h];
            #pragma unroll
            for (int j = 0; j < 4; j++) {
                int col = h * 32 + tx * 4 + j;
                g_capre[(size_t)row * DIM + col] = acc[i][j] + cf * bv[col];
            }
        }
    }
}

// fused residual + layernorm (warp per row, in-place on g_prop, optional mirror to out)
__global__ void ln_kernel(const float* __restrict__ addv, const float* __restrict__ w,
                          const float* __restrict__ bia, float* __restrict__ outw) {
    int row = blockIdx.x * 8 + (threadIdx.x >> 5);
    int lane = threadIdx.x & 31;
    if (row >= BB * NP) return;
    float x[8];
    float s = 0.f;
    #pragma unroll
    for (int i = 0; i < 8; i++) {
        int d = lane + 32 * i;
        x[i] = g_prop[(size_t)row * DIM + d] + addv[(size_t)row * DIM + d];
        s += x[i];
    }
    #pragma unroll
    for (int o = 16; o > 0; o >>= 1) s += __shfl_xor_sync(0xffffffff, s, o);
    float m = s / 256.0f;
    float v = 0.f;
    #pragma unroll
    for (int i = 0; i < 8; i++) { float dd = x[i] - m; v += dd * dd; }
    #pragma unroll
    for (int o = 16; o > 0; o >>= 1) v += __shfl_xor_sync(0xffffffff, v, o);
    v /= 256.0f;
    float inv = rsqrtf(v + 1e-5f);
    #pragma unroll
    for (int i = 0; i < 8; i++) {
        int d = lane + 32 * i;
        float val = (x[i] - m) * inv * w[d] + bia[d];
        g_prop[(size_t)row * DIM + d] = val;
        if (outw) outw[(size_t)row * DIM + d] = val;
    }
}

// combined L2 norms for qh / kp / kt halves
__global__ void norms_kernel() {
    int idx = blockIdx.x * blockDim.x + threadIdx.x;
    const int NQ = BB * NP * NH2;           // 4800
    const int NK = BB * NT * NH2;           // 800
    const float* x; float* o;
    if (idx < NQ) {
        int h = idx & 1, r = idx >> 1;
        x = g_qk + (size_t)r * 512 + h * DH2; o = g_qn + idx;
    } else if (idx < 2 * NQ) {
        int i2 = idx - NQ;
        int h = i2 & 1, r = i2 >> 1;
        x = g_qk + (size_t)r * 512 + 256 + h * DH2; o = g_kpn + i2;
    } else if (idx < 2 * NQ + NK) {
        int i2 = idx - 2 * NQ;
        int h = i2 & 1, r = i2 >> 1;
        x = g_kt + (size_t)r * 256 + h * DH2; o = g_ktn + i2;
    } else return;
    float s = 0.f;
    #pragma unroll 8
    for (int d = 0; d < 128; d++) { float v = x[d]; s += v * v; }
    *o = sqrtf(s);
}

// Tiled weight_attn: block = (q-tile of 16, h, b); Q-tile + K staged in smem.
__global__ void __launch_bounds__(256) wattn2_kernel(
        const float* __restrict__ Q, const float* __restrict__ K,
        const float* __restrict__ qn, const float* __restrict__ kn,
        int nk, int ldq, int ldk,
        float* __restrict__ cos_out, float* __restrict__ mm_out) {
    int qt = blockIdx.x, h = blockIdx.y, b = blockIdx.z;
    int q0 = qt * QT;
    __shared__ float qv[QT][129];
    __shared__ float kt[32][129];
    __shared__ float sc[QT][304];
    int t = threadIdx.x;

    for (int i = t; i < QT * 128; i += 256) {
        int r = i >> 7, d = i & 127;
        int row = q0 + r;
        qv[r][d] = (row < NP) ? Q[(size_t)(b * NP + row) * ldq + h * DH2 + d] : 0.f;
    }
    __syncthreads();

    for (int kb = 0; kb < nk; kb += 32) {
        for (int i = t; i < 32 * 128; i += 256) {
            int r = i >> 7, d = i & 127;
            int krow = kb + r;
            kt[r][d] = (krow < nk) ? K[(size_t)(b * nk + krow) * ldk + h * DH2 + d] : 0.f;
        }
        __syncthreads();
        #pragma unroll
        for (int p = 0; p < 2; p++) {
            int pid = t + p * 256;
            int qq = pid >> 5, kk = pid & 31;
            float dot = 0.f;
            #pragma unroll 16
            for (int d = 0; d < 128; d++) dot += qv[qq][d] * kt[kk][d];
            if (kb + kk < nk) sc[qq][kb + kk] = dot;
        }
        __syncthreads();
    }

    const float scale = 0.088388347648318447f;   // 1/sqrt(128)
    int w = t >> 5, lane = t & 31;
    for (int r = w; r < QT; r += 8) {
        int row = q0 + r;
        if (row >= NP) continue;
        float mx = -1e30f;
        for (int k = lane; k < nk; k += 32) mx = fmaxf(mx, sc[r][k] * scale);
        #pragma unroll
        for (int o = 16; o > 0; o >>= 1) mx = fmaxf(mx, __shfl_xor_sync(0xffffffff, mx, o));
        float sum = 0.f;
        for (int k = lane; k < nk; k += 32) sum += expf(sc[r][k] * scale - mx);
        #pragma unroll
        for (int o = 16; o > 0; o >>= 1) sum += __shfl_xor_sync(0xffffffff, sum, o);
        float inv = 1.0f / sum;
        float qnv = qn[(b * NP + row) * NH2 + h] + 1e-6f;
        size_t base = ((size_t)(b * NH2 + h) * NP + row) * nk;
        for (int k = lane; k < nk; k += 32) {
            mm_out[base + k] = expf(sc[r][k] * scale - mx) * inv;
            float knv = kn[(b * nk + k) * NH2 + h] + 1e-6f;
            cos_out[base + k] = sc[r][k] / (qnv * knv);
        }
    }
}

__global__ void copy_pref_out(const float* __restrict__ refp, float* __restrict__ out) {
    int idx = blockIdx.x * blockDim.x + threadIdx.x;
    if (idx >= BB * NP * 4) return;
    int c = idx & 3;
    int q = (idx >> 2) % NP;
    int b = idx / (4 * NP);
    out[OUT_PREF + idx] = refp[((size_t)(b * NQT + q)) * 4 + c];
}

// ---------------- host orchestration ----------------
static inline int cdiv(int a, int b) { return (a + b - 1) / b; }

extern "C" void kernel_launch(void* const* d_in, const int* in_sizes, int n_in,
                              void* d_out, int out_size) {
    const float* tgt   = (const float*)d_in[0];
    const float* refp  = (const float*)d_in[1];
    const float* src   = (const float*)d_in[2];
    const float* Woff  = (const float*)d_in[7];
    const float* boff  = (const float*)d_in[8];
    const float* Wa    = (const float*)d_in[9];
    const float* ba    = (const float*)d_in[10];
    const float* Wv    = (const float*)d_in[11];
    const float* bv    = (const float*)d_in[12];
    const float* Wout  = (const float*)d_in[13];
    const float* bout  = (const float*)d_in[14];
    const float* Wl1   = (const float*)d_in[15];
    const float* bl1   = (const float*)d_in[16];
    const float* Wl2   = (const float*)d_in[17];
    const float* bl2   = (const float*)d_in[18];
    const float* Wq    = (const float*)d_in[19];
    const float* bq    = (const float*)d_in[20];
    const float* Wk    = (const float*)d_in[21];
    const float* bk    = (const float*)d_in[22];
    const float* n1w   = (const float*)d_in[23];
    const float* n1b   = (const float*)d_in[24];
    const float* n3w   = (const float*)d_in[25];
    const float* n3b   = (const float*)d_in[26];
    float* out = (float*)d_out;

    float *pprop, *pppos, *poff, *pca, *pffn, *ptrack, *pqk, *pkt;
    float *pqn, *pkpn, *pktn, *pcapre, *pb1, *pb5;
    __nv_bfloat16 *w1h, *w1l, *w2h, *w2l, *w3h, *w3l, *w4h, *w4l, *w5h, *w5l;
    cudaGetSymbolAddress((void**)&pprop,  g_prop);
    cudaGetSymbolAddress((void**)&pppos,  g_ppos);
    cudaGetSymbolAddress((void**)&poff,   g_off);
    cudaGetSymbolAddress((void**)&pcapre, g_capre);
    cudaGetSymbolAddress((void**)&pca,    g_ca);
    cudaGetSymbolAddress((void**)&pffn,   g_ffn);
    cudaGetSymbolAddress((void**)&ptrack, g_track);
    cudaGetSymbolAddress((void**)&pqk,    g_qk);
    cudaGetSymbolAddress((void**)&pkt,    g_kt);
    cudaGetSymbolAddress((void**)&pqn,    g_qn);
    cudaGetSymbolAddress((void**)&pkpn,   g_kpn);
    cudaGetSymbolAddress((void**)&pktn,   g_ktn);
    cudaGetSymbolAddress((void**)&pb1,    g_b1);
    cudaGetSymbolAddress((void**)&pb5,    g_b5);
    cudaGetSymbolAddress((void**)&w1h,    g_w1h);
    cudaGetSymbolAddress((void**)&w1l,    g_w1l);
    cudaGetSymbolAddress((void**)&w2h,    g_w2h);
    cudaGetSymbolAddress((void**)&w2l,    g_w2l);
    cudaGetSymbolAddress((void**)&w3h,    g_w3h);
    cudaGetSymbolAddress((void**)&w3l,    g_w3l);
    cudaGetSymbolAddress((void**)&w4h,    g_w4h);
    cudaGetSymbolAddress((void**)&w4l,    g_w4l);
    cudaGetSymbolAddress((void**)&w5h,    g_w5h);
    cudaGetSymbolAddress((void**)&w5l,    g_w5l);

    const int NPROPS = BB * NP;        // 2400
    const int NEL = NPROPS * DIM;

    auto gemm = [&](const float* A, const __nv_bfloat16* Bh, const __nv_bfloat16* Bl,
                    const float* bias, float* C, int M, int N, int K, int ldb, int ldc,
                    bool relu) {
        dim3 g(cdiv(M, 64), N / 64);
        if (relu) mma_gemm2_kernel<true, false><<<g, 256>>>(A, nullptr, Bh, Bl, bias, C, M, N, K, ldb, ldc);
        else      mma_gemm2_kernel<false, false><<<g, 256>>>(A, nullptr, Bh, Bl, bias, C, M, N, K, ldb, ldc);
    };
    auto gemm_add = [&](const float* A, const float* A2, const __nv_bfloat16* Bh,
                        const __nv_bfloat16* Bl, const float* bias, float* C,
                        int M, int N, int K, int ldb, int ldc) {
        dim3 g(cdiv(M, 64), N / 64);
        mma_gemm2_kernel<false, true><<<g, 256>>>(A, A2, Bh, Bl, bias, C, M, N, K, ldb, ldc);
    };

    // launch 1: fused setup
    setup_kernel<<<cdiv(NEL, 256), 256>>>(tgt, refp);
    // launch 2: one-shot weight split/pack
    const long TOTC = (long)S1 + S2 + S3 + S4 + S5 + SB1 + SB5;
    convert_all<<<(unsigned)cdiv((int)TOTC, 256), 256>>>(Woff, Wa, Wout, Wl1, Wl2,
                                                         Wq, Wk, boff, ba, bq, bk);
    // launch 3: src -> fp16 staging (serves all 6 layers)
    {
        const size_t TOT8 = ((size_t)BB * STOT * DIM) / 8;
        convert_src<<<(unsigned)cdiv((int)TOT8, 256), 256>>>(src);
    }

    for (int l = 0; l < NLAY; l++) {
        // packed offsets+logits from q = prop + pos
        gemm_add(pprop, pppos, w1h + (size_t)l * 98304, w1l + (size_t)l * 98304,
                 pb1 + l * 384, poff, NPROPS, 384, DIM, 384, OA);
        // gather on fp16-staged src
        gather2_kernel<<<BB * NP, 256>>>(refp);
        // per-head projection through Wv (+ coef-weighted bias)
        dim3 hg(cdiv(NPROPS, 64), HH);
        hproj_kernel<<<hg, 256>>>(Wv + (size_t)l * DIM * DIM, bv + l * DIM);
        // output projection
        gemm(pcapre, w2h + (size_t)l * 65536, w2l + (size_t)l * 65536,
             bout + l * 256, pca, NPROPS, 256, 256, 256, 256, false);
        ln_kernel<<<cdiv(NPROPS, 8), 256>>>(pca, n1w + l * DIM, n1b + l * DIM, nullptr);
        // FFN
        gemm(pprop, w3h + (size_t)l * 262144, w3l + (size_t)l * 262144,
             bl1 + l * DFF, pffn, NPROPS, DFF, 256, DFF, DFF, true);
        gemm(pffn, w4h + (size_t)l * 262144, w4l + (size_t)l * 262144,
             bl2 + l * 256, pca, NPROPS, 256, DFF, 256, 256, false);
        ln_kernel<<<cdiv(NPROPS, 8), 256>>>(pca, n3w + l * DIM, n3b + l * DIM,
                                            (l == NLAY - 1) ? (out + OUT_PROP) : nullptr);
    }

    // weight_attn (only last layer's weights matter)
    const int L = NLAY - 1;
    gemm(pprop, w5h, w5l, pb5, pqk, NPROPS, 512, 256, 512, 512, false);
    gemm(ptrack, w5h + 256, w5l + 256, bk + L * 256, pkt, BB * NT, 256, 256, 512, 256, false);
    norms_kernel<<<cdiv(2 * NPROPS * NH2 + BB * NT * NH2, 256), 256>>>();

    dim3 wg2(cdiv(NP, QT), NH2, BB);
    wattn2_kernel<<<wg2, 256>>>(pqk, pkt, pqn, pktn, NT, 512, 256,
                                out + OUT_PTCOS, out + OUT_PTMM);
    wattn2_kernel<<<wg2, 256>>>(pqk, pqk + 256, pqn, pkpn, NP, 512, 512,
                                out + OUT_PPCOS, out + OUT_PPMM);

    copy_pref_out<<<cdiv(BB * NP * 4, 256), 256>>>(refp, out);
}